// round 6
// baseline (speedup 1.0000x reference)
#include <cuda_runtime.h>
#include <cuda_bf16.h>
#include <cuda_fp16.h>
#include <math.h>
#include <stdint.h>

// Problem constants
#define BB 4
#define TT 2048
#define CC 1024
#define NHH 16
#define HDD 64
#define ROWS (BB*TT)          // 8192
#define N_QKV (3*CC)          // 3072

// ---------------- scratch (device globals; no allocation) ----------------
__device__ __nv_bfloat16 g_xh[(size_t)ROWS * CC];
__device__ __nv_bfloat16 g_xl[(size_t)ROWS * CC];
__device__ __nv_bfloat16 g_wqh[(size_t)N_QKV * CC];   // [N,K] transposed
__device__ __nv_bfloat16 g_wql[(size_t)N_QKV * CC];
__device__ __nv_bfloat16 g_wph[(size_t)CC * CC];
__device__ __nv_bfloat16 g_wpl[(size_t)CC * CC];
__device__ __nv_bfloat16 g_yh[(size_t)ROWS * CC];
__device__ __nv_bfloat16 g_yl[(size_t)ROWS * CC];
__device__ float g_cost[(size_t)TT * 32];
__device__ float g_sint[(size_t)TT * 32];

__device__ __half g_qh[(size_t)BB * NHH * TT * HDD];  // [bh][t][d]
__device__ __half g_kh[(size_t)BB * NHH * TT * HDD];  // [bh][t][d]
__device__ __half g_vh[(size_t)BB * NHH * TT * HDD];  // [bh][t][d]
__device__ __half g_vt[(size_t)BB * NHH * HDD * TT];  // [bh][d][t]

// ---------------- PTX helpers (arch-baseline only: no tcgen05) ------------
__device__ __forceinline__ uint32_t smem_u32(const void* p) {
    uint32_t a;
    asm("{ .reg .u64 t; cvta.to.shared.u64 t, %1; cvt.u32.u64 %0, t; }" : "=r"(a) : "l"(p));
    return a;
}
__device__ __forceinline__ void cp16(uint32_t saddr, const void* g) {
    asm volatile("cp.async.cg.shared.global [%0], [%1], 16;" :: "r"(saddr), "l"(g));
}
__device__ __forceinline__ void ldsm4(uint32_t* r, uint32_t addr) {
    asm volatile("ldmatrix.sync.aligned.m8n8.x4.shared.b16 {%0,%1,%2,%3}, [%4];"
                 : "=r"(r[0]), "=r"(r[1]), "=r"(r[2]), "=r"(r[3]) : "r"(addr));
}
__device__ __forceinline__ void mma16816(float* c, const uint32_t* a, const uint32_t* b) {
    asm volatile(
        "mma.sync.aligned.m16n8k16.row.col.f32.bf16.bf16.f32 "
        "{%0,%1,%2,%3}, {%4,%5,%6,%7}, {%8,%9}, {%0,%1,%2,%3};"
        : "+f"(c[0]), "+f"(c[1]), "+f"(c[2]), "+f"(c[3])
        : "r"(a[0]), "r"(a[1]), "r"(a[2]), "r"(a[3]), "r"(b[0]), "r"(b[1]));
}
__device__ __forceinline__ void mma16816h(float* c, const uint32_t* a, const uint32_t* b) {
    asm volatile(
        "mma.sync.aligned.m16n8k16.row.col.f32.f16.f16.f32 "
        "{%0,%1,%2,%3}, {%4,%5,%6,%7}, {%8,%9}, {%0,%1,%2,%3};"
        : "+f"(c[0]), "+f"(c[1]), "+f"(c[2]), "+f"(c[3])
        : "r"(a[0]), "r"(a[1]), "r"(a[2]), "r"(a[3]), "r"(b[0]), "r"(b[1]));
}
__device__ __forceinline__ uint32_t packh2(float a, float b) {
    __half2 h = __floats2half2_rn(a, b);
    return *(uint32_t*)&h;
}

// ---------------- precision-split conversions ------------------------------
__global__ __launch_bounds__(256) void split_kernel(
    const float* __restrict__ in, __nv_bfloat16* __restrict__ hi,
    __nv_bfloat16* __restrict__ lo, int n)
{
    int i = blockIdx.x * 256 + threadIdx.x;
    if (i >= n) return;
    float v = in[i];
    __nv_bfloat16 h = __float2bfloat16(v);
    hi[i] = h;
    lo[i] = __float2bfloat16(v - __bfloat162float(h));
}

// W[K,N] f32 -> hi/lo[N,K] bf16 (transpose + split)
__global__ __launch_bounds__(256) void transpose_split_kernel(
    const float* __restrict__ W, __nv_bfloat16* __restrict__ hi,
    __nv_bfloat16* __restrict__ lo, int K, int N)
{
    __shared__ float tile[32][33];
    int k0 = blockIdx.x * 32, n0 = blockIdx.y * 32;
    int tx = threadIdx.x & 31, ty = threadIdx.x >> 5;   // 32x8
    #pragma unroll
    for (int r = 0; r < 4; r++)
        tile[ty + 8 * r][tx] = W[(size_t)(k0 + ty + 8 * r) * N + n0 + tx];
    __syncthreads();
    #pragma unroll
    for (int r = 0; r < 4; r++) {
        float v = tile[tx][ty + 8 * r];
        __nv_bfloat16 h = __float2bfloat16(v);
        size_t o = (size_t)(n0 + ty + 8 * r) * K + k0 + tx;
        hi[o] = h;
        lo[o] = __float2bfloat16(v - __bfloat162float(h));
    }
}

// ---------------- RoPE table (mimic jax f32 computation) -------------------
__global__ __launch_bounds__(256) void rope_table_kernel(float* ct, float* st) {
    int idx = blockIdx.x * 256 + threadIdx.x;   // TT*32
    int t = idx >> 5, i = idx & 31;
    // inv_freq rounded to f32 (matches jax f32 power result), f32 product
    float invf = (float)exp(-(double)i / 32.0 * 9.210340371976184);
    float fr = (float)t * invf;
    double a = (double)fr;
    ct[idx] = (float)cos(a);
    st[idx] = (float)sin(a);
}

// ---------------- HMMA split-bf16 GEMM (mma.sync, 3-stage) -----------------
// MODE 0: C = f32 out + bias (proj)
// MODE 1: fused QKV epilogue: bias + RoPE -> fp16 Q,K ; fp16 V  (C unused)
#define TILE_B 16384
#define STAGE_B (4*TILE_B)     // Ah, Al, Bh, Bl
#define GSMEM (3*STAGE_B)      // 196608

__device__ __forceinline__ void load_stage(
    uint32_t base, int kt, int tid, int row0, int col0, int K,
    const __nv_bfloat16* __restrict__ Ah, const __nv_bfloat16* __restrict__ Al,
    const __nv_bfloat16* __restrict__ Bh, const __nv_bfloat16* __restrict__ Bl)
{
    int k0 = kt * 64;
    const __nv_bfloat16* srcs[4] = {Ah, Al, Bh, Bl};
    #pragma unroll
    for (int t = 0; t < 4; t++) {
        int rbase = (t < 2) ? row0 : col0;
        const __nv_bfloat16* s = srcs[t];
        #pragma unroll
        for (int i = 0; i < 4; i++) {
            int lin = i * 256 + tid;
            int r = lin >> 3, c = lin & 7;
            uint32_t off = r * 128 + c * 16;
            uint32_t sw = off ^ ((off >> 3) & 0x70);
            cp16(base + t * TILE_B + sw, s + (size_t)(rbase + r) * K + k0 + c * 8);
        }
    }
    asm volatile("cp.async.commit_group;" ::: "memory");
}

template<int MODE>
__global__ __launch_bounds__(256, 1) void tc_gemm_kernel(
    const __nv_bfloat16* __restrict__ Ah, const __nv_bfloat16* __restrict__ Al,
    const __nv_bfloat16* __restrict__ Bh, const __nv_bfloat16* __restrict__ Bl,
    const float* __restrict__ bias, float* __restrict__ C,
    __half* __restrict__ Qo, __half* __restrict__ Ko, __half* __restrict__ Vo,
    const float* __restrict__ ct, const float* __restrict__ st,
    int N, int K)
{
    extern __shared__ char smem[];
    uint32_t sb = smem_u32(smem);
    const int tid = threadIdx.x;
    const int wid = tid >> 5, lane = tid & 31;
    const int wr = (wid & 3) * 32;
    const int wc = (wid >> 2) * 64;
    const int col0 = blockIdx.x * 128;
    const int row0 = blockIdx.y * 128;
    const int NK = K >> 6;

    float acc[2][8][4];
    #pragma unroll
    for (int mi = 0; mi < 2; mi++)
        #pragma unroll
        for (int ni = 0; ni < 8; ni++)
            #pragma unroll
            for (int j = 0; j < 4; j++) acc[mi][ni][j] = 0.f;

    load_stage(sb, 0, tid, row0, col0, K, Ah, Al, Bh, Bl);
    if (NK > 1)
        load_stage(sb + STAGE_B, 1, tid, row0, col0, K, Ah, Al, Bh, Bl);

    const int grp = lane >> 3, l8 = lane & 7;

    for (int kt = 0; kt < NK; kt++) {
        if (kt + 1 < NK) { asm volatile("cp.async.wait_group 1;" ::: "memory"); }
        else             { asm volatile("cp.async.wait_group 0;" ::: "memory"); }
        __syncthreads();

        uint32_t sbase = sb + (kt % 3) * STAGE_B;
        #pragma unroll
        for (int p = 0; p < 3; p++) {
            uint32_t abase = sbase + ((p == 2) ? TILE_B : 0);
            uint32_t bbase = sbase + ((p == 1) ? 3 * TILE_B : 2 * TILE_B);
            #pragma unroll
            for (int ks = 0; ks < 4; ks++) {
                uint32_t a[2][4], b[8][2];
                #pragma unroll
                for (int mi = 0; mi < 2; mi++) {
                    int row = wr + mi * 16 + (grp & 1) * 8 + l8;
                    int chunk = ks * 2 + (grp >> 1);
                    ldsm4(a[mi], abase + row * 128 + ((chunk ^ (row & 7)) << 4));
                }
                #pragma unroll
                for (int nj = 0; nj < 4; nj++) {
                    int row = wc + nj * 16 + (grp >> 1) * 8 + l8;
                    int chunk = ks * 2 + (grp & 1);
                    uint32_t rr[4];
                    ldsm4(rr, bbase + row * 128 + ((chunk ^ (row & 7)) << 4));
                    b[2 * nj][0] = rr[0]; b[2 * nj][1] = rr[1];
                    b[2 * nj + 1][0] = rr[2]; b[2 * nj + 1][1] = rr[3];
                }
                #pragma unroll
                for (int mi = 0; mi < 2; mi++)
                    #pragma unroll
                    for (int ni = 0; ni < 8; ni++)
                        mma16816(acc[mi][ni], a[mi], b[ni]);
            }
        }
        // issue load for kt+2 (overwrites slot of kt-1; safe: all warps passed
        // this iteration's __syncthreads, hence finished reading it)
        if (kt + 2 < NK)
            load_stage(sb + ((kt + 2) % 3) * STAGE_B, kt + 2, tid, row0, col0, K,
                       Ah, Al, Bh, Bl);
    }

    const int qr = lane >> 2, qc = (lane & 3) * 2;

    if (MODE == 0) {
        #pragma unroll
        for (int mi = 0; mi < 2; mi++) {
            #pragma unroll
            for (int ni = 0; ni < 8; ni++) {
                int r = row0 + wr + mi * 16 + qr;
                int c = col0 + wc + ni * 8 + qc;
                float b0 = bias[c], b1 = bias[c + 1];
                float2 o0 = make_float2(acc[mi][ni][0] + b0, acc[mi][ni][1] + b1);
                float2 o1 = make_float2(acc[mi][ni][2] + b0, acc[mi][ni][3] + b1);
                *(float2*)&C[(size_t)r * N + c] = o0;
                *(float2*)&C[(size_t)(r + 8) * N + c] = o1;
            }
        }
    } else {
        // fused QKV epilogue: bias + RoPE -> fp16
        int cb = col0 + wc;                 // 64-aligned head base
        int sec = cb >> 10;                 // 0=q, 1=k, 2=v
        int h = (cb & 1023) >> 6;
        #pragma unroll
        for (int mi = 0; mi < 2; mi++) {
            int r0 = row0 + wr + mi * 16 + qr;
            #pragma unroll
            for (int half = 0; half < 2; half++) {
                int r = r0 + half * 8;
                int e = half * 2;
                int t = r & (TT - 1);
                int b_ = r >> 11;
                size_t rowoff = ((size_t)((b_ * NHH + h) * TT + t)) * HDD;
                #pragma unroll
                for (int nj = 0; nj < 4; nj++) {
                    int d0 = nj * 8 + qc;            // even, < 32
                    int c0 = cb + d0;
                    float u00 = acc[mi][nj][e]     + bias[c0];
                    float u01 = acc[mi][nj][e + 1] + bias[c0 + 1];
                    float u10 = acc[mi][nj + 4][e]     + bias[c0 + 32];
                    float u11 = acc[mi][nj + 4][e + 1] + bias[c0 + 33];
                    if (sec < 2) {
                        float cA = ct[t * 32 + d0], cB = ct[t * 32 + d0 + 1];
                        float sA = st[t * 32 + d0], sB = st[t * 32 + d0 + 1];
                        float lo0 = u00 * cA - u10 * sA;
                        float lo1 = u01 * cB - u11 * sB;
                        float hi0 = u10 * cA + u00 * sA;
                        float hi1 = u11 * cB + u01 * sB;
                        __half* dst = (sec == 0) ? Qo : Ko;
                        *(__half2*)&dst[rowoff + d0]      = __floats2half2_rn(lo0, lo1);
                        *(__half2*)&dst[rowoff + d0 + 32] = __floats2half2_rn(hi0, hi1);
                    } else {
                        *(__half2*)&Vo[rowoff + d0]      = __floats2half2_rn(u00, u01);
                        *(__half2*)&Vo[rowoff + d0 + 32] = __floats2half2_rn(u10, u11);
                    }
                }
            }
        }
    }
}

// ---------------- fp16 V transpose: [bh][t][d] -> [bh][d][t] ---------------
__global__ __launch_bounds__(256) void vt_kernel(
    const __half* __restrict__ Vh, __half* __restrict__ Vt)
{
    __shared__ __half sm[64][72];
    int t0 = blockIdx.x * 64;
    int bh = blockIdx.y;
    const __half* src = Vh + ((size_t)bh * TT + t0) * HDD;
    #pragma unroll
    for (int i = 0; i < 2; i++) {
        int lin = i * 256 + threadIdx.x;      // 512 x 8 halfs
        int r = lin >> 3, c = (lin & 7) * 8;
        uint4 v = *(const uint4*)(src + (size_t)r * HDD + c);
        __half hv[8];
        *(uint4*)hv = v;
        #pragma unroll
        for (int j = 0; j < 8; j++) sm[c + j][r] = hv[j];
    }
    __syncthreads();
    #pragma unroll
    for (int i = 0; i < 2; i++) {
        int lin = i * 256 + threadIdx.x;
        int d = lin >> 3, tc = (lin & 7) * 8;
        *(uint4*)&Vt[((size_t)bh * HDD + d) * TT + t0 + tc] = *(uint4*)&sm[d][tc];
    }
}

// ---------------- Tensor-core flash attention (fp16, BM=128 BN=128) --------
// 256 threads, 8 warps x 16 q-rows. 3-stage KV pipeline, 1 sync/iter.
#define KV_STAGE 32768                     // K 16KB + V 16KB
#define AT_SMEM (16384 + 3*KV_STAGE)       // Q + 3 stages = 114688

__device__ __forceinline__ void attn_load_kv(
    uint32_t dst, const __half* __restrict__ Kb, const __half* __restrict__ Vb,
    int ktbase, int tid)
{
    // K tile: 128 t-rows x 64 d (128B rows)
    #pragma unroll
    for (int i = 0; i < 4; i++) {
        int lin = i * 256 + tid;              // 1024
        int r = lin >> 3, c = lin & 7;
        cp16(dst + r * 128 + ((c ^ (r & 7)) << 4),
             Kb + (size_t)(ktbase + r) * HDD + c * 8);
    }
    // V tile: 64 d-rows x 128 t (256B rows)
    #pragma unroll
    for (int i = 0; i < 4; i++) {
        int lin = i * 256 + tid;              // 1024
        int r = lin >> 4, c = lin & 15;
        cp16(dst + 16384 + r * 256 + ((c ^ (r & 7)) << 4),
             Vb + (size_t)r * TT + ktbase + c * 8);
    }
    asm volatile("cp.async.commit_group;" ::: "memory");
}

__global__ __launch_bounds__(256, 1) void attn_kernel(
    const __half* __restrict__ Qg, const __half* __restrict__ Kg,
    const __half* __restrict__ Vtg,
    __nv_bfloat16* __restrict__ Yh, __nv_bfloat16* __restrict__ Yl)
{
    extern __shared__ char smem[];
    uint32_t sb = smem_u32(smem);
    uint32_t sQ = sb;
    uint32_t sKV = sb + 16384;

    const int tid = threadIdx.x;
    const int wid = tid >> 5, lane = tid & 31;
    const int grp = lane >> 3, l8 = lane & 7;
    const int qt = (int)gridDim.x - 1 - (int)blockIdx.x;   // longest first
    const int bh = blockIdx.y;
    const int q0 = qt * 128;

    const __half* Qb = Qg + ((size_t)bh * TT + q0) * HDD;
    const __half* Kb = Kg + (size_t)bh * TT * HDD;
    const __half* Vb = Vtg + (size_t)bh * HDD * TT;

    // G0 = Q + kv tile 0
    #pragma unroll
    for (int i = 0; i < 4; i++) {
        int lin = i * 256 + tid;
        int r = lin >> 3, c = lin & 7;
        cp16(sQ + r * 128 + ((c ^ (r & 7)) << 4), Qb + (size_t)r * HDD + c * 8);
    }
    attn_load_kv(sKV, Kb, Vb, 0, tid);
    if (qt >= 1) attn_load_kv(sKV + KV_STAGE, Kb, Vb, 128, tid);   // G1

    uint32_t qf[4][4];
    float m0 = -1e30f, m1 = -1e30f, l0 = 0.f, l1 = 0.f;
    float oacc[8][4];
    #pragma unroll
    for (int nj = 0; nj < 8; nj++)
        #pragma unroll
        for (int e = 0; e < 4; e++) oacc[nj][e] = 0.f;

    const int rquad = lane >> 2;       // 0..7
    const int cpair = (lane & 3) * 2;  // 0,2,4,6

    for (int kt = 0; kt <= qt; kt++) {
        if (kt + 1 <= qt) { asm volatile("cp.async.wait_group 1;" ::: "memory"); }
        else              { asm volatile("cp.async.wait_group 0;" ::: "memory"); }
        __syncthreads();

        if (kt == 0) {
            #pragma unroll
            for (int kc = 0; kc < 4; kc++) {
                int row = wid * 16 + (grp & 1) * 8 + l8;
                int ch = kc * 2 + (grp >> 1);
                ldsm4(qf[kc], sQ + row * 128 + ((ch ^ (row & 7)) << 4));
            }
        }

        uint32_t sK = sKV + (kt % 3) * KV_STAGE;
        uint32_t sV = sK + 16384;
        const bool diag = (kt == qt);
        const int jmax = diag ? (wid + 1) : 8;

        // S = Q K^T  (16 n8 tiles)
        float sacc[16][4];
        #pragma unroll
        for (int nj = 0; nj < 16; nj++)
            #pragma unroll
            for (int e = 0; e < 4; e++) sacc[nj][e] = 0.f;

        #pragma unroll
        for (int ks = 0; ks < 4; ks++) {
            #pragma unroll
            for (int j = 0; j < 8; j++) {
                if (j < jmax) {
                    int row = j * 16 + (grp >> 1) * 8 + l8;
                    int ch = ks * 2 + (grp & 1);
                    uint32_t rr[4];
                    ldsm4(rr, sK + row * 128 + ((ch ^ (row & 7)) << 4));
                    uint32_t b0[2] = {rr[0], rr[1]}, b1[2] = {rr[2], rr[3]};
                    mma16816h(sacc[2 * j], qf[ks], b0);
                    mma16816h(sacc[2 * j + 1], qf[ks], b1);
                }
            }
        }

        // scale + causal mask
        const float sc = 0.125f;
        if (diag) {
            int row0g = q0 + wid * 16 + rquad;
            #pragma unroll
            for (int nj = 0; nj < 16; nj++) {
                int colg = kt * 128 + nj * 8 + cpair;
                #pragma unroll
                for (int e = 0; e < 4; e++) {
                    int cg = colg + (e & 1);
                    int rg = row0g + ((e >= 2) ? 8 : 0);
                    sacc[nj][e] = (cg <= rg) ? sacc[nj][e] * sc : -1e30f;
                }
            }
        } else {
            #pragma unroll
            for (int nj = 0; nj < 16; nj++)
                #pragma unroll
                for (int e = 0; e < 4; e++) sacc[nj][e] *= sc;
        }

        // online softmax (two rows per thread; 4-lane quad reductions)
        float rm0 = -1e30f, rm1 = -1e30f;
        #pragma unroll
        for (int nj = 0; nj < 16; nj++) {
            rm0 = fmaxf(rm0, fmaxf(sacc[nj][0], sacc[nj][1]));
            rm1 = fmaxf(rm1, fmaxf(sacc[nj][2], sacc[nj][3]));
        }
        rm0 = fmaxf(rm0, __shfl_xor_sync(0xffffffffu, rm0, 1));
        rm0 = fmaxf(rm0, __shfl_xor_sync(0xffffffffu, rm0, 2));
        rm1 = fmaxf(rm1, __shfl_xor_sync(0xffffffffu, rm1, 1));
        rm1 = fmaxf(rm1, __shfl_xor_sync(0xffffffffu, rm1, 2));

        float n0 = fmaxf(m0, rm0), n1 = fmaxf(m1, rm1);
        float a0 = __expf(m0 - n0), a1 = __expf(m1 - n1);
        float rs0 = 0.f, rs1 = 0.f;
        #pragma unroll
        for (int nj = 0; nj < 16; nj++) {
            sacc[nj][0] = __expf(sacc[nj][0] - n0);
            sacc[nj][1] = __expf(sacc[nj][1] - n0);
            sacc[nj][2] = __expf(sacc[nj][2] - n1);
            sacc[nj][3] = __expf(sacc[nj][3] - n1);
            rs0 += sacc[nj][0] + sacc[nj][1];
            rs1 += sacc[nj][2] + sacc[nj][3];
        }
        rs0 += __shfl_xor_sync(0xffffffffu, rs0, 1);
        rs0 += __shfl_xor_sync(0xffffffffu, rs0, 2);
        rs1 += __shfl_xor_sync(0xffffffffu, rs1, 1);
        rs1 += __shfl_xor_sync(0xffffffffu, rs1, 2);

        l0 = l0 * a0 + rs0;
        l1 = l1 * a1 + rs1;
        m0 = n0; m1 = n1;
        #pragma unroll
        for (int nj = 0; nj < 8; nj++) {
            oacc[nj][0] *= a0; oacc[nj][1] *= a0;
            oacc[nj][2] *= a1; oacc[nj][3] *= a1;
        }

        // pack P into A-fragments (registers only): kc = t-chunk 0..7
        uint32_t pf[8][4];
        #pragma unroll
        for (int kc = 0; kc < 8; kc++) {
            pf[kc][0] = packh2(sacc[2 * kc][0],     sacc[2 * kc][1]);
            pf[kc][1] = packh2(sacc[2 * kc][2],     sacc[2 * kc][3]);
            pf[kc][2] = packh2(sacc[2 * kc + 1][0], sacc[2 * kc + 1][1]);
            pf[kc][3] = packh2(sacc[2 * kc + 1][2], sacc[2 * kc + 1][3]);
        }

        // O += P @ V  (V [d][t], 256B rows)
        const int kcmax = diag ? (wid + 1) : 8;
        #pragma unroll
        for (int kc = 0; kc < 8; kc++) {
            if (kc < kcmax) {
                #pragma unroll
                for (int nj = 0; nj < 4; nj++) {
                    int row = nj * 16 + (grp >> 1) * 8 + l8;   // d rows
                    int ch = kc * 2 + (grp & 1);               // t chunks
                    uint32_t rr[4];
                    ldsm4(rr, sV + row * 256 + ((ch ^ (row & 7)) << 4));
                    uint32_t b0[2] = {rr[0], rr[1]}, b1[2] = {rr[2], rr[3]};
                    mma16816h(oacc[2 * nj], pf[kc], b0);
                    mma16816h(oacc[2 * nj + 1], pf[kc], b1);
                }
            }
        }

        // prefetch kv tile kt+2 (overwrites slot of kt-1; safe past this sync)
        if (kt + 2 <= qt)
            attn_load_kv(sKV + ((kt + 2) % 3) * KV_STAGE, Kb, Vb, (kt + 2) * 128, tid);
    }

    // epilogue: normalize + split-bf16 store to [b,t,c]
    float i0 = 1.f / l0, i1 = 1.f / l1;
    int b_ = bh >> 4, h = bh & 15;
    int r0g = q0 + wid * 16 + rquad;
    #pragma unroll
    for (int nj = 0; nj < 8; nj++) {
        int c = h * 64 + nj * 8 + cpair;
        float v0 = oacc[nj][0] * i0, v1 = oacc[nj][1] * i0;
        float v2 = oacc[nj][2] * i1, v3 = oacc[nj][3] * i1;
        size_t o0 = (size_t)(b_ * TT + r0g) * CC + c;
        size_t o1 = (size_t)(b_ * TT + r0g + 8) * CC + c;
        __nv_bfloat16 h0 = __float2bfloat16(v0), h1 = __float2bfloat16(v1);
        __nv_bfloat16 h2 = __float2bfloat16(v2), h3 = __float2bfloat16(v3);
        *(__nv_bfloat162*)&Yh[o0] = __nv_bfloat162(h0, h1);
        *(__nv_bfloat162*)&Yh[o1] = __nv_bfloat162(h2, h3);
        *(__nv_bfloat162*)&Yl[o0] = __nv_bfloat162(
            __float2bfloat16(v0 - __bfloat162float(h0)),
            __float2bfloat16(v1 - __bfloat162float(h1)));
        *(__nv_bfloat162*)&Yl[o1] = __nv_bfloat162(
            __float2bfloat16(v2 - __bfloat162float(h2)),
            __float2bfloat16(v3 - __bfloat162float(h3)));
    }
}

// ---------------- launch ---------------------------------------------------
extern "C" void kernel_launch(void* const* d_in, const int* in_sizes, int n_in,
                              void* d_out, int out_size)
{
    const float* x     = (const float*)d_in[0];
    const float* Wqkv  = (const float*)d_in[1];
    const float* bqkv  = (const float*)d_in[2];
    const float* Wproj = (const float*)d_in[3];
    const float* bproj = (const float*)d_in[4];
    float* out = (float*)d_out;

    float *ct, *st;
    __nv_bfloat16 *xh, *xl, *wqh, *wql, *wph, *wpl, *yh, *yl;
    __half *qh, *kh, *vh, *vt;
    cudaGetSymbolAddress((void**)&ct, g_cost);
    cudaGetSymbolAddress((void**)&st, g_sint);
    cudaGetSymbolAddress((void**)&xh, g_xh);
    cudaGetSymbolAddress((void**)&xl, g_xl);
    cudaGetSymbolAddress((void**)&wqh, g_wqh);
    cudaGetSymbolAddress((void**)&wql, g_wql);
    cudaGetSymbolAddress((void**)&wph, g_wph);
    cudaGetSymbolAddress((void**)&wpl, g_wpl);
    cudaGetSymbolAddress((void**)&yh, g_yh);
    cudaGetSymbolAddress((void**)&yl, g_yl);
    cudaGetSymbolAddress((void**)&qh, g_qh);
    cudaGetSymbolAddress((void**)&kh, g_kh);
    cudaGetSymbolAddress((void**)&vh, g_vh);
    cudaGetSymbolAddress((void**)&vt, g_vt);

    cudaFuncSetAttribute(tc_gemm_kernel<0>,
                         cudaFuncAttributeMaxDynamicSharedMemorySize, GSMEM);
    cudaFuncSetAttribute(tc_gemm_kernel<1>,
                         cudaFuncAttributeMaxDynamicSharedMemorySize, GSMEM);
    cudaFuncSetAttribute(attn_kernel,
                         cudaFuncAttributeMaxDynamicSharedMemorySize, AT_SMEM);

    // conversions
    split_kernel<<<(ROWS * CC) / 256, 256>>>(x, xh, xl, ROWS * CC);
    transpose_split_kernel<<<dim3(CC / 32, N_QKV / 32), 256>>>(Wqkv, wqh, wql, CC, N_QKV);
    transpose_split_kernel<<<dim3(CC / 32, CC / 32), 256>>>(Wproj, wph, wpl, CC, CC);
    rope_table_kernel<<<(TT * 32) / 256, 256>>>(ct, st);

    // 1) QKV GEMM + bias + fused RoPE -> fp16 Q,K,V
    tc_gemm_kernel<1><<<dim3(N_QKV / 128, ROWS / 128), 256, GSMEM>>>(
        xh, xl, wqh, wql, bqkv, nullptr, qh, kh, vh, ct, st, N_QKV, CC);

    // 2) V transpose fp16 [bh][t][d] -> [bh][d][t]
    vt_kernel<<<dim3(TT / 64, BB * NHH), 256>>>(vh, vt);

    // 3) tensor-core causal flash attention -> split-bf16 Y
    attn_kernel<<<dim3(TT / 128, BB * NHH), 256, AT_SMEM>>>(qh, kh, vt, yh, yl);

    // 4) output projection + bias
    tc_gemm_kernel<0><<<dim3(CC / 128, ROWS / 128), 256, GSMEM>>>(
        yh, yl, wph, wpl, bproj, out, nullptr, nullptr, nullptr, ct, st, CC, CC);
}

// round 7
// speedup vs baseline: 1.0276x; 1.0276x over previous
#include <cuda_runtime.h>
#include <cuda_bf16.h>
#include <cuda_fp16.h>
#include <math.h>
#include <stdint.h>

// Problem constants
#define BB 4
#define TT 2048
#define CC 1024
#define NHH 16
#define HDD 64
#define ROWS (BB*TT)          // 8192
#define N_QKV (3*CC)          // 3072

// ---------------- scratch (device globals; no allocation) ----------------
__device__ __nv_bfloat16 g_xh[(size_t)ROWS * CC];
__device__ __nv_bfloat16 g_xl[(size_t)ROWS * CC];
__device__ __nv_bfloat16 g_wqh[(size_t)N_QKV * CC];   // [N,K] transposed
__device__ __nv_bfloat16 g_wql[(size_t)N_QKV * CC];
__device__ __nv_bfloat16 g_wph[(size_t)CC * CC];
__device__ __nv_bfloat16 g_wpl[(size_t)CC * CC];
__device__ __nv_bfloat16 g_yh[(size_t)ROWS * CC];
__device__ __nv_bfloat16 g_yl[(size_t)ROWS * CC];
__device__ float g_cost[(size_t)TT * 32];
__device__ float g_sint[(size_t)TT * 32];

__device__ __half g_qh[(size_t)BB * NHH * TT * HDD];  // [bh][t][d]
__device__ __half g_kh[(size_t)BB * NHH * TT * HDD];  // [bh][t][d]
__device__ __half g_vh[(size_t)BB * NHH * TT * HDD];  // [bh][t][d]
__device__ __half g_vt[(size_t)BB * NHH * HDD * TT];  // [bh][d][t]

// ---------------- PTX helpers (arch-baseline only: no tcgen05) ------------
__device__ __forceinline__ uint32_t smem_u32(const void* p) {
    uint32_t a;
    asm("{ .reg .u64 t; cvta.to.shared.u64 t, %1; cvt.u32.u64 %0, t; }" : "=r"(a) : "l"(p));
    return a;
}
__device__ __forceinline__ void cp16(uint32_t saddr, const void* g) {
    asm volatile("cp.async.cg.shared.global [%0], [%1], 16;" :: "r"(saddr), "l"(g));
}
__device__ __forceinline__ void ldsm4(uint32_t* r, uint32_t addr) {
    asm volatile("ldmatrix.sync.aligned.m8n8.x4.shared.b16 {%0,%1,%2,%3}, [%4];"
                 : "=r"(r[0]), "=r"(r[1]), "=r"(r[2]), "=r"(r[3]) : "r"(addr));
}
__device__ __forceinline__ void mma16816(float* c, const uint32_t* a, const uint32_t* b) {
    asm volatile(
        "mma.sync.aligned.m16n8k16.row.col.f32.bf16.bf16.f32 "
        "{%0,%1,%2,%3}, {%4,%5,%6,%7}, {%8,%9}, {%0,%1,%2,%3};"
        : "+f"(c[0]), "+f"(c[1]), "+f"(c[2]), "+f"(c[3])
        : "r"(a[0]), "r"(a[1]), "r"(a[2]), "r"(a[3]), "r"(b[0]), "r"(b[1]));
}
__device__ __forceinline__ void mma16816h(float* c, const uint32_t* a, const uint32_t* b) {
    asm volatile(
        "mma.sync.aligned.m16n8k16.row.col.f32.f16.f16.f32 "
        "{%0,%1,%2,%3}, {%4,%5,%6,%7}, {%8,%9}, {%0,%1,%2,%3};"
        : "+f"(c[0]), "+f"(c[1]), "+f"(c[2]), "+f"(c[3])
        : "r"(a[0]), "r"(a[1]), "r"(a[2]), "r"(a[3]), "r"(b[0]), "r"(b[1]));
}
__device__ __forceinline__ uint32_t packh2(float a, float b) {
    __half2 h = __floats2half2_rn(a, b);
    return *(uint32_t*)&h;
}

// ---------------- precision-split conversions ------------------------------
__global__ __launch_bounds__(256) void split_kernel(
    const float* __restrict__ in, __nv_bfloat16* __restrict__ hi,
    __nv_bfloat16* __restrict__ lo, int n)
{
    int i = blockIdx.x * 256 + threadIdx.x;
    if (i >= n) return;
    float v = in[i];
    __nv_bfloat16 h = __float2bfloat16(v);
    hi[i] = h;
    lo[i] = __float2bfloat16(v - __bfloat162float(h));
}

// W[K,N] f32 -> hi/lo[N,K] bf16 (transpose + split)
__global__ __launch_bounds__(256) void transpose_split_kernel(
    const float* __restrict__ W, __nv_bfloat16* __restrict__ hi,
    __nv_bfloat16* __restrict__ lo, int K, int N)
{
    __shared__ float tile[32][33];
    int k0 = blockIdx.x * 32, n0 = blockIdx.y * 32;
    int tx = threadIdx.x & 31, ty = threadIdx.x >> 5;   // 32x8
    #pragma unroll
    for (int r = 0; r < 4; r++)
        tile[ty + 8 * r][tx] = W[(size_t)(k0 + ty + 8 * r) * N + n0 + tx];
    __syncthreads();
    #pragma unroll
    for (int r = 0; r < 4; r++) {
        float v = tile[tx][ty + 8 * r];
        __nv_bfloat16 h = __float2bfloat16(v);
        size_t o = (size_t)(n0 + ty + 8 * r) * K + k0 + tx;
        hi[o] = h;
        lo[o] = __float2bfloat16(v - __bfloat162float(h));
    }
}

// ---------------- RoPE table (mimic jax f32 computation) -------------------
__global__ __launch_bounds__(256) void rope_table_kernel(float* ct, float* st) {
    int idx = blockIdx.x * 256 + threadIdx.x;   // TT*32
    int t = idx >> 5, i = idx & 31;
    float invf = (float)exp(-(double)i / 32.0 * 9.210340371976184);
    float fr = (float)t * invf;
    double a = (double)fr;
    ct[idx] = (float)cos(a);
    st[idx] = (float)sin(a);
}

// ---------------- HMMA split-bf16 GEMM (mma.sync, 3-stage) -----------------
// MODE 0: C = f32 out + bias (proj)
// MODE 1: fused QKV epilogue: bias + RoPE -> fp16 Q,K ; fp16 V  (C unused)
#define TILE_B 16384
#define STAGE_B (4*TILE_B)     // Ah, Al, Bh, Bl
#define GSMEM (3*STAGE_B)      // 196608

__device__ __forceinline__ void load_stage(
    uint32_t base, int kt, int tid, int row0, int col0, int K,
    const __nv_bfloat16* __restrict__ Ah, const __nv_bfloat16* __restrict__ Al,
    const __nv_bfloat16* __restrict__ Bh, const __nv_bfloat16* __restrict__ Bl)
{
    int k0 = kt * 64;
    const __nv_bfloat16* srcs[4] = {Ah, Al, Bh, Bl};
    #pragma unroll
    for (int t = 0; t < 4; t++) {
        int rbase = (t < 2) ? row0 : col0;
        const __nv_bfloat16* s = srcs[t];
        #pragma unroll
        for (int i = 0; i < 4; i++) {
            int lin = i * 256 + tid;
            int r = lin >> 3, c = lin & 7;
            uint32_t off = r * 128 + c * 16;
            uint32_t sw = off ^ ((off >> 3) & 0x70);
            cp16(base + t * TILE_B + sw, s + (size_t)(rbase + r) * K + k0 + c * 8);
        }
    }
    asm volatile("cp.async.commit_group;" ::: "memory");
}

template<int MODE>
__global__ __launch_bounds__(256, 1) void tc_gemm_kernel(
    const __nv_bfloat16* __restrict__ Ah, const __nv_bfloat16* __restrict__ Al,
    const __nv_bfloat16* __restrict__ Bh, const __nv_bfloat16* __restrict__ Bl,
    const float* __restrict__ bias, float* __restrict__ C,
    __half* __restrict__ Qo, __half* __restrict__ Ko, __half* __restrict__ Vo,
    const float* __restrict__ ct, const float* __restrict__ st,
    int N, int K)
{
    extern __shared__ char smem[];
    uint32_t sb = smem_u32(smem);
    const int tid = threadIdx.x;
    const int wid = tid >> 5, lane = tid & 31;
    const int wr = (wid & 3) * 32;
    const int wc = (wid >> 2) * 64;
    const int col0 = blockIdx.x * 128;
    const int row0 = blockIdx.y * 128;
    const int NK = K >> 6;

    float acc[2][8][4];
    #pragma unroll
    for (int mi = 0; mi < 2; mi++)
        #pragma unroll
        for (int ni = 0; ni < 8; ni++)
            #pragma unroll
            for (int j = 0; j < 4; j++) acc[mi][ni][j] = 0.f;

    load_stage(sb, 0, tid, row0, col0, K, Ah, Al, Bh, Bl);
    if (NK > 1)
        load_stage(sb + STAGE_B, 1, tid, row0, col0, K, Ah, Al, Bh, Bl);

    const int grp = lane >> 3, l8 = lane & 7;

    for (int kt = 0; kt < NK; kt++) {
        if (kt + 1 < NK) { asm volatile("cp.async.wait_group 1;" ::: "memory"); }
        else             { asm volatile("cp.async.wait_group 0;" ::: "memory"); }
        __syncthreads();

        uint32_t sbase = sb + (kt % 3) * STAGE_B;
        #pragma unroll
        for (int p = 0; p < 3; p++) {
            uint32_t abase = sbase + ((p == 2) ? TILE_B : 0);
            uint32_t bbase = sbase + ((p == 1) ? 3 * TILE_B : 2 * TILE_B);
            #pragma unroll
            for (int ks = 0; ks < 4; ks++) {
                uint32_t a[2][4], b[8][2];
                #pragma unroll
                for (int mi = 0; mi < 2; mi++) {
                    int row = wr + mi * 16 + (grp & 1) * 8 + l8;
                    int chunk = ks * 2 + (grp >> 1);
                    ldsm4(a[mi], abase + row * 128 + ((chunk ^ (row & 7)) << 4));
                }
                #pragma unroll
                for (int nj = 0; nj < 4; nj++) {
                    int row = wc + nj * 16 + (grp >> 1) * 8 + l8;
                    int chunk = ks * 2 + (grp & 1);
                    uint32_t rr[4];
                    ldsm4(rr, bbase + row * 128 + ((chunk ^ (row & 7)) << 4));
                    b[2 * nj][0] = rr[0]; b[2 * nj][1] = rr[1];
                    b[2 * nj + 1][0] = rr[2]; b[2 * nj + 1][1] = rr[3];
                }
                #pragma unroll
                for (int mi = 0; mi < 2; mi++)
                    #pragma unroll
                    for (int ni = 0; ni < 8; ni++)
                        mma16816(acc[mi][ni], a[mi], b[ni]);
            }
        }
        if (kt + 2 < NK)
            load_stage(sb + ((kt + 2) % 3) * STAGE_B, kt + 2, tid, row0, col0, K,
                       Ah, Al, Bh, Bl);
    }

    const int qr = lane >> 2, qc = (lane & 3) * 2;

    if (MODE == 0) {
        #pragma unroll
        for (int mi = 0; mi < 2; mi++) {
            #pragma unroll
            for (int ni = 0; ni < 8; ni++) {
                int r = row0 + wr + mi * 16 + qr;
                int c = col0 + wc + ni * 8 + qc;
                float b0 = bias[c], b1 = bias[c + 1];
                float2 o0 = make_float2(acc[mi][ni][0] + b0, acc[mi][ni][1] + b1);
                float2 o1 = make_float2(acc[mi][ni][2] + b0, acc[mi][ni][3] + b1);
                *(float2*)&C[(size_t)r * N + c] = o0;
                *(float2*)&C[(size_t)(r + 8) * N + c] = o1;
            }
        }
    } else {
        // fused QKV epilogue: bias + RoPE -> fp16
        int cb = col0 + wc;                 // 64-aligned head base
        int sec = cb >> 10;                 // 0=q, 1=k, 2=v
        int h = (cb & 1023) >> 6;
        #pragma unroll
        for (int mi = 0; mi < 2; mi++) {
            int r0 = row0 + wr + mi * 16 + qr;
            #pragma unroll
            for (int half = 0; half < 2; half++) {
                int r = r0 + half * 8;
                int e = half * 2;
                int t = r & (TT - 1);
                int b_ = r >> 11;
                size_t rowoff = ((size_t)((b_ * NHH + h) * TT + t)) * HDD;
                #pragma unroll
                for (int nj = 0; nj < 4; nj++) {
                    int d0 = nj * 8 + qc;            // even, < 32
                    int c0 = cb + d0;
                    float u00 = acc[mi][nj][e]     + bias[c0];
                    float u01 = acc[mi][nj][e + 1] + bias[c0 + 1];
                    float u10 = acc[mi][nj + 4][e]     + bias[c0 + 32];
                    float u11 = acc[mi][nj + 4][e + 1] + bias[c0 + 33];
                    if (sec < 2) {
                        float cA = ct[t * 32 + d0], cB = ct[t * 32 + d0 + 1];
                        float sA = st[t * 32 + d0], sB = st[t * 32 + d0 + 1];
                        float lo0 = u00 * cA - u10 * sA;
                        float lo1 = u01 * cB - u11 * sB;
                        float hi0 = u10 * cA + u00 * sA;
                        float hi1 = u11 * cB + u01 * sB;
                        __half* dst = (sec == 0) ? Qo : Ko;
                        *(__half2*)&dst[rowoff + d0]      = __floats2half2_rn(lo0, lo1);
                        *(__half2*)&dst[rowoff + d0 + 32] = __floats2half2_rn(hi0, hi1);
                    } else {
                        *(__half2*)&Vo[rowoff + d0]      = __floats2half2_rn(u00, u01);
                        *(__half2*)&Vo[rowoff + d0 + 32] = __floats2half2_rn(u10, u11);
                    }
                }
            }
        }
    }
}

// ---------------- fp16 V transpose: [bh][t][d] -> [bh][d][t] ---------------
__global__ __launch_bounds__(256) void vt_kernel(
    const __half* __restrict__ Vh, __half* __restrict__ Vt)
{
    __shared__ __half sm[64][72];
    int t0 = blockIdx.x * 64;
    int bh = blockIdx.y;
    const __half* src = Vh + ((size_t)bh * TT + t0) * HDD;
    #pragma unroll
    for (int i = 0; i < 2; i++) {
        int lin = i * 256 + threadIdx.x;      // 512 x 8 halfs
        int r = lin >> 3, c = (lin & 7) * 8;
        uint4 v = *(const uint4*)(src + (size_t)r * HDD + c);
        __half hv[8];
        *(uint4*)hv = v;
        #pragma unroll
        for (int j = 0; j < 8; j++) sm[c + j][r] = hv[j];
    }
    __syncthreads();
    #pragma unroll
    for (int i = 0; i < 2; i++) {
        int lin = i * 256 + threadIdx.x;
        int d = lin >> 3, tc = (lin & 7) * 8;
        *(uint4*)&Vt[((size_t)bh * HDD + d) * TT + t0 + tc] = *(uint4*)&sm[d][tc];
    }
}

// ---------------- Tensor-core flash attention (fp16, BM=128 BN=64) ---------
// 256 threads (8 warps x 16 q-rows), 2-stage KV pipeline, diag work skipping.
#define AT_SMEM (16384 + 2*16384)   // Q + 2 stages of (K 8KB + V 8KB)

__device__ __forceinline__ void attn_load_kv(
    uint32_t dst, const __half* __restrict__ Kb, const __half* __restrict__ Vb,
    int ktbase, int tid)
{
    #pragma unroll
    for (int i = 0; i < 2; i++) {
        int lin = i * 256 + tid;
        int r = lin >> 3, c = lin & 7;
        uint32_t sw = r * 128 + ((c ^ (r & 7)) << 4);
        cp16(dst + sw, Kb + (size_t)(ktbase + r) * HDD + c * 8);
        cp16(dst + 8192 + sw, Vb + (size_t)r * TT + ktbase + c * 8);
    }
    asm volatile("cp.async.commit_group;" ::: "memory");
}

__global__ __launch_bounds__(256, 1) void attn_kernel(
    const __half* __restrict__ Qg, const __half* __restrict__ Kg,
    const __half* __restrict__ Vtg,
    __nv_bfloat16* __restrict__ Yh, __nv_bfloat16* __restrict__ Yl)
{
    extern __shared__ char smem[];
    uint32_t sb = smem_u32(smem);
    uint32_t sQ = sb;
    uint32_t sKV = sb + 16384;

    const int tid = threadIdx.x;
    const int wid = tid >> 5, lane = tid & 31;
    const int grp = lane >> 3, l8 = lane & 7;
    const int qt = (int)gridDim.x - 1 - (int)blockIdx.x;   // longest first
    const int bh = blockIdx.y;
    const int q0 = qt * 128;
    const int nkt = 2 * qt + 2;

    const __half* Qb = Qg + ((size_t)bh * TT + q0) * HDD;
    const __half* Kb = Kg + (size_t)bh * TT * HDD;
    const __half* Vb = Vtg + (size_t)bh * HDD * TT;

    // stage Q (group 0) then prefetch kv tile 0 (group 1)
    #pragma unroll
    for (int i = 0; i < 4; i++) {
        int lin = i * 256 + tid;
        int r = lin >> 3, c = lin & 7;
        cp16(sQ + r * 128 + ((c ^ (r & 7)) << 4), Qb + (size_t)r * HDD + c * 8);
    }
    asm volatile("cp.async.commit_group;" ::: "memory");
    attn_load_kv(sKV, Kb, Vb, 0, tid);

    asm volatile("cp.async.wait_group 1;" ::: "memory");   // Q ready
    __syncthreads();

    // preload Q fragments
    uint32_t qf[4][4];
    #pragma unroll
    for (int kc = 0; kc < 4; kc++) {
        int row = wid * 16 + (grp & 1) * 8 + l8;
        int ch = kc * 2 + (grp >> 1);
        ldsm4(qf[kc], sQ + row * 128 + ((ch ^ (row & 7)) << 4));
    }

    float m0 = -1e30f, m1 = -1e30f, l0 = 0.f, l1 = 0.f;
    float oacc[8][4];
    #pragma unroll
    for (int nj = 0; nj < 8; nj++)
        #pragma unroll
        for (int e = 0; e < 4; e++) oacc[nj][e] = 0.f;

    const int rquad = lane >> 2;       // 0..7
    const int cpair = (lane & 3) * 2;  // 0,2,4,6

    for (int kt = 0; kt < nkt; kt++) {
        int s = kt & 1;
        if (kt + 1 < nkt) {
            attn_load_kv(sKV + (s ^ 1) * 16384, Kb, Vb, (kt + 1) * 64, tid);
            asm volatile("cp.async.wait_group 1;" ::: "memory");
        } else {
            asm volatile("cp.async.wait_group 0;" ::: "memory");
        }
        __syncthreads();

        uint32_t sK = sKV + s * 16384;
        uint32_t sV = sK + 8192;

        // diagonal work skipping: nb = # of active 16-col blocks (of 4)
        int nb = 4;
        if (kt == nkt - 2)      nb = (wid + 1 < 4) ? wid + 1 : 4;
        else if (kt == nkt - 1) nb = (wid >= 4) ? ((wid - 3 < 4) ? wid - 3 : 4) : 0;

        // S = Q K^T
        float sacc[8][4];
        #pragma unroll
        for (int nj = 0; nj < 8; nj++)
            #pragma unroll
            for (int e = 0; e < 4; e++) sacc[nj][e] = 0.f;

        #pragma unroll
        for (int ks = 0; ks < 4; ks++) {
            #pragma unroll
            for (int nj = 0; nj < 4; nj++) {
                if (nj < nb) {
                    int row = nj * 16 + (grp >> 1) * 8 + l8;
                    int ch = ks * 2 + (grp & 1);
                    uint32_t rr[4];
                    ldsm4(rr, sK + row * 128 + ((ch ^ (row & 7)) << 4));
                    uint32_t b0[2] = {rr[0], rr[1]}, b1[2] = {rr[2], rr[3]};
                    mma16816h(sacc[2 * nj], qf[ks], b0);
                    mma16816h(sacc[2 * nj + 1], qf[ks], b1);
                }
            }
        }

        // scale + causal mask (only last two tiles touch the diagonal)
        const float sc = 0.125f;
        if (kt >= nkt - 2) {
            int row0g = q0 + wid * 16 + rquad;
            #pragma unroll
            for (int nj = 0; nj < 8; nj++) {
                int colg = kt * 64 + nj * 8 + cpair;
                #pragma unroll
                for (int e = 0; e < 4; e++) {
                    int cg = colg + (e & 1);
                    int rg = row0g + ((e >= 2) ? 8 : 0);
                    sacc[nj][e] = (cg <= rg) ? sacc[nj][e] * sc : -1e30f;
                }
            }
        } else {
            #pragma unroll
            for (int nj = 0; nj < 8; nj++)
                #pragma unroll
                for (int e = 0; e < 4; e++) sacc[nj][e] *= sc;
        }

        // online softmax (two rows per thread; 4-lane quad reductions)
        float rm0 = -1e30f, rm1 = -1e30f;
        #pragma unroll
        for (int nj = 0; nj < 8; nj++) {
            rm0 = fmaxf(rm0, fmaxf(sacc[nj][0], sacc[nj][1]));
            rm1 = fmaxf(rm1, fmaxf(sacc[nj][2], sacc[nj][3]));
        }
        rm0 = fmaxf(rm0, __shfl_xor_sync(0xffffffffu, rm0, 1));
        rm0 = fmaxf(rm0, __shfl_xor_sync(0xffffffffu, rm0, 2));
        rm1 = fmaxf(rm1, __shfl_xor_sync(0xffffffffu, rm1, 1));
        rm1 = fmaxf(rm1, __shfl_xor_sync(0xffffffffu, rm1, 2));

        float n0 = fmaxf(m0, rm0), n1 = fmaxf(m1, rm1);
        float a0 = __expf(m0 - n0), a1 = __expf(m1 - n1);
        float rs0 = 0.f, rs1 = 0.f;
        #pragma unroll
        for (int nj = 0; nj < 8; nj++) {
            sacc[nj][0] = __expf(sacc[nj][0] - n0);
            sacc[nj][1] = __expf(sacc[nj][1] - n0);
            sacc[nj][2] = __expf(sacc[nj][2] - n1);
            sacc[nj][3] = __expf(sacc[nj][3] - n1);
            rs0 += sacc[nj][0] + sacc[nj][1];
            rs1 += sacc[nj][2] + sacc[nj][3];
        }
        rs0 += __shfl_xor_sync(0xffffffffu, rs0, 1);
        rs0 += __shfl_xor_sync(0xffffffffu, rs0, 2);
        rs1 += __shfl_xor_sync(0xffffffffu, rs1, 1);
        rs1 += __shfl_xor_sync(0xffffffffu, rs1, 2);

        l0 = l0 * a0 + rs0;
        l1 = l1 * a1 + rs1;
        m0 = n0; m1 = n1;
        #pragma unroll
        for (int nj = 0; nj < 8; nj++) {
            oacc[nj][0] *= a0; oacc[nj][1] *= a0;
            oacc[nj][2] *= a1; oacc[nj][3] *= a1;
        }

        // pack P into A-operand fragments (registers only)
        uint32_t pf[4][4];
        #pragma unroll
        for (int kc = 0; kc < 4; kc++) {
            pf[kc][0] = packh2(sacc[2 * kc][0],     sacc[2 * kc][1]);
            pf[kc][1] = packh2(sacc[2 * kc][2],     sacc[2 * kc][3]);
            pf[kc][2] = packh2(sacc[2 * kc + 1][0], sacc[2 * kc + 1][1]);
            pf[kc][3] = packh2(sacc[2 * kc + 1][2], sacc[2 * kc + 1][3]);
        }

        // O += P @ V   (V [d][t]; skip t-chunks with all-zero P on diag tiles)
        #pragma unroll
        for (int kc = 0; kc < 4; kc++) {
            if (kc < nb) {
                #pragma unroll
                for (int nj = 0; nj < 4; nj++) {
                    int row = nj * 16 + (grp >> 1) * 8 + l8;
                    int ch = kc * 2 + (grp & 1);
                    uint32_t rr[4];
                    ldsm4(rr, sV + row * 128 + ((ch ^ (row & 7)) << 4));
                    uint32_t b0[2] = {rr[0], rr[1]}, b1[2] = {rr[2], rr[3]};
                    mma16816h(oacc[2 * nj], pf[kc], b0);
                    mma16816h(oacc[2 * nj + 1], pf[kc], b1);
                }
            }
        }
        __syncthreads();
    }

    // epilogue: normalize + split-bf16 store to [b,t,c]
    float i0 = 1.f / l0, i1 = 1.f / l1;
    int b_ = bh >> 4, h = bh & 15;
    int r0g = q0 + wid * 16 + rquad;
    #pragma unroll
    for (int nj = 0; nj < 8; nj++) {
        int c = h * 64 + nj * 8 + cpair;
        float v0 = oacc[nj][0] * i0, v1 = oacc[nj][1] * i0;
        float v2 = oacc[nj][2] * i1, v3 = oacc[nj][3] * i1;
        size_t o0 = (size_t)(b_ * TT + r0g) * CC + c;
        size_t o1 = (size_t)(b_ * TT + r0g + 8) * CC + c;
        __nv_bfloat16 h0 = __float2bfloat16(v0), h1 = __float2bfloat16(v1);
        __nv_bfloat16 h2 = __float2bfloat16(v2), h3 = __float2bfloat16(v3);
        *(__nv_bfloat162*)&Yh[o0] = __nv_bfloat162(h0, h1);
        *(__nv_bfloat162*)&Yh[o1] = __nv_bfloat162(h2, h3);
        *(__nv_bfloat162*)&Yl[o0] = __nv_bfloat162(
            __float2bfloat16(v0 - __bfloat162float(h0)),
            __float2bfloat16(v1 - __bfloat162float(h1)));
        *(__nv_bfloat162*)&Yl[o1] = __nv_bfloat162(
            __float2bfloat16(v2 - __bfloat162float(h2)),
            __float2bfloat16(v3 - __bfloat162float(h3)));
    }
}

// ---------------- launch ---------------------------------------------------
extern "C" void kernel_launch(void* const* d_in, const int* in_sizes, int n_in,
                              void* d_out, int out_size)
{
    const float* x     = (const float*)d_in[0];
    const float* Wqkv  = (const float*)d_in[1];
    const float* bqkv  = (const float*)d_in[2];
    const float* Wproj = (const float*)d_in[3];
    const float* bproj = (const float*)d_in[4];
    float* out = (float*)d_out;

    float *ct, *st;
    __nv_bfloat16 *xh, *xl, *wqh, *wql, *wph, *wpl, *yh, *yl;
    __half *qh, *kh, *vh, *vt;
    cudaGetSymbolAddress((void**)&ct, g_cost);
    cudaGetSymbolAddress((void**)&st, g_sint);
    cudaGetSymbolAddress((void**)&xh, g_xh);
    cudaGetSymbolAddress((void**)&xl, g_xl);
    cudaGetSymbolAddress((void**)&wqh, g_wqh);
    cudaGetSymbolAddress((void**)&wql, g_wql);
    cudaGetSymbolAddress((void**)&wph, g_wph);
    cudaGetSymbolAddress((void**)&wpl, g_wpl);
    cudaGetSymbolAddress((void**)&yh, g_yh);
    cudaGetSymbolAddress((void**)&yl, g_yl);
    cudaGetSymbolAddress((void**)&qh, g_qh);
    cudaGetSymbolAddress((void**)&kh, g_kh);
    cudaGetSymbolAddress((void**)&vh, g_vh);
    cudaGetSymbolAddress((void**)&vt, g_vt);

    cudaFuncSetAttribute(tc_gemm_kernel<0>,
                         cudaFuncAttributeMaxDynamicSharedMemorySize, GSMEM);
    cudaFuncSetAttribute(tc_gemm_kernel<1>,
                         cudaFuncAttributeMaxDynamicSharedMemorySize, GSMEM);
    cudaFuncSetAttribute(attn_kernel,
                         cudaFuncAttributeMaxDynamicSharedMemorySize, AT_SMEM);

    // conversions
    split_kernel<<<(ROWS * CC) / 256, 256>>>(x, xh, xl, ROWS * CC);
    transpose_split_kernel<<<dim3(CC / 32, N_QKV / 32), 256>>>(Wqkv, wqh, wql, CC, N_QKV);
    transpose_split_kernel<<<dim3(CC / 32, CC / 32), 256>>>(Wproj, wph, wpl, CC, CC);
    rope_table_kernel<<<(TT * 32) / 256, 256>>>(ct, st);

    // 1) QKV GEMM + bias + fused RoPE -> fp16 Q,K,V
    tc_gemm_kernel<1><<<dim3(N_QKV / 128, ROWS / 128), 256, GSMEM>>>(
        xh, xl, wqh, wql, bqkv, nullptr, qh, kh, vh, ct, st, N_QKV, CC);

    // 2) V transpose fp16 [bh][t][d] -> [bh][d][t]
    vt_kernel<<<dim3(TT / 64, BB * NHH), 256>>>(vh, vt);

    // 3) tensor-core causal flash attention -> split-bf16 Y
    attn_kernel<<<dim3(TT / 128, BB * NHH), 256, AT_SMEM>>>(qh, kh, vt, yh, yl);

    // 4) output projection + bias
    tc_gemm_kernel<0><<<dim3(CC / 128, ROWS / 128), 256, GSMEM>>>(
        yh, yl, wph, wpl, bproj, out, nullptr, nullptr, nullptr, ct, st, CC, CC);
}

// round 8
// speedup vs baseline: 1.4279x; 1.3896x over previous
#include <cuda_runtime.h>
#include <cuda_bf16.h>
#include <cuda_fp16.h>
#include <math.h>
#include <stdint.h>

// Problem constants
#define BB 4
#define TT 2048
#define CC 1024
#define NHH 16
#define HDD 64
#define ROWS (BB*TT)          // 8192
#define N_QKV (3*CC)          // 3072

// ---------------- scratch (device globals; no allocation) ----------------
__device__ __half g_xh[(size_t)ROWS * CC];            // x hi (fp16)
__device__ __half g_xl[(size_t)ROWS * CC];            // x lo (fp16)
__device__ __half g_wq[(size_t)N_QKV * CC];           // Wqkv^T [N,K] fp16
__device__ __half g_wp[(size_t)CC * CC];              // Wproj^T [N,K] fp16
__device__ __half g_yh[(size_t)ROWS * CC];            // attn out hi (fp16)
__device__ __half g_yl[(size_t)ROWS * CC];            // attn out lo (fp16)
__device__ float g_cost[(size_t)TT * 32];
__device__ float g_sint[(size_t)TT * 32];

__device__ __half g_qh[(size_t)BB * NHH * TT * HDD];  // [bh][t][d]
__device__ __half g_kh[(size_t)BB * NHH * TT * HDD];  // [bh][t][d]
__device__ __half g_vh[(size_t)BB * NHH * TT * HDD];  // [bh][t][d]
__device__ __half g_vt[(size_t)BB * NHH * HDD * TT];  // [bh][d][t]

// ---------------- PTX helpers (arch-baseline only: no tcgen05) ------------
__device__ __forceinline__ uint32_t smem_u32(const void* p) {
    uint32_t a;
    asm("{ .reg .u64 t; cvta.to.shared.u64 t, %1; cvt.u32.u64 %0, t; }" : "=r"(a) : "l"(p));
    return a;
}
__device__ __forceinline__ void cp16(uint32_t saddr, const void* g) {
    asm volatile("cp.async.cg.shared.global [%0], [%1], 16;" :: "r"(saddr), "l"(g));
}
__device__ __forceinline__ void ldsm4(uint32_t* r, uint32_t addr) {
    asm volatile("ldmatrix.sync.aligned.m8n8.x4.shared.b16 {%0,%1,%2,%3}, [%4];"
                 : "=r"(r[0]), "=r"(r[1]), "=r"(r[2]), "=r"(r[3]) : "r"(addr));
}
__device__ __forceinline__ void mma16816h(float* c, const uint32_t* a, const uint32_t* b) {
    asm volatile(
        "mma.sync.aligned.m16n8k16.row.col.f32.f16.f16.f32 "
        "{%0,%1,%2,%3}, {%4,%5,%6,%7}, {%8,%9}, {%0,%1,%2,%3};"
        : "+f"(c[0]), "+f"(c[1]), "+f"(c[2]), "+f"(c[3])
        : "r"(a[0]), "r"(a[1]), "r"(a[2]), "r"(a[3]), "r"(b[0]), "r"(b[1]));
}
__device__ __forceinline__ uint32_t packh2(float a, float b) {
    __half2 h = __floats2half2_rn(a, b);
    return *(uint32_t*)&h;
}

// ---------------- conversions ----------------------------------------------
// x f32 -> fp16 hi + fp16 lo (exact 22-bit split)
__global__ __launch_bounds__(256) void split_kernel(
    const float* __restrict__ in, __half* __restrict__ hi,
    __half* __restrict__ lo, int n)
{
    int i = blockIdx.x * 256 + threadIdx.x;
    if (i >= n) return;
    float v = in[i];
    __half h = __float2half(v);
    hi[i] = h;
    lo[i] = __float2half(v - __half2float(h));
}

// W[K,N] f32 -> [N,K] fp16 (transpose + quantize once)
__global__ __launch_bounds__(256) void transpose_half_kernel(
    const float* __restrict__ W, __half* __restrict__ Wt, int K, int N)
{
    __shared__ float tile[32][33];
    int k0 = blockIdx.x * 32, n0 = blockIdx.y * 32;
    int tx = threadIdx.x & 31, ty = threadIdx.x >> 5;   // 32x8
    #pragma unroll
    for (int r = 0; r < 4; r++)
        tile[ty + 8 * r][tx] = W[(size_t)(k0 + ty + 8 * r) * N + n0 + tx];
    __syncthreads();
    #pragma unroll
    for (int r = 0; r < 4; r++)
        Wt[(size_t)(n0 + ty + 8 * r) * K + k0 + tx] = __float2half(tile[tx][ty + 8 * r]);
}

// ---------------- RoPE table (mimic jax f32 computation) -------------------
__global__ __launch_bounds__(256) void rope_table_kernel(float* ct, float* st) {
    int idx = blockIdx.x * 256 + threadIdx.x;   // TT*32
    int t = idx >> 5, i = idx & 31;
    float invf = (float)exp(-(double)i / 32.0 * 9.210340371976184);
    float fr = (float)t * invf;
    double a = (double)fr;
    ct[idx] = (float)cos(a);
    st[idx] = (float)sin(a);
}

// ---------------- HMMA exact-A/quantized-B GEMM (2-pass fp16) --------------
// C = (Ah + Al) @ B^T (+bias);  Ah,Al:[M,K] fp16 split of fp32 A; B:[N,K] fp16
// MODE 0: f32 out + bias (proj).  MODE 1: fused QKV bias+RoPE -> fp16 Q,K,V.
#define TILE_B 16384
#define STAGE_B (3*TILE_B)     // Ah, Al, B
#define GSMEM (3*STAGE_B)      // 147456

__device__ __forceinline__ void load_stage(
    uint32_t base, int kt, int tid, int row0, int col0, int K,
    const __half* __restrict__ Ah, const __half* __restrict__ Al,
    const __half* __restrict__ Bq)
{
    int k0 = kt * 64;
    const __half* srcs[3] = {Ah, Al, Bq};
    #pragma unroll
    for (int t = 0; t < 3; t++) {
        int rbase = (t < 2) ? row0 : col0;
        const __half* s = srcs[t];
        #pragma unroll
        for (int i = 0; i < 4; i++) {
            int lin = i * 256 + tid;
            int r = lin >> 3, c = lin & 7;
            uint32_t off = r * 128 + c * 16;
            uint32_t sw = off ^ ((off >> 3) & 0x70);
            cp16(base + t * TILE_B + sw, s + (size_t)(rbase + r) * K + k0 + c * 8);
        }
    }
    asm volatile("cp.async.commit_group;" ::: "memory");
}

template<int MODE>
__global__ __launch_bounds__(256, 1) void tc_gemm_kernel(
    const __half* __restrict__ Ah, const __half* __restrict__ Al,
    const __half* __restrict__ Bq,
    const float* __restrict__ bias, float* __restrict__ C,
    __half* __restrict__ Qo, __half* __restrict__ Ko, __half* __restrict__ Vo,
    const float* __restrict__ ct, const float* __restrict__ st,
    int N, int K)
{
    extern __shared__ char smem[];
    uint32_t sb = smem_u32(smem);
    const int tid = threadIdx.x;
    const int wid = tid >> 5, lane = tid & 31;
    const int wr = (wid & 3) * 32;
    const int wc = (wid >> 2) * 64;
    const int col0 = blockIdx.x * 128;
    const int row0 = blockIdx.y * 128;
    const int NK = K >> 6;

    float acc[2][8][4];
    #pragma unroll
    for (int mi = 0; mi < 2; mi++)
        #pragma unroll
        for (int ni = 0; ni < 8; ni++)
            #pragma unroll
            for (int j = 0; j < 4; j++) acc[mi][ni][j] = 0.f;

    load_stage(sb, 0, tid, row0, col0, K, Ah, Al, Bq);
    if (NK > 1)
        load_stage(sb + STAGE_B, 1, tid, row0, col0, K, Ah, Al, Bq);

    const int grp = lane >> 3, l8 = lane & 7;

    for (int kt = 0; kt < NK; kt++) {
        if (kt + 1 < NK) { asm volatile("cp.async.wait_group 1;" ::: "memory"); }
        else             { asm volatile("cp.async.wait_group 0;" ::: "memory"); }
        __syncthreads();

        uint32_t sbase = sb + (kt % 3) * STAGE_B;
        uint32_t bbase = sbase + 2 * TILE_B;
        #pragma unroll
        for (int p = 0; p < 2; p++) {
            uint32_t abase = sbase + p * TILE_B;
            #pragma unroll
            for (int ks = 0; ks < 4; ks++) {
                uint32_t a[2][4], b[8][2];
                #pragma unroll
                for (int mi = 0; mi < 2; mi++) {
                    int row = wr + mi * 16 + (grp & 1) * 8 + l8;
                    int chunk = ks * 2 + (grp >> 1);
                    ldsm4(a[mi], abase + row * 128 + ((chunk ^ (row & 7)) << 4));
                }
                #pragma unroll
                for (int nj = 0; nj < 4; nj++) {
                    int row = wc + nj * 16 + (grp >> 1) * 8 + l8;
                    int chunk = ks * 2 + (grp & 1);
                    uint32_t rr[4];
                    ldsm4(rr, bbase + row * 128 + ((chunk ^ (row & 7)) << 4));
                    b[2 * nj][0] = rr[0]; b[2 * nj][1] = rr[1];
                    b[2 * nj + 1][0] = rr[2]; b[2 * nj + 1][1] = rr[3];
                }
                #pragma unroll
                for (int mi = 0; mi < 2; mi++)
                    #pragma unroll
                    for (int ni = 0; ni < 8; ni++)
                        mma16816h(acc[mi][ni], a[mi], b[ni]);
            }
        }
        if (kt + 2 < NK)
            load_stage(sb + ((kt + 2) % 3) * STAGE_B, kt + 2, tid, row0, col0, K,
                       Ah, Al, Bq);
    }

    const int qr = lane >> 2, qc = (lane & 3) * 2;

    if (MODE == 0) {
        #pragma unroll
        for (int mi = 0; mi < 2; mi++) {
            #pragma unroll
            for (int ni = 0; ni < 8; ni++) {
                int r = row0 + wr + mi * 16 + qr;
                int c = col0 + wc + ni * 8 + qc;
                float b0 = bias[c], b1 = bias[c + 1];
                float2 o0 = make_float2(acc[mi][ni][0] + b0, acc[mi][ni][1] + b1);
                float2 o1 = make_float2(acc[mi][ni][2] + b0, acc[mi][ni][3] + b1);
                *(float2*)&C[(size_t)r * N + c] = o0;
                *(float2*)&C[(size_t)(r + 8) * N + c] = o1;
            }
        }
    } else {
        // fused QKV epilogue: bias + RoPE -> fp16
        int cb = col0 + wc;                 // 64-aligned head base
        int sec = cb >> 10;                 // 0=q, 1=k, 2=v
        int h = (cb & 1023) >> 6;
        #pragma unroll
        for (int mi = 0; mi < 2; mi++) {
            int r0 = row0 + wr + mi * 16 + qr;
            #pragma unroll
            for (int half = 0; half < 2; half++) {
                int r = r0 + half * 8;
                int e = half * 2;
                int t = r & (TT - 1);
                int b_ = r >> 11;
                size_t rowoff = ((size_t)((b_ * NHH + h) * TT + t)) * HDD;
                #pragma unroll
                for (int nj = 0; nj < 4; nj++) {
                    int d0 = nj * 8 + qc;            // even, < 32
                    int c0 = cb + d0;
                    float u00 = acc[mi][nj][e]     + bias[c0];
                    float u01 = acc[mi][nj][e + 1] + bias[c0 + 1];
                    float u10 = acc[mi][nj + 4][e]     + bias[c0 + 32];
                    float u11 = acc[mi][nj + 4][e + 1] + bias[c0 + 33];
                    if (sec < 2) {
                        float cA = ct[t * 32 + d0], cB = ct[t * 32 + d0 + 1];
                        float sA = st[t * 32 + d0], sB = st[t * 32 + d0 + 1];
                        float lo0 = u00 * cA - u10 * sA;
                        float lo1 = u01 * cB - u11 * sB;
                        float hi0 = u10 * cA + u00 * sA;
                        float hi1 = u11 * cB + u01 * sB;
                        __half* dst = (sec == 0) ? Qo : Ko;
                        *(__half2*)&dst[rowoff + d0]      = __floats2half2_rn(lo0, lo1);
                        *(__half2*)&dst[rowoff + d0 + 32] = __floats2half2_rn(hi0, hi1);
                    } else {
                        *(__half2*)&Vo[rowoff + d0]      = __floats2half2_rn(u00, u01);
                        *(__half2*)&Vo[rowoff + d0 + 32] = __floats2half2_rn(u10, u11);
                    }
                }
            }
        }
    }
}

// ---------------- fp16 V transpose: [bh][t][d] -> [bh][d][t] ---------------
__global__ __launch_bounds__(256) void vt_kernel(
    const __half* __restrict__ Vh, __half* __restrict__ Vt)
{
    __shared__ __half sm[64][72];
    int t0 = blockIdx.x * 64;
    int bh = blockIdx.y;
    const __half* src = Vh + ((size_t)bh * TT + t0) * HDD;
    #pragma unroll
    for (int i = 0; i < 2; i++) {
        int lin = i * 256 + threadIdx.x;      // 512 x 8 halfs
        int r = lin >> 3, c = (lin & 7) * 8;
        uint4 v = *(const uint4*)(src + (size_t)r * HDD + c);
        __half hv[8];
        *(uint4*)hv = v;
        #pragma unroll
        for (int j = 0; j < 8; j++) sm[c + j][r] = hv[j];
    }
    __syncthreads();
    #pragma unroll
    for (int i = 0; i < 2; i++) {
        int lin = i * 256 + threadIdx.x;
        int d = lin >> 3, tc = (lin & 7) * 8;
        *(uint4*)&Vt[((size_t)bh * HDD + d) * TT + t0 + tc] = *(uint4*)&sm[d][tc];
    }
}

// ---------------- Tensor-core flash attention (fp16, BM=128 BN=64) ---------
// 256 threads (8 warps x 16 q-rows), 2-stage KV pipeline, diag work skipping.
#define AT_SMEM (16384 + 2*16384)   // Q + 2 stages of (K 8KB + V 8KB)

__device__ __forceinline__ void attn_load_kv(
    uint32_t dst, const __half* __restrict__ Kb, const __half* __restrict__ Vb,
    int ktbase, int tid)
{
    #pragma unroll
    for (int i = 0; i < 2; i++) {
        int lin = i * 256 + tid;
        int r = lin >> 3, c = lin & 7;
        uint32_t sw = r * 128 + ((c ^ (r & 7)) << 4);
        cp16(dst + sw, Kb + (size_t)(ktbase + r) * HDD + c * 8);
        cp16(dst + 8192 + sw, Vb + (size_t)r * TT + ktbase + c * 8);
    }
    asm volatile("cp.async.commit_group;" ::: "memory");
}

__global__ __launch_bounds__(256, 2) void attn_kernel(
    const __half* __restrict__ Qg, const __half* __restrict__ Kg,
    const __half* __restrict__ Vtg,
    __half* __restrict__ Yh, __half* __restrict__ Yl)
{
    extern __shared__ char smem[];
    uint32_t sb = smem_u32(smem);
    uint32_t sQ = sb;
    uint32_t sKV = sb + 16384;

    const int tid = threadIdx.x;
    const int wid = tid >> 5, lane = tid & 31;
    const int grp = lane >> 3, l8 = lane & 7;
    const int qt = (int)gridDim.x - 1 - (int)blockIdx.x;   // longest first
    const int bh = blockIdx.y;
    const int q0 = qt * 128;
    const int nkt = 2 * qt + 2;

    const __half* Qb = Qg + ((size_t)bh * TT + q0) * HDD;
    const __half* Kb = Kg + (size_t)bh * TT * HDD;
    const __half* Vb = Vtg + (size_t)bh * HDD * TT;

    // stage Q (group 0) then prefetch kv tile 0 (group 1)
    #pragma unroll
    for (int i = 0; i < 4; i++) {
        int lin = i * 256 + tid;
        int r = lin >> 3, c = lin & 7;
        cp16(sQ + r * 128 + ((c ^ (r & 7)) << 4), Qb + (size_t)r * HDD + c * 8);
    }
    asm volatile("cp.async.commit_group;" ::: "memory");
    attn_load_kv(sKV, Kb, Vb, 0, tid);

    asm volatile("cp.async.wait_group 1;" ::: "memory");   // Q ready
    __syncthreads();

    // preload Q fragments
    uint32_t qf[4][4];
    #pragma unroll
    for (int kc = 0; kc < 4; kc++) {
        int row = wid * 16 + (grp & 1) * 8 + l8;
        int ch = kc * 2 + (grp >> 1);
        ldsm4(qf[kc], sQ + row * 128 + ((ch ^ (row & 7)) << 4));
    }

    float m0 = -1e30f, m1 = -1e30f, l0 = 0.f, l1 = 0.f;
    float oacc[8][4];
    #pragma unroll
    for (int nj = 0; nj < 8; nj++)
        #pragma unroll
        for (int e = 0; e < 4; e++) oacc[nj][e] = 0.f;

    const int rquad = lane >> 2;       // 0..7
    const int cpair = (lane & 3) * 2;  // 0,2,4,6

    for (int kt = 0; kt < nkt; kt++) {
        int s = kt & 1;
        if (kt + 1 < nkt) {
            attn_load_kv(sKV + (s ^ 1) * 16384, Kb, Vb, (kt + 1) * 64, tid);
            asm volatile("cp.async.wait_group 1;" ::: "memory");
        } else {
            asm volatile("cp.async.wait_group 0;" ::: "memory");
        }
        __syncthreads();

        uint32_t sK = sKV + s * 16384;
        uint32_t sV = sK + 8192;

        // diagonal work skipping: nb = # of active 16-col blocks (of 4)
        int nb = 4;
        if (kt == nkt - 2)      nb = (wid + 1 < 4) ? wid + 1 : 4;
        else if (kt == nkt - 1) nb = (wid >= 4) ? ((wid - 3 < 4) ? wid - 3 : 4) : 0;

        // S = Q K^T
        float sacc[8][4];
        #pragma unroll
        for (int nj = 0; nj < 8; nj++)
            #pragma unroll
            for (int e = 0; e < 4; e++) sacc[nj][e] = 0.f;

        #pragma unroll
        for (int ks = 0; ks < 4; ks++) {
            #pragma unroll
            for (int nj = 0; nj < 4; nj++) {
                if (nj < nb) {
                    int row = nj * 16 + (grp >> 1) * 8 + l8;
                    int ch = ks * 2 + (grp & 1);
                    uint32_t rr[4];
                    ldsm4(rr, sK + row * 128 + ((ch ^ (row & 7)) << 4));
                    uint32_t b0[2] = {rr[0], rr[1]}, b1[2] = {rr[2], rr[3]};
                    mma16816h(sacc[2 * nj], qf[ks], b0);
                    mma16816h(sacc[2 * nj + 1], qf[ks], b1);
                }
            }
        }

        // scale + causal mask (only last two tiles touch the diagonal)
        const float sc = 0.125f;
        if (kt >= nkt - 2) {
            int row0g = q0 + wid * 16 + rquad;
            #pragma unroll
            for (int nj = 0; nj < 8; nj++) {
                int colg = kt * 64 + nj * 8 + cpair;
                #pragma unroll
                for (int e = 0; e < 4; e++) {
                    int cg = colg + (e & 1);
                    int rg = row0g + ((e >= 2) ? 8 : 0);
                    sacc[nj][e] = (cg <= rg) ? sacc[nj][e] * sc : -1e30f;
                }
            }
        } else {
            #pragma unroll
            for (int nj = 0; nj < 8; nj++)
                #pragma unroll
                for (int e = 0; e < 4; e++) sacc[nj][e] *= sc;
        }

        // online softmax (two rows per thread; 4-lane quad reductions)
        float rm0 = -1e30f, rm1 = -1e30f;
        #pragma unroll
        for (int nj = 0; nj < 8; nj++) {
            rm0 = fmaxf(rm0, fmaxf(sacc[nj][0], sacc[nj][1]));
            rm1 = fmaxf(rm1, fmaxf(sacc[nj][2], sacc[nj][3]));
        }
        rm0 = fmaxf(rm0, __shfl_xor_sync(0xffffffffu, rm0, 1));
        rm0 = fmaxf(rm0, __shfl_xor_sync(0xffffffffu, rm0, 2));
        rm1 = fmaxf(rm1, __shfl_xor_sync(0xffffffffu, rm1, 1));
        rm1 = fmaxf(rm1, __shfl_xor_sync(0xffffffffu, rm1, 2));

        float n0 = fmaxf(m0, rm0), n1 = fmaxf(m1, rm1);
        float a0 = __expf(m0 - n0), a1 = __expf(m1 - n1);
        float rs0 = 0.f, rs1 = 0.f;
        #pragma unroll
        for (int nj = 0; nj < 8; nj++) {
            sacc[nj][0] = __expf(sacc[nj][0] - n0);
            sacc[nj][1] = __expf(sacc[nj][1] - n0);
            sacc[nj][2] = __expf(sacc[nj][2] - n1);
            sacc[nj][3] = __expf(sacc[nj][3] - n1);
            rs0 += sacc[nj][0] + sacc[nj][1];
            rs1 += sacc[nj][2] + sacc[nj][3];
        }
        rs0 += __shfl_xor_sync(0xffffffffu, rs0, 1);
        rs0 += __shfl_xor_sync(0xffffffffu, rs0, 2);
        rs1 += __shfl_xor_sync(0xffffffffu, rs1, 1);
        rs1 += __shfl_xor_sync(0xffffffffu, rs1, 2);

        l0 = l0 * a0 + rs0;
        l1 = l1 * a1 + rs1;
        m0 = n0; m1 = n1;
        #pragma unroll
        for (int nj = 0; nj < 8; nj++) {
            oacc[nj][0] *= a0; oacc[nj][1] *= a0;
            oacc[nj][2] *= a1; oacc[nj][3] *= a1;
        }

        // pack P into A-operand fragments (registers only)
        uint32_t pf[4][4];
        #pragma unroll
        for (int kc = 0; kc < 4; kc++) {
            pf[kc][0] = packh2(sacc[2 * kc][0],     sacc[2 * kc][1]);
            pf[kc][1] = packh2(sacc[2 * kc][2],     sacc[2 * kc][3]);
            pf[kc][2] = packh2(sacc[2 * kc + 1][0], sacc[2 * kc + 1][1]);
            pf[kc][3] = packh2(sacc[2 * kc + 1][2], sacc[2 * kc + 1][3]);
        }

        // O += P @ V   (V [d][t]; skip t-chunks with all-zero P on diag tiles)
        #pragma unroll
        for (int kc = 0; kc < 4; kc++) {
            if (kc < nb) {
                #pragma unroll
                for (int nj = 0; nj < 4; nj++) {
                    int row = nj * 16 + (grp >> 1) * 8 + l8;
                    int ch = kc * 2 + (grp & 1);
                    uint32_t rr[4];
                    ldsm4(rr, sV + row * 128 + ((ch ^ (row & 7)) << 4));
                    uint32_t b0[2] = {rr[0], rr[1]}, b1[2] = {rr[2], rr[3]};
                    mma16816h(oacc[2 * nj], pf[kc], b0);
                    mma16816h(oacc[2 * nj + 1], pf[kc], b1);
                }
            }
        }
        __syncthreads();
    }

    // epilogue: normalize + fp16 hi/lo split store to [b,t,c]
    float i0 = 1.f / l0, i1 = 1.f / l1;
    int b_ = bh >> 4, h = bh & 15;
    int r0g = q0 + wid * 16 + rquad;
    #pragma unroll
    for (int nj = 0; nj < 8; nj++) {
        int c = h * 64 + nj * 8 + cpair;
        float v0 = oacc[nj][0] * i0, v1 = oacc[nj][1] * i0;
        float v2 = oacc[nj][2] * i1, v3 = oacc[nj][3] * i1;
        size_t o0 = (size_t)(b_ * TT + r0g) * CC + c;
        size_t o1 = (size_t)(b_ * TT + r0g + 8) * CC + c;
        __half2 h0 = __floats2half2_rn(v0, v1);
        __half2 h1 = __floats2half2_rn(v2, v3);
        *(__half2*)&Yh[o0] = h0;
        *(__half2*)&Yh[o1] = h1;
        *(__half2*)&Yl[o0] = __floats2half2_rn(v0 - __half2float(__low2half(h0)),
                                               v1 - __half2float(__high2half(h0)));
        *(__half2*)&Yl[o1] = __floats2half2_rn(v2 - __half2float(__low2half(h1)),
                                               v3 - __half2float(__high2half(h1)));
    }
}

// ---------------- launch ---------------------------------------------------
extern "C" void kernel_launch(void* const* d_in, const int* in_sizes, int n_in,
                              void* d_out, int out_size)
{
    const float* x     = (const float*)d_in[0];
    const float* Wqkv  = (const float*)d_in[1];
    const float* bqkv  = (const float*)d_in[2];
    const float* Wproj = (const float*)d_in[3];
    const float* bproj = (const float*)d_in[4];
    float* out = (float*)d_out;

    float *ct, *st;
    __half *xh, *xl, *wq, *wp, *yh, *yl, *qh, *kh, *vh, *vt;
    cudaGetSymbolAddress((void**)&ct, g_cost);
    cudaGetSymbolAddress((void**)&st, g_sint);
    cudaGetSymbolAddress((void**)&xh, g_xh);
    cudaGetSymbolAddress((void**)&xl, g_xl);
    cudaGetSymbolAddress((void**)&wq, g_wq);
    cudaGetSymbolAddress((void**)&wp, g_wp);
    cudaGetSymbolAddress((void**)&yh, g_yh);
    cudaGetSymbolAddress((void**)&yl, g_yl);
    cudaGetSymbolAddress((void**)&qh, g_qh);
    cudaGetSymbolAddress((void**)&kh, g_kh);
    cudaGetSymbolAddress((void**)&vh, g_vh);
    cudaGetSymbolAddress((void**)&vt, g_vt);

    cudaFuncSetAttribute(tc_gemm_kernel<0>,
                         cudaFuncAttributeMaxDynamicSharedMemorySize, GSMEM);
    cudaFuncSetAttribute(tc_gemm_kernel<1>,
                         cudaFuncAttributeMaxDynamicSharedMemorySize, GSMEM);
    cudaFuncSetAttribute(attn_kernel,
                         cudaFuncAttributeMaxDynamicSharedMemorySize, AT_SMEM);

    // ordered so the QKV GEMM lands on the ncu-captured launch slot
    split_kernel<<<(ROWS * CC) / 256, 256>>>(x, xh, xl, ROWS * CC);                    // 0
    transpose_half_kernel<<<dim3(CC / 32, N_QKV / 32), 256>>>(Wqkv, wq, CC, N_QKV);    // 1
    rope_table_kernel<<<(TT * 32) / 256, 256>>>(ct, st);                               // 2

    // 3) QKV GEMM + bias + fused RoPE -> fp16 Q,K,V
    tc_gemm_kernel<1><<<dim3(N_QKV / 128, ROWS / 128), 256, GSMEM>>>(
        xh, xl, wq, bqkv, nullptr, qh, kh, vh, ct, st, N_QKV, CC);

    transpose_half_kernel<<<dim3(CC / 32, CC / 32), 256>>>(Wproj, wp, CC, CC);         // 4

    // 5) V transpose fp16 [bh][t][d] -> [bh][d][t]
    vt_kernel<<<dim3(TT / 64, BB * NHH), 256>>>(vh, vt);

    // 6) tensor-core causal flash attention -> fp16 hi/lo Y
    attn_kernel<<<dim3(TT / 128, BB * NHH), 256, AT_SMEM>>>(qh, kh, vt, yh, yl);

    // 7) output projection + bias
    tc_gemm_kernel<0><<<dim3(CC / 128, ROWS / 128), 256, GSMEM>>>(
        yh, yl, wp, bproj, out, nullptr, nullptr, nullptr, ct, st, CC, CC);
}

// round 9
// speedup vs baseline: 1.4340x; 1.0042x over previous
#include <cuda_runtime.h>
#include <cuda_bf16.h>
#include <cuda_fp16.h>
#include <math.h>
#include <stdint.h>

// Problem constants
#define BB 4
#define TT 2048
#define CC 1024
#define NHH 16
#define HDD 64
#define ROWS (BB*TT)          // 8192
#define N_QKV (3*CC)          // 3072

// ---------------- scratch (device globals; no allocation) ----------------
__device__ __half g_xh[(size_t)ROWS * CC];            // x hi (fp16)
__device__ __half g_xl[(size_t)ROWS * CC];            // x lo (fp16)
__device__ __half g_wq[(size_t)N_QKV * CC];           // Wqkv^T [N,K] fp16
__device__ __half g_wp[(size_t)CC * CC];              // Wproj^T [N,K] fp16
__device__ __half g_yh[(size_t)ROWS * CC];            // attn out hi (fp16)
__device__ __half g_yl[(size_t)ROWS * CC];            // attn out lo (fp16)
__device__ float g_cost[(size_t)TT * 32];
__device__ float g_sint[(size_t)TT * 32];

__device__ __half g_qh[(size_t)BB * NHH * TT * HDD];  // [bh][t][d]
__device__ __half g_kh[(size_t)BB * NHH * TT * HDD];  // [bh][t][d]
__device__ __half g_vh[(size_t)BB * NHH * TT * HDD];  // [bh][t][d]
__device__ __half g_vt[(size_t)BB * NHH * HDD * TT];  // [bh][d][t]

// ---------------- PTX helpers (arch-baseline only: no tcgen05) ------------
__device__ __forceinline__ uint32_t smem_u32(const void* p) {
    uint32_t a;
    asm("{ .reg .u64 t; cvta.to.shared.u64 t, %1; cvt.u32.u64 %0, t; }" : "=r"(a) : "l"(p));
    return a;
}
__device__ __forceinline__ void cp16(uint32_t saddr, const void* g) {
    asm volatile("cp.async.cg.shared.global [%0], [%1], 16;" :: "r"(saddr), "l"(g));
}
__device__ __forceinline__ void ldsm4(uint32_t* r, uint32_t addr) {
    asm volatile("ldmatrix.sync.aligned.m8n8.x4.shared.b16 {%0,%1,%2,%3}, [%4];"
                 : "=r"(r[0]), "=r"(r[1]), "=r"(r[2]), "=r"(r[3]) : "r"(addr));
}
__device__ __forceinline__ void mma16816h(float* c, const uint32_t* a, const uint32_t* b) {
    asm volatile(
        "mma.sync.aligned.m16n8k16.row.col.f32.f16.f16.f32 "
        "{%0,%1,%2,%3}, {%4,%5,%6,%7}, {%8,%9}, {%0,%1,%2,%3};"
        : "+f"(c[0]), "+f"(c[1]), "+f"(c[2]), "+f"(c[3])
        : "r"(a[0]), "r"(a[1]), "r"(a[2]), "r"(a[3]), "r"(b[0]), "r"(b[1]));
}
__device__ __forceinline__ uint32_t packh2(float a, float b) {
    __half2 h = __floats2half2_rn(a, b);
    return *(uint32_t*)&h;
}

// ---------------- conversions ----------------------------------------------
// x f32 -> fp16 hi + fp16 lo (exact 22-bit split)
__global__ __launch_bounds__(256) void split_kernel(
    const float* __restrict__ in, __half* __restrict__ hi,
    __half* __restrict__ lo, int n)
{
    int i = blockIdx.x * 256 + threadIdx.x;
    if (i >= n) return;
    float v = in[i];
    __half h = __float2half(v);
    hi[i] = h;
    lo[i] = __float2half(v - __half2float(h));
}

// W[K,N] f32 -> [N,K] fp16 (transpose + quantize once)
__global__ __launch_bounds__(256) void transpose_half_kernel(
    const float* __restrict__ W, __half* __restrict__ Wt, int K, int N)
{
    __shared__ float tile[32][33];
    int k0 = blockIdx.x * 32, n0 = blockIdx.y * 32;
    int tx = threadIdx.x & 31, ty = threadIdx.x >> 5;   // 32x8
    #pragma unroll
    for (int r = 0; r < 4; r++)
        tile[ty + 8 * r][tx] = W[(size_t)(k0 + ty + 8 * r) * N + n0 + tx];
    __syncthreads();
    #pragma unroll
    for (int r = 0; r < 4; r++)
        Wt[(size_t)(n0 + ty + 8 * r) * K + k0 + tx] = __float2half(tile[tx][ty + 8 * r]);
}

// ---------------- RoPE table (mimic jax f32 computation) -------------------
__global__ __launch_bounds__(256) void rope_table_kernel(float* ct, float* st) {
    int idx = blockIdx.x * 256 + threadIdx.x;   // TT*32
    int t = idx >> 5, i = idx & 31;
    float invf = (float)exp(-(double)i / 32.0 * 9.210340371976184);
    float fr = (float)t * invf;
    double a = (double)fr;
    ct[idx] = (float)cos(a);
    st[idx] = (float)sin(a);
}

// ---------------- HMMA exact-A/quantized-B GEMM (2-pass fp16) --------------
// C = (Ah + Al) @ B^T (+bias);  Ah,Al:[M,K] fp16 split of fp32 A; B:[N,K] fp16
// B fragments loaded ONCE per ks and reused for both hi/lo passes.
// MODE 0: f32 out + bias (proj).  MODE 1: fused QKV bias+RoPE -> fp16 Q,K,V.
#define TILE_B 16384
#define STAGE_B (3*TILE_B)     // Ah, Al, B
#define GSMEM (3*STAGE_B)      // 147456

__device__ __forceinline__ void load_stage(
    uint32_t base, int kt, int tid, int row0, int col0, int K,
    const __half* __restrict__ Ah, const __half* __restrict__ Al,
    const __half* __restrict__ Bq)
{
    int k0 = kt * 64;
    const __half* srcs[3] = {Ah, Al, Bq};
    #pragma unroll
    for (int t = 0; t < 3; t++) {
        int rbase = (t < 2) ? row0 : col0;
        const __half* s = srcs[t];
        #pragma unroll
        for (int i = 0; i < 4; i++) {
            int lin = i * 256 + tid;
            int r = lin >> 3, c = lin & 7;
            uint32_t off = r * 128 + c * 16;
            uint32_t sw = off ^ ((off >> 3) & 0x70);
            cp16(base + t * TILE_B + sw, s + (size_t)(rbase + r) * K + k0 + c * 8);
        }
    }
    asm volatile("cp.async.commit_group;" ::: "memory");
}

template<int MODE>
__global__ __launch_bounds__(256, 1) void tc_gemm_kernel(
    const __half* __restrict__ Ah, const __half* __restrict__ Al,
    const __half* __restrict__ Bq,
    const float* __restrict__ bias, float* __restrict__ C,
    __half* __restrict__ Qo, __half* __restrict__ Ko, __half* __restrict__ Vo,
    const float* __restrict__ ct, const float* __restrict__ st,
    int N, int K)
{
    extern __shared__ char smem[];
    uint32_t sb = smem_u32(smem);
    const int tid = threadIdx.x;
    const int wid = tid >> 5, lane = tid & 31;
    const int wr = (wid & 3) * 32;
    const int wc = (wid >> 2) * 64;
    const int col0 = blockIdx.x * 128;
    const int row0 = blockIdx.y * 128;
    const int NK = K >> 6;

    float acc[2][8][4];
    #pragma unroll
    for (int mi = 0; mi < 2; mi++)
        #pragma unroll
        for (int ni = 0; ni < 8; ni++)
            #pragma unroll
            for (int j = 0; j < 4; j++) acc[mi][ni][j] = 0.f;

    load_stage(sb, 0, tid, row0, col0, K, Ah, Al, Bq);
    if (NK > 1)
        load_stage(sb + STAGE_B, 1, tid, row0, col0, K, Ah, Al, Bq);

    const int grp = lane >> 3, l8 = lane & 7;

    for (int kt = 0; kt < NK; kt++) {
        if (kt + 1 < NK) { asm volatile("cp.async.wait_group 1;" ::: "memory"); }
        else             { asm volatile("cp.async.wait_group 0;" ::: "memory"); }
        __syncthreads();

        uint32_t sbase = sb + (kt % 3) * STAGE_B;
        uint32_t ahb = sbase, alb = sbase + TILE_B, bbase = sbase + 2 * TILE_B;
        #pragma unroll
        for (int ks = 0; ks < 4; ks++) {
            // B fragments once per ks (4 ldsm4)
            uint32_t b[8][2];
            #pragma unroll
            for (int nj = 0; nj < 4; nj++) {
                int row = wc + nj * 16 + (grp >> 1) * 8 + l8;
                int chunk = ks * 2 + (grp & 1);
                uint32_t rr[4];
                ldsm4(rr, bbase + row * 128 + ((chunk ^ (row & 7)) << 4));
                b[2 * nj][0] = rr[0]; b[2 * nj][1] = rr[1];
                b[2 * nj + 1][0] = rr[2]; b[2 * nj + 1][1] = rr[3];
            }
            // A hi + lo fragments (2+2 ldsm4)
            uint32_t ah[2][4], al[2][4];
            #pragma unroll
            for (int mi = 0; mi < 2; mi++) {
                int row = wr + mi * 16 + (grp & 1) * 8 + l8;
                int chunk = ks * 2 + (grp >> 1);
                uint32_t sw = ((chunk ^ (row & 7)) << 4);
                ldsm4(ah[mi], ahb + row * 128 + sw);
                ldsm4(al[mi], alb + row * 128 + sw);
            }
            // 32 MMAs, B fragments reused across both passes
            #pragma unroll
            for (int mi = 0; mi < 2; mi++)
                #pragma unroll
                for (int ni = 0; ni < 8; ni++)
                    mma16816h(acc[mi][ni], ah[mi], b[ni]);
            #pragma unroll
            for (int mi = 0; mi < 2; mi++)
                #pragma unroll
                for (int ni = 0; ni < 8; ni++)
                    mma16816h(acc[mi][ni], al[mi], b[ni]);
        }
        if (kt + 2 < NK)
            load_stage(sb + ((kt + 2) % 3) * STAGE_B, kt + 2, tid, row0, col0, K,
                       Ah, Al, Bq);
    }

    const int qr = lane >> 2, qc = (lane & 3) * 2;

    if (MODE == 0) {
        #pragma unroll
        for (int mi = 0; mi < 2; mi++) {
            #pragma unroll
            for (int ni = 0; ni < 8; ni++) {
                int r = row0 + wr + mi * 16 + qr;
                int c = col0 + wc + ni * 8 + qc;
                float b0 = bias[c], b1 = bias[c + 1];
                float2 o0 = make_float2(acc[mi][ni][0] + b0, acc[mi][ni][1] + b1);
                float2 o1 = make_float2(acc[mi][ni][2] + b0, acc[mi][ni][3] + b1);
                *(float2*)&C[(size_t)r * N + c] = o0;
                *(float2*)&C[(size_t)(r + 8) * N + c] = o1;
            }
        }
    } else {
        // fused QKV epilogue: bias + RoPE -> fp16
        int cb = col0 + wc;                 // 64-aligned head base
        int sec = cb >> 10;                 // 0=q, 1=k, 2=v
        int h = (cb & 1023) >> 6;
        #pragma unroll
        for (int mi = 0; mi < 2; mi++) {
            int r0 = row0 + wr + mi * 16 + qr;
            #pragma unroll
            for (int half = 0; half < 2; half++) {
                int r = r0 + half * 8;
                int e = half * 2;
                int t = r & (TT - 1);
                int b_ = r >> 11;
                size_t rowoff = ((size_t)((b_ * NHH + h) * TT + t)) * HDD;
                #pragma unroll
                for (int nj = 0; nj < 4; nj++) {
                    int d0 = nj * 8 + qc;            // even, < 32
                    int c0 = cb + d0;
                    float u00 = acc[mi][nj][e]     + bias[c0];
                    float u01 = acc[mi][nj][e + 1] + bias[c0 + 1];
                    float u10 = acc[mi][nj + 4][e]     + bias[c0 + 32];
                    float u11 = acc[mi][nj + 4][e + 1] + bias[c0 + 33];
                    if (sec < 2) {
                        float cA = ct[t * 32 + d0], cB = ct[t * 32 + d0 + 1];
                        float sA = st[t * 32 + d0], sB = st[t * 32 + d0 + 1];
                        float lo0 = u00 * cA - u10 * sA;
                        float lo1 = u01 * cB - u11 * sB;
                        float hi0 = u10 * cA + u00 * sA;
                        float hi1 = u11 * cB + u01 * sB;
                        __half* dst = (sec == 0) ? Qo : Ko;
                        *(__half2*)&dst[rowoff + d0]      = __floats2half2_rn(lo0, lo1);
                        *(__half2*)&dst[rowoff + d0 + 32] = __floats2half2_rn(hi0, hi1);
                    } else {
                        *(__half2*)&Vo[rowoff + d0]      = __floats2half2_rn(u00, u01);
                        *(__half2*)&Vo[rowoff + d0 + 32] = __floats2half2_rn(u10, u11);
                    }
                }
            }
        }
    }
}

// ---------------- fp16 V transpose: [bh][t][d] -> [bh][d][t] ---------------
__global__ __launch_bounds__(256) void vt_kernel(
    const __half* __restrict__ Vh, __half* __restrict__ Vt)
{
    __shared__ __half sm[64][72];
    int t0 = blockIdx.x * 64;
    int bh = blockIdx.y;
    const __half* src = Vh + ((size_t)bh * TT + t0) * HDD;
    #pragma unroll
    for (int i = 0; i < 2; i++) {
        int lin = i * 256 + threadIdx.x;      // 512 x 8 halfs
        int r = lin >> 3, c = (lin & 7) * 8;
        uint4 v = *(const uint4*)(src + (size_t)r * HDD + c);
        __half hv[8];
        *(uint4*)hv = v;
        #pragma unroll
        for (int j = 0; j < 8; j++) sm[c + j][r] = hv[j];
    }
    __syncthreads();
    #pragma unroll
    for (int i = 0; i < 2; i++) {
        int lin = i * 256 + threadIdx.x;
        int d = lin >> 3, tc = (lin & 7) * 8;
        *(uint4*)&Vt[((size_t)bh * HDD + d) * TT + t0 + tc] = *(uint4*)&sm[d][tc];
    }
}

// ---------------- Tensor-core flash attention (fp16, BM=128 BN=64) ---------
// 256 threads (8 warps x 16 q-rows), 2-stage KV pipeline, diag work skipping.
#define AT_SMEM (16384 + 2*16384)   // Q + 2 stages of (K 8KB + V 8KB)

__device__ __forceinline__ void attn_load_kv(
    uint32_t dst, const __half* __restrict__ Kb, const __half* __restrict__ Vb,
    int ktbase, int tid)
{
    #pragma unroll
    for (int i = 0; i < 2; i++) {
        int lin = i * 256 + tid;
        int r = lin >> 3, c = lin & 7;
        uint32_t sw = r * 128 + ((c ^ (r & 7)) << 4);
        cp16(dst + sw, Kb + (size_t)(ktbase + r) * HDD + c * 8);
        cp16(dst + 8192 + sw, Vb + (size_t)r * TT + ktbase + c * 8);
    }
    asm volatile("cp.async.commit_group;" ::: "memory");
}

__global__ __launch_bounds__(256, 2) void attn_kernel(
    const __half* __restrict__ Qg, const __half* __restrict__ Kg,
    const __half* __restrict__ Vtg,
    __half* __restrict__ Yh, __half* __restrict__ Yl)
{
    extern __shared__ char smem[];
    uint32_t sb = smem_u32(smem);
    uint32_t sQ = sb;
    uint32_t sKV = sb + 16384;

    const int tid = threadIdx.x;
    const int wid = tid >> 5, lane = tid & 31;
    const int grp = lane >> 3, l8 = lane & 7;
    const int qt = (int)gridDim.x - 1 - (int)blockIdx.x;   // longest first
    const int bh = blockIdx.y;
    const int q0 = qt * 128;
    const int nkt = 2 * qt + 2;

    const __half* Qb = Qg + ((size_t)bh * TT + q0) * HDD;
    const __half* Kb = Kg + (size_t)bh * TT * HDD;
    const __half* Vb = Vtg + (size_t)bh * HDD * TT;

    // stage Q (group 0) then prefetch kv tile 0 (group 1)
    #pragma unroll
    for (int i = 0; i < 4; i++) {
        int lin = i * 256 + tid;
        int r = lin >> 3, c = lin & 7;
        cp16(sQ + r * 128 + ((c ^ (r & 7)) << 4), Qb + (size_t)r * HDD + c * 8);
    }
    asm volatile("cp.async.commit_group;" ::: "memory");
    attn_load_kv(sKV, Kb, Vb, 0, tid);

    asm volatile("cp.async.wait_group 1;" ::: "memory");   // Q ready
    __syncthreads();

    // preload Q fragments
    uint32_t qf[4][4];
    #pragma unroll
    for (int kc = 0; kc < 4; kc++) {
        int row = wid * 16 + (grp & 1) * 8 + l8;
        int ch = kc * 2 + (grp >> 1);
        ldsm4(qf[kc], sQ + row * 128 + ((ch ^ (row & 7)) << 4));
    }

    float m0 = -1e30f, m1 = -1e30f, l0 = 0.f, l1 = 0.f;
    float oacc[8][4];
    #pragma unroll
    for (int nj = 0; nj < 8; nj++)
        #pragma unroll
        for (int e = 0; e < 4; e++) oacc[nj][e] = 0.f;

    const int rquad = lane >> 2;       // 0..7
    const int cpair = (lane & 3) * 2;  // 0,2,4,6

    for (int kt = 0; kt < nkt; kt++) {
        int s = kt & 1;
        if (kt + 1 < nkt) {
            attn_load_kv(sKV + (s ^ 1) * 16384, Kb, Vb, (kt + 1) * 64, tid);
            asm volatile("cp.async.wait_group 1;" ::: "memory");
        } else {
            asm volatile("cp.async.wait_group 0;" ::: "memory");
        }
        __syncthreads();

        uint32_t sK = sKV + s * 16384;
        uint32_t sV = sK + 8192;

        // diagonal work skipping: nb = # of active 16-col blocks (of 4)
        int nb = 4;
        if (kt == nkt - 2)      nb = (wid + 1 < 4) ? wid + 1 : 4;
        else if (kt == nkt - 1) nb = (wid >= 4) ? ((wid - 3 < 4) ? wid - 3 : 4) : 0;

        // S = Q K^T
        float sacc[8][4];
        #pragma unroll
        for (int nj = 0; nj < 8; nj++)
            #pragma unroll
            for (int e = 0; e < 4; e++) sacc[nj][e] = 0.f;

        #pragma unroll
        for (int ks = 0; ks < 4; ks++) {
            #pragma unroll
            for (int nj = 0; nj < 4; nj++) {
                if (nj < nb) {
                    int row = nj * 16 + (grp >> 1) * 8 + l8;
                    int ch = ks * 2 + (grp & 1);
                    uint32_t rr[4];
                    ldsm4(rr, sK + row * 128 + ((ch ^ (row & 7)) << 4));
                    uint32_t b0[2] = {rr[0], rr[1]}, b1[2] = {rr[2], rr[3]};
                    mma16816h(sacc[2 * nj], qf[ks], b0);
                    mma16816h(sacc[2 * nj + 1], qf[ks], b1);
                }
            }
        }

        // scale + causal mask (only last two tiles touch the diagonal)
        const float sc = 0.125f;
        if (kt >= nkt - 2) {
            int row0g = q0 + wid * 16 + rquad;
            #pragma unroll
            for (int nj = 0; nj < 8; nj++) {
                int colg = kt * 64 + nj * 8 + cpair;
                #pragma unroll
                for (int e = 0; e < 4; e++) {
                    int cg = colg + (e & 1);
                    int rg = row0g + ((e >= 2) ? 8 : 0);
                    sacc[nj][e] = (cg <= rg) ? sacc[nj][e] * sc : -1e30f;
                }
            }
        } else {
            #pragma unroll
            for (int nj = 0; nj < 8; nj++)
                #pragma unroll
                for (int e = 0; e < 4; e++) sacc[nj][e] *= sc;
        }

        // online softmax (two rows per thread; 4-lane quad reductions)
        float rm0 = -1e30f, rm1 = -1e30f;
        #pragma unroll
        for (int nj = 0; nj < 8; nj++) {
            rm0 = fmaxf(rm0, fmaxf(sacc[nj][0], sacc[nj][1]));
            rm1 = fmaxf(rm1, fmaxf(sacc[nj][2], sacc[nj][3]));
        }
        rm0 = fmaxf(rm0, __shfl_xor_sync(0xffffffffu, rm0, 1));
        rm0 = fmaxf(rm0, __shfl_xor_sync(0xffffffffu, rm0, 2));
        rm1 = fmaxf(rm1, __shfl_xor_sync(0xffffffffu, rm1, 1));
        rm1 = fmaxf(rm1, __shfl_xor_sync(0xffffffffu, rm1, 2));

        float n0 = fmaxf(m0, rm0), n1 = fmaxf(m1, rm1);
        float a0 = __expf(m0 - n0), a1 = __expf(m1 - n1);
        float rs0 = 0.f, rs1 = 0.f;
        #pragma unroll
        for (int nj = 0; nj < 8; nj++) {
            sacc[nj][0] = __expf(sacc[nj][0] - n0);
            sacc[nj][1] = __expf(sacc[nj][1] - n0);
            sacc[nj][2] = __expf(sacc[nj][2] - n1);
            sacc[nj][3] = __expf(sacc[nj][3] - n1);
            rs0 += sacc[nj][0] + sacc[nj][1];
            rs1 += sacc[nj][2] + sacc[nj][3];
        }
        rs0 += __shfl_xor_sync(0xffffffffu, rs0, 1);
        rs0 += __shfl_xor_sync(0xffffffffu, rs0, 2);
        rs1 += __shfl_xor_sync(0xffffffffu, rs1, 1);
        rs1 += __shfl_xor_sync(0xffffffffu, rs1, 2);

        l0 = l0 * a0 + rs0;
        l1 = l1 * a1 + rs1;
        m0 = n0; m1 = n1;
        #pragma unroll
        for (int nj = 0; nj < 8; nj++) {
            oacc[nj][0] *= a0; oacc[nj][1] *= a0;
            oacc[nj][2] *= a1; oacc[nj][3] *= a1;
        }

        // pack P into A-operand fragments (registers only)
        uint32_t pf[4][4];
        #pragma unroll
        for (int kc = 0; kc < 4; kc++) {
            pf[kc][0] = packh2(sacc[2 * kc][0],     sacc[2 * kc][1]);
            pf[kc][1] = packh2(sacc[2 * kc][2],     sacc[2 * kc][3]);
            pf[kc][2] = packh2(sacc[2 * kc + 1][0], sacc[2 * kc + 1][1]);
            pf[kc][3] = packh2(sacc[2 * kc + 1][2], sacc[2 * kc + 1][3]);
        }

        // O += P @ V   (V [d][t]; skip t-chunks with all-zero P on diag tiles)
        #pragma unroll
        for (int kc = 0; kc < 4; kc++) {
            if (kc < nb) {
                #pragma unroll
                for (int nj = 0; nj < 4; nj++) {
                    int row = nj * 16 + (grp >> 1) * 8 + l8;
                    int ch = kc * 2 + (grp & 1);
                    uint32_t rr[4];
                    ldsm4(rr, sV + row * 128 + ((ch ^ (row & 7)) << 4));
                    uint32_t b0[2] = {rr[0], rr[1]}, b1[2] = {rr[2], rr[3]};
                    mma16816h(oacc[2 * nj], pf[kc], b0);
                    mma16816h(oacc[2 * nj + 1], pf[kc], b1);
                }
            }
        }
        __syncthreads();
    }

    // epilogue: normalize + fp16 hi/lo split store to [b,t,c]
    float i0 = 1.f / l0, i1 = 1.f / l1;
    int b_ = bh >> 4, h = bh & 15;
    int r0g = q0 + wid * 16 + rquad;
    #pragma unroll
    for (int nj = 0; nj < 8; nj++) {
        int c = h * 64 + nj * 8 + cpair;
        float v0 = oacc[nj][0] * i0, v1 = oacc[nj][1] * i0;
        float v2 = oacc[nj][2] * i1, v3 = oacc[nj][3] * i1;
        size_t o0 = (size_t)(b_ * TT + r0g) * CC + c;
        size_t o1 = (size_t)(b_ * TT + r0g + 8) * CC + c;
        __half2 h0 = __floats2half2_rn(v0, v1);
        __half2 h1 = __floats2half2_rn(v2, v3);
        *(__half2*)&Yh[o0] = h0;
        *(__half2*)&Yh[o1] = h1;
        *(__half2*)&Yl[o0] = __floats2half2_rn(v0 - __half2float(__low2half(h0)),
                                               v1 - __half2float(__high2half(h0)));
        *(__half2*)&Yl[o1] = __floats2half2_rn(v2 - __half2float(__low2half(h1)),
                                               v3 - __half2float(__high2half(h1)));
    }
}

// ---------------- launch ---------------------------------------------------
extern "C" void kernel_launch(void* const* d_in, const int* in_sizes, int n_in,
                              void* d_out, int out_size)
{
    const float* x     = (const float*)d_in[0];
    const float* Wqkv  = (const float*)d_in[1];
    const float* bqkv  = (const float*)d_in[2];
    const float* Wproj = (const float*)d_in[3];
    const float* bproj = (const float*)d_in[4];
    float* out = (float*)d_out;

    float *ct, *st;
    __half *xh, *xl, *wq, *wp, *yh, *yl, *qh, *kh, *vh, *vt;
    cudaGetSymbolAddress((void**)&ct, g_cost);
    cudaGetSymbolAddress((void**)&st, g_sint);
    cudaGetSymbolAddress((void**)&xh, g_xh);
    cudaGetSymbolAddress((void**)&xl, g_xl);
    cudaGetSymbolAddress((void**)&wq, g_wq);
    cudaGetSymbolAddress((void**)&wp, g_wp);
    cudaGetSymbolAddress((void**)&yh, g_yh);
    cudaGetSymbolAddress((void**)&yl, g_yl);
    cudaGetSymbolAddress((void**)&qh, g_qh);
    cudaGetSymbolAddress((void**)&kh, g_kh);
    cudaGetSymbolAddress((void**)&vh, g_vh);
    cudaGetSymbolAddress((void**)&vt, g_vt);

    cudaFuncSetAttribute(tc_gemm_kernel<0>,
                         cudaFuncAttributeMaxDynamicSharedMemorySize, GSMEM);
    cudaFuncSetAttribute(tc_gemm_kernel<1>,
                         cudaFuncAttributeMaxDynamicSharedMemorySize, GSMEM);
    cudaFuncSetAttribute(attn_kernel,
                         cudaFuncAttributeMaxDynamicSharedMemorySize, AT_SMEM);

    // ordered so the QKV GEMM lands on the ncu-captured launch slot
    split_kernel<<<(ROWS * CC) / 256, 256>>>(x, xh, xl, ROWS * CC);                    // 0
    transpose_half_kernel<<<dim3(CC / 32, N_QKV / 32), 256>>>(Wqkv, wq, CC, N_QKV);    // 1
    rope_table_kernel<<<(TT * 32) / 256, 256>>>(ct, st);                               // 2

    // 3) QKV GEMM + bias + fused RoPE -> fp16 Q,K,V
    tc_gemm_kernel<1><<<dim3(N_QKV / 128, ROWS / 128), 256, GSMEM>>>(
        xh, xl, wq, bqkv, nullptr, qh, kh, vh, ct, st, N_QKV, CC);

    transpose_half_kernel<<<dim3(CC / 32, CC / 32), 256>>>(Wproj, wp, CC, CC);         // 4

    // 5) V transpose fp16 [bh][t][d] -> [bh][d][t]
    vt_kernel<<<dim3(TT / 64, BB * NHH), 256>>>(vh, vt);

    // 6) tensor-core causal flash attention -> fp16 hi/lo Y
    attn_kernel<<<dim3(TT / 128, BB * NHH), 256, AT_SMEM>>>(qh, kh, vt, yh, yl);

    // 7) output projection + bias
    tc_gemm_kernel<0><<<dim3(CC / 128, ROWS / 128), 256, GSMEM>>>(
        yh, yl, wp, bproj, out, nullptr, nullptr, nullptr, ct, st, CC, CC);
}

// round 10
// speedup vs baseline: 1.7425x; 1.2152x over previous
#include <cuda_runtime.h>
#include <cuda_bf16.h>
#include <cuda_fp16.h>
#include <math.h>
#include <stdint.h>

// Problem constants
#define BB 4
#define TT 2048
#define CC 1024
#define NHH 16
#define HDD 64
#define ROWS (BB*TT)          // 8192
#define N_QKV (3*CC)          // 3072

// ---------------- scratch (device globals; no allocation) ----------------
__device__ __half g_xh[(size_t)ROWS * CC];            // x fp16
__device__ __half g_wq[(size_t)N_QKV * CC];           // Wqkv^T [N,K] fp16
__device__ __half g_wp[(size_t)CC * CC];              // Wproj^T [N,K] fp16
__device__ __half g_yh[(size_t)ROWS * CC];            // attn out hi (fp16)
__device__ __half g_yl[(size_t)ROWS * CC];            // attn out lo (fp16)
__device__ float g_cost[(size_t)TT * 32];
__device__ float g_sint[(size_t)TT * 32];

__device__ __half g_qh[(size_t)BB * NHH * TT * HDD];  // [bh][t][d]
__device__ __half g_kh[(size_t)BB * NHH * TT * HDD];  // [bh][t][d]
__device__ __half g_vh[(size_t)BB * NHH * TT * HDD];  // [bh][t][d]

// ---------------- PTX helpers (arch-baseline only: no tcgen05) ------------
__device__ __forceinline__ uint32_t smem_u32(const void* p) {
    uint32_t a;
    asm("{ .reg .u64 t; cvta.to.shared.u64 t, %1; cvt.u32.u64 %0, t; }" : "=r"(a) : "l"(p));
    return a;
}
__device__ __forceinline__ void cp16(uint32_t saddr, const void* g) {
    asm volatile("cp.async.cg.shared.global [%0], [%1], 16;" :: "r"(saddr), "l"(g));
}
__device__ __forceinline__ void ldsm4(uint32_t* r, uint32_t addr) {
    asm volatile("ldmatrix.sync.aligned.m8n8.x4.shared.b16 {%0,%1,%2,%3}, [%4];"
                 : "=r"(r[0]), "=r"(r[1]), "=r"(r[2]), "=r"(r[3]) : "r"(addr));
}
__device__ __forceinline__ void ldsm4t(uint32_t* r, uint32_t addr) {
    asm volatile("ldmatrix.sync.aligned.m8n8.x4.trans.shared.b16 {%0,%1,%2,%3}, [%4];"
                 : "=r"(r[0]), "=r"(r[1]), "=r"(r[2]), "=r"(r[3]) : "r"(addr));
}
__device__ __forceinline__ void mma16816h(float* c, const uint32_t* a, const uint32_t* b) {
    asm volatile(
        "mma.sync.aligned.m16n8k16.row.col.f32.f16.f16.f32 "
        "{%0,%1,%2,%3}, {%4,%5,%6,%7}, {%8,%9}, {%0,%1,%2,%3};"
        : "+f"(c[0]), "+f"(c[1]), "+f"(c[2]), "+f"(c[3])
        : "r"(a[0]), "r"(a[1]), "r"(a[2]), "r"(a[3]), "r"(b[0]), "r"(b[1]));
}
__device__ __forceinline__ uint32_t packh2(float a, float b) {
    __half2 h = __floats2half2_rn(a, b);
    return *(uint32_t*)&h;
}

// ---------------- conversions ----------------------------------------------
// x f32 -> fp16 (single quantize; Q/K/V are fp16 downstream anyway)
__global__ __launch_bounds__(256) void quant_half_kernel(
    const float* __restrict__ in, __half* __restrict__ out, int n)
{
    int i = blockIdx.x * 256 + threadIdx.x;
    if (i >= n) return;
    out[i] = __float2half(in[i]);
}

// W[K,N] f32 -> [N,K] fp16 (transpose + quantize once)
__global__ __launch_bounds__(256) void transpose_half_kernel(
    const float* __restrict__ W, __half* __restrict__ Wt, int K, int N)
{
    __shared__ float tile[32][33];
    int k0 = blockIdx.x * 32, n0 = blockIdx.y * 32;
    int tx = threadIdx.x & 31, ty = threadIdx.x >> 5;   // 32x8
    #pragma unroll
    for (int r = 0; r < 4; r++)
        tile[ty + 8 * r][tx] = W[(size_t)(k0 + ty + 8 * r) * N + n0 + tx];
    __syncthreads();
    #pragma unroll
    for (int r = 0; r < 4; r++)
        Wt[(size_t)(n0 + ty + 8 * r) * K + k0 + tx] = __float2half(tile[tx][ty + 8 * r]);
}

// ---------------- RoPE table (mimic jax f32 computation) -------------------
__global__ __launch_bounds__(256) void rope_table_kernel(float* ct, float* st) {
    int idx = blockIdx.x * 256 + threadIdx.x;   // TT*32
    int t = idx >> 5, i = idx & 31;
    float invf = (float)exp(-(double)i / 32.0 * 9.210340371976184);
    float fr = (float)t * invf;
    double a = (double)fr;
    ct[idx] = (float)cos(a);
    st[idx] = (float)sin(a);
}

// ---------------- HMMA GEMM (mma.sync, 1- or 2-pass fp16) ------------------
// PASSES=1: C = Ah @ B^T            (QKV: x fp16)
// PASSES=2: C = (Ah + Al) @ B^T     (proj: exact-y hi/lo split)
// MODE 0: f32 out + bias.  MODE 1: fused QKV bias+RoPE -> fp16 Q,K,V.
#define TILE_B 16384

template<int PASSES>
__device__ __forceinline__ void load_stage(
    uint32_t base, int kt, int tid, int row0, int col0, int K,
    const __half* __restrict__ Ah, const __half* __restrict__ Al,
    const __half* __restrict__ Bq)
{
    int k0 = kt * 64;
    #pragma unroll
    for (int i = 0; i < 4; i++) {
        int lin = i * 256 + tid;
        int r = lin >> 3, c = lin & 7;
        uint32_t off = r * 128 + c * 16;
        uint32_t sw = off ^ ((off >> 3) & 0x70);
        cp16(base + sw, Ah + (size_t)(row0 + r) * K + k0 + c * 8);
        if (PASSES == 2)
            cp16(base + TILE_B + sw, Al + (size_t)(row0 + r) * K + k0 + c * 8);
        cp16(base + PASSES * TILE_B + sw, Bq + (size_t)(col0 + r) * K + k0 + c * 8);
    }
    asm volatile("cp.async.commit_group;" ::: "memory");
}

template<int MODE, int PASSES>
__global__ __launch_bounds__(256, 1) void tc_gemm_kernel(
    const __half* __restrict__ Ah, const __half* __restrict__ Al,
    const __half* __restrict__ Bq,
    const float* __restrict__ bias, float* __restrict__ C,
    __half* __restrict__ Qo, __half* __restrict__ Ko, __half* __restrict__ Vo,
    const float* __restrict__ ct, const float* __restrict__ st,
    int N, int K)
{
    const uint32_t STB = (PASSES + 1) * TILE_B;
    extern __shared__ char smem[];
    uint32_t sb = smem_u32(smem);
    const int tid = threadIdx.x;
    const int wid = tid >> 5, lane = tid & 31;
    const int wr = (wid & 3) * 32;
    const int wc = (wid >> 2) * 64;
    const int col0 = blockIdx.x * 128;
    const int row0 = blockIdx.y * 128;
    const int NK = K >> 6;

    float acc[2][8][4];
    #pragma unroll
    for (int mi = 0; mi < 2; mi++)
        #pragma unroll
        for (int ni = 0; ni < 8; ni++)
            #pragma unroll
            for (int j = 0; j < 4; j++) acc[mi][ni][j] = 0.f;

    load_stage<PASSES>(sb, 0, tid, row0, col0, K, Ah, Al, Bq);
    if (NK > 1)
        load_stage<PASSES>(sb + STB, 1, tid, row0, col0, K, Ah, Al, Bq);

    const int grp = lane >> 3, l8 = lane & 7;

    for (int kt = 0; kt < NK; kt++) {
        if (kt + 1 < NK) { asm volatile("cp.async.wait_group 1;" ::: "memory"); }
        else             { asm volatile("cp.async.wait_group 0;" ::: "memory"); }
        __syncthreads();

        uint32_t sbase = sb + (kt % 3) * STB;
        uint32_t ahb = sbase, alb = sbase + TILE_B;
        uint32_t bbase = sbase + PASSES * TILE_B;
        #pragma unroll
        for (int ks = 0; ks < 4; ks++) {
            uint32_t b[8][2];
            #pragma unroll
            for (int nj = 0; nj < 4; nj++) {
                int row = wc + nj * 16 + (grp >> 1) * 8 + l8;
                int chunk = ks * 2 + (grp & 1);
                uint32_t rr[4];
                ldsm4(rr, bbase + row * 128 + ((chunk ^ (row & 7)) << 4));
                b[2 * nj][0] = rr[0]; b[2 * nj][1] = rr[1];
                b[2 * nj + 1][0] = rr[2]; b[2 * nj + 1][1] = rr[3];
            }
            uint32_t ah[2][4], al[2][4];
            #pragma unroll
            for (int mi = 0; mi < 2; mi++) {
                int row = wr + mi * 16 + (grp & 1) * 8 + l8;
                int chunk = ks * 2 + (grp >> 1);
                uint32_t sw = ((chunk ^ (row & 7)) << 4);
                ldsm4(ah[mi], ahb + row * 128 + sw);
                if (PASSES == 2) ldsm4(al[mi], alb + row * 128 + sw);
            }
            #pragma unroll
            for (int mi = 0; mi < 2; mi++)
                #pragma unroll
                for (int ni = 0; ni < 8; ni++)
                    mma16816h(acc[mi][ni], ah[mi], b[ni]);
            if (PASSES == 2) {
                #pragma unroll
                for (int mi = 0; mi < 2; mi++)
                    #pragma unroll
                    for (int ni = 0; ni < 8; ni++)
                        mma16816h(acc[mi][ni], al[mi], b[ni]);
            }
        }
        if (kt + 2 < NK)
            load_stage<PASSES>(sb + ((kt + 2) % 3) * STB, kt + 2, tid, row0, col0, K,
                               Ah, Al, Bq);
    }

    const int qr = lane >> 2, qc = (lane & 3) * 2;

    if (MODE == 0) {
        #pragma unroll
        for (int mi = 0; mi < 2; mi++) {
            #pragma unroll
            for (int ni = 0; ni < 8; ni++) {
                int r = row0 + wr + mi * 16 + qr;
                int c = col0 + wc + ni * 8 + qc;
                float b0 = bias[c], b1 = bias[c + 1];
                float2 o0 = make_float2(acc[mi][ni][0] + b0, acc[mi][ni][1] + b1);
                float2 o1 = make_float2(acc[mi][ni][2] + b0, acc[mi][ni][3] + b1);
                *(float2*)&C[(size_t)r * N + c] = o0;
                *(float2*)&C[(size_t)(r + 8) * N + c] = o1;
            }
        }
    } else {
        // fused QKV epilogue: bias + RoPE -> fp16
        int cb = col0 + wc;                 // 64-aligned head base
        int sec = cb >> 10;                 // 0=q, 1=k, 2=v
        int h = (cb & 1023) >> 6;
        #pragma unroll
        for (int mi = 0; mi < 2; mi++) {
            int r0 = row0 + wr + mi * 16 + qr;
            #pragma unroll
            for (int half = 0; half < 2; half++) {
                int r = r0 + half * 8;
                int e = half * 2;
                int t = r & (TT - 1);
                int b_ = r >> 11;
                size_t rowoff = ((size_t)((b_ * NHH + h) * TT + t)) * HDD;
                #pragma unroll
                for (int nj = 0; nj < 4; nj++) {
                    int d0 = nj * 8 + qc;            // even, < 32
                    int c0 = cb + d0;
                    float u00 = acc[mi][nj][e]     + bias[c0];
                    float u01 = acc[mi][nj][e + 1] + bias[c0 + 1];
                    float u10 = acc[mi][nj + 4][e]     + bias[c0 + 32];
                    float u11 = acc[mi][nj + 4][e + 1] + bias[c0 + 33];
                    if (sec < 2) {
                        float cA = ct[t * 32 + d0], cB = ct[t * 32 + d0 + 1];
                        float sA = st[t * 32 + d0], sB = st[t * 32 + d0 + 1];
                        float lo0 = u00 * cA - u10 * sA;
                        float lo1 = u01 * cB - u11 * sB;
                        float hi0 = u10 * cA + u00 * sA;
                        float hi1 = u11 * cB + u01 * sB;
                        __half* dst = (sec == 0) ? Qo : Ko;
                        *(__half2*)&dst[rowoff + d0]      = __floats2half2_rn(lo0, lo1);
                        *(__half2*)&dst[rowoff + d0 + 32] = __floats2half2_rn(hi0, hi1);
                    } else {
                        *(__half2*)&Vo[rowoff + d0]      = __floats2half2_rn(u00, u01);
                        *(__half2*)&Vo[rowoff + d0 + 32] = __floats2half2_rn(u10, u11);
                    }
                }
            }
        }
    }
}

// ---------------- Tensor-core flash attention (fp16, BM=128 BN=64) ---------
// 256 threads (8 warps x 16 q-rows), 2-stage KV pipeline, diag work skipping.
// V consumed straight from [t][d] layout via ldmatrix.trans (no vt kernel).
#define AT_SMEM (16384 + 2*16384)   // Q + 2 stages of (K 8KB + V 8KB)

__device__ __forceinline__ void attn_load_kv(
    uint32_t dst, const __half* __restrict__ Kb, const __half* __restrict__ Vb,
    int ktbase, int tid)
{
    #pragma unroll
    for (int i = 0; i < 2; i++) {
        int lin = i * 256 + tid;
        int r = lin >> 3, c = lin & 7;
        uint32_t sw = r * 128 + ((c ^ (r & 7)) << 4);
        cp16(dst + sw, Kb + (size_t)(ktbase + r) * HDD + c * 8);
        cp16(dst + 8192 + sw, Vb + (size_t)(ktbase + r) * HDD + c * 8);
    }
    asm volatile("cp.async.commit_group;" ::: "memory");
}

__global__ __launch_bounds__(256, 2) void attn_kernel(
    const __half* __restrict__ Qg, const __half* __restrict__ Kg,
    const __half* __restrict__ Vg,
    __half* __restrict__ Yh, __half* __restrict__ Yl)
{
    extern __shared__ char smem[];
    uint32_t sb = smem_u32(smem);
    uint32_t sQ = sb;
    uint32_t sKV = sb + 16384;

    const int tid = threadIdx.x;
    const int wid = tid >> 5, lane = tid & 31;
    const int grp = lane >> 3, l8 = lane & 7;
    const int qt = (int)gridDim.x - 1 - (int)blockIdx.x;   // longest first
    const int bh = blockIdx.y;
    const int q0 = qt * 128;
    const int nkt = 2 * qt + 2;

    const __half* Qb = Qg + ((size_t)bh * TT + q0) * HDD;
    const __half* Kb = Kg + (size_t)bh * TT * HDD;
    const __half* Vb = Vg + (size_t)bh * TT * HDD;

    // stage Q (group 0) then prefetch kv tile 0 (group 1)
    #pragma unroll
    for (int i = 0; i < 4; i++) {
        int lin = i * 256 + tid;
        int r = lin >> 3, c = lin & 7;
        cp16(sQ + r * 128 + ((c ^ (r & 7)) << 4), Qb + (size_t)r * HDD + c * 8);
    }
    asm volatile("cp.async.commit_group;" ::: "memory");
    attn_load_kv(sKV, Kb, Vb, 0, tid);

    asm volatile("cp.async.wait_group 1;" ::: "memory");   // Q ready
    __syncthreads();

    // preload Q fragments
    uint32_t qf[4][4];
    #pragma unroll
    for (int kc = 0; kc < 4; kc++) {
        int row = wid * 16 + (grp & 1) * 8 + l8;
        int ch = kc * 2 + (grp >> 1);
        ldsm4(qf[kc], sQ + row * 128 + ((ch ^ (row & 7)) << 4));
    }

    float m0 = -1e30f, m1 = -1e30f, l0 = 0.f, l1 = 0.f;
    float oacc[8][4];
    #pragma unroll
    for (int nj = 0; nj < 8; nj++)
        #pragma unroll
        for (int e = 0; e < 4; e++) oacc[nj][e] = 0.f;

    const int rquad = lane >> 2;       // 0..7
    const int cpair = (lane & 3) * 2;  // 0,2,4,6

    for (int kt = 0; kt < nkt; kt++) {
        int s = kt & 1;
        if (kt + 1 < nkt) {
            attn_load_kv(sKV + (s ^ 1) * 16384, Kb, Vb, (kt + 1) * 64, tid);
            asm volatile("cp.async.wait_group 1;" ::: "memory");
        } else {
            asm volatile("cp.async.wait_group 0;" ::: "memory");
        }
        __syncthreads();

        uint32_t sK = sKV + s * 16384;
        uint32_t sV = sK + 8192;

        // diagonal work skipping: nb = # of active 16-col blocks (of 4)
        int nb = 4;
        if (kt == nkt - 2)      nb = (wid + 1 < 4) ? wid + 1 : 4;
        else if (kt == nkt - 1) nb = (wid >= 4) ? ((wid - 3 < 4) ? wid - 3 : 4) : 0;

        // S = Q K^T
        float sacc[8][4];
        #pragma unroll
        for (int nj = 0; nj < 8; nj++)
            #pragma unroll
            for (int e = 0; e < 4; e++) sacc[nj][e] = 0.f;

        #pragma unroll
        for (int ks = 0; ks < 4; ks++) {
            #pragma unroll
            for (int nj = 0; nj < 4; nj++) {
                if (nj < nb) {
                    int row = nj * 16 + (grp >> 1) * 8 + l8;
                    int ch = ks * 2 + (grp & 1);
                    uint32_t rr[4];
                    ldsm4(rr, sK + row * 128 + ((ch ^ (row & 7)) << 4));
                    uint32_t b0[2] = {rr[0], rr[1]}, b1[2] = {rr[2], rr[3]};
                    mma16816h(sacc[2 * nj], qf[ks], b0);
                    mma16816h(sacc[2 * nj + 1], qf[ks], b1);
                }
            }
        }

        // scale + causal mask (only last two tiles touch the diagonal)
        const float sc = 0.125f;
        if (kt >= nkt - 2) {
            int row0g = q0 + wid * 16 + rquad;
            #pragma unroll
            for (int nj = 0; nj < 8; nj++) {
                int colg = kt * 64 + nj * 8 + cpair;
                #pragma unroll
                for (int e = 0; e < 4; e++) {
                    int cg = colg + (e & 1);
                    int rg = row0g + ((e >= 2) ? 8 : 0);
                    sacc[nj][e] = (cg <= rg) ? sacc[nj][e] * sc : -1e30f;
                }
            }
        } else {
            #pragma unroll
            for (int nj = 0; nj < 8; nj++)
                #pragma unroll
                for (int e = 0; e < 4; e++) sacc[nj][e] *= sc;
        }

        // online softmax (two rows per thread; 4-lane quad reductions)
        float rm0 = -1e30f, rm1 = -1e30f;
        #pragma unroll
        for (int nj = 0; nj < 8; nj++) {
            rm0 = fmaxf(rm0, fmaxf(sacc[nj][0], sacc[nj][1]));
            rm1 = fmaxf(rm1, fmaxf(sacc[nj][2], sacc[nj][3]));
        }
        rm0 = fmaxf(rm0, __shfl_xor_sync(0xffffffffu, rm0, 1));
        rm0 = fmaxf(rm0, __shfl_xor_sync(0xffffffffu, rm0, 2));
        rm1 = fmaxf(rm1, __shfl_xor_sync(0xffffffffu, rm1, 1));
        rm1 = fmaxf(rm1, __shfl_xor_sync(0xffffffffu, rm1, 2));

        float n0 = fmaxf(m0, rm0), n1 = fmaxf(m1, rm1);
        float a0 = __expf(m0 - n0), a1 = __expf(m1 - n1);
        float rs0 = 0.f, rs1 = 0.f;
        #pragma unroll
        for (int nj = 0; nj < 8; nj++) {
            sacc[nj][0] = __expf(sacc[nj][0] - n0);
            sacc[nj][1] = __expf(sacc[nj][1] - n0);
            sacc[nj][2] = __expf(sacc[nj][2] - n1);
            sacc[nj][3] = __expf(sacc[nj][3] - n1);
            rs0 += sacc[nj][0] + sacc[nj][1];
            rs1 += sacc[nj][2] + sacc[nj][3];
        }
        rs0 += __shfl_xor_sync(0xffffffffu, rs0, 1);
        rs0 += __shfl_xor_sync(0xffffffffu, rs0, 2);
        rs1 += __shfl_xor_sync(0xffffffffu, rs1, 1);
        rs1 += __shfl_xor_sync(0xffffffffu, rs1, 2);

        l0 = l0 * a0 + rs0;
        l1 = l1 * a1 + rs1;
        m0 = n0; m1 = n1;
        #pragma unroll
        for (int nj = 0; nj < 8; nj++) {
            oacc[nj][0] *= a0; oacc[nj][1] *= a0;
            oacc[nj][2] *= a1; oacc[nj][3] *= a1;
        }

        // pack P into A-operand fragments (registers only)
        uint32_t pf[4][4];
        #pragma unroll
        for (int kc = 0; kc < 4; kc++) {
            pf[kc][0] = packh2(sacc[2 * kc][0],     sacc[2 * kc][1]);
            pf[kc][1] = packh2(sacc[2 * kc][2],     sacc[2 * kc][3]);
            pf[kc][2] = packh2(sacc[2 * kc + 1][0], sacc[2 * kc + 1][1]);
            pf[kc][3] = packh2(sacc[2 * kc + 1][2], sacc[2 * kc + 1][3]);
        }

        // O += P @ V ; V is [t][d] in smem, B-fragments via ldmatrix.trans
        #pragma unroll
        for (int kc = 0; kc < 4; kc++) {
            if (kc < nb) {
                #pragma unroll
                for (int nj = 0; nj < 4; nj++) {
                    int trow = kc * 16 + (grp & 1) * 8 + l8;   // t rows
                    int ch = nj * 2 + (grp >> 1);              // d chunks
                    uint32_t rr[4];
                    ldsm4t(rr, sV + trow * 128 + ((ch ^ (trow & 7)) << 4));
                    uint32_t b0[2] = {rr[0], rr[1]}, b1[2] = {rr[2], rr[3]};
                    mma16816h(oacc[2 * nj], pf[kc], b0);
                    mma16816h(oacc[2 * nj + 1], pf[kc], b1);
                }
            }
        }
        __syncthreads();
    }

    // epilogue: normalize + fp16 hi/lo split store to [b,t,c]
    float i0 = 1.f / l0, i1 = 1.f / l1;
    int b_ = bh >> 4, h = bh & 15;
    int r0g = q0 + wid * 16 + rquad;
    #pragma unroll
    for (int nj = 0; nj < 8; nj++) {
        int c = h * 64 + nj * 8 + cpair;
        float v0 = oacc[nj][0] * i0, v1 = oacc[nj][1] * i0;
        float v2 = oacc[nj][2] * i1, v3 = oacc[nj][3] * i1;
        size_t o0 = (size_t)(b_ * TT + r0g) * CC + c;
        size_t o1 = (size_t)(b_ * TT + r0g + 8) * CC + c;
        __half2 h0 = __floats2half2_rn(v0, v1);
        __half2 h1 = __floats2half2_rn(v2, v3);
        *(__half2*)&Yh[o0] = h0;
        *(__half2*)&Yh[o1] = h1;
        *(__half2*)&Yl[o0] = __floats2half2_rn(v0 - __half2float(__low2half(h0)),
                                               v1 - __half2float(__high2half(h0)));
        *(__half2*)&Yl[o1] = __floats2half2_rn(v2 - __half2float(__low2half(h1)),
                                               v3 - __half2float(__high2half(h1)));
    }
}

// ---------------- launch ---------------------------------------------------
extern "C" void kernel_launch(void* const* d_in, const int* in_sizes, int n_in,
                              void* d_out, int out_size)
{
    const float* x     = (const float*)d_in[0];
    const float* Wqkv  = (const float*)d_in[1];
    const float* bqkv  = (const float*)d_in[2];
    const float* Wproj = (const float*)d_in[3];
    const float* bproj = (const float*)d_in[4];
    float* out = (float*)d_out;

    float *ct, *st;
    __half *xh, *wq, *wp, *yh, *yl, *qh, *kh, *vh;
    cudaGetSymbolAddress((void**)&ct, g_cost);
    cudaGetSymbolAddress((void**)&st, g_sint);
    cudaGetSymbolAddress((void**)&xh, g_xh);
    cudaGetSymbolAddress((void**)&wq, g_wq);
    cudaGetSymbolAddress((void**)&wp, g_wp);
    cudaGetSymbolAddress((void**)&yh, g_yh);
    cudaGetSymbolAddress((void**)&yl, g_yl);
    cudaGetSymbolAddress((void**)&qh, g_qh);
    cudaGetSymbolAddress((void**)&kh, g_kh);
    cudaGetSymbolAddress((void**)&vh, g_vh);

    const int GS1 = 3 * 2 * TILE_B;   // 1-pass: 96 KB
    const int GS2 = 3 * 3 * TILE_B;   // 2-pass: 144 KB
    cudaFuncSetAttribute(tc_gemm_kernel<1, 1>,
                         cudaFuncAttributeMaxDynamicSharedMemorySize, GS1);
    cudaFuncSetAttribute(tc_gemm_kernel<0, 2>,
                         cudaFuncAttributeMaxDynamicSharedMemorySize, GS2);
    cudaFuncSetAttribute(attn_kernel,
                         cudaFuncAttributeMaxDynamicSharedMemorySize, AT_SMEM);

    // launches ordered so ncu (-s 5 -c 1) captures the attention kernel
    quant_half_kernel<<<(ROWS * CC) / 256, 256>>>(x, xh, ROWS * CC);                   // 1
    transpose_half_kernel<<<dim3(CC / 32, N_QKV / 32), 256>>>(Wqkv, wq, CC, N_QKV);    // 2
    rope_table_kernel<<<(TT * 32) / 256, 256>>>(ct, st);                               // 3

    // 4) QKV GEMM (1-pass fp16) + bias + fused RoPE -> fp16 Q,K,V
    tc_gemm_kernel<1, 1><<<dim3(N_QKV / 128, ROWS / 128), 256, GS1>>>(
        xh, nullptr, wq, bqkv, nullptr, qh, kh, vh, ct, st, N_QKV, CC);

    transpose_half_kernel<<<dim3(CC / 32, CC / 32), 256>>>(Wproj, wp, CC, CC);         // 5

    // 6) tensor-core causal flash attention -> fp16 hi/lo Y
    attn_kernel<<<dim3(TT / 128, BB * NHH), 256, AT_SMEM>>>(qh, kh, vh, yh, yl);

    // 7) output projection (2-pass exact-y) + bias
    tc_gemm_kernel<0, 2><<<dim3(CC / 128, ROWS / 128), 256, GS2>>>(
        yh, yl, wp, bproj, out, nullptr, nullptr, nullptr, ct, st, CC, CC);
}

// round 11
// speedup vs baseline: 1.8692x; 1.0727x over previous
#include <cuda_runtime.h>
#include <cuda_bf16.h>
#include <cuda_fp16.h>
#include <math.h>
#include <stdint.h>

// Problem constants
#define BB 4
#define TT 2048
#define CC 1024
#define NHH 16
#define HDD 64
#define ROWS (BB*TT)          // 8192
#define N_QKV (3*CC)          // 3072

// ---------------- scratch (device globals; no allocation) ----------------
__device__ __half g_xh[(size_t)ROWS * CC];            // x fp16
__device__ __half g_wq[(size_t)N_QKV * CC];           // Wqkv^T [N,K] fp16
__device__ __half g_wp[(size_t)CC * CC];              // Wproj^T [N,K] fp16
__device__ __half g_yh[(size_t)ROWS * CC];            // attn out (fp16)
__device__ float g_cost[(size_t)TT * 32];
__device__ float g_sint[(size_t)TT * 32];

__device__ __half g_qh[(size_t)BB * NHH * TT * HDD];  // [bh][t][d]
__device__ __half g_kh[(size_t)BB * NHH * TT * HDD];  // [bh][t][d]
__device__ __half g_vh[(size_t)BB * NHH * TT * HDD];  // [bh][t][d]

// ---------------- PTX helpers (arch-baseline only: no tcgen05) ------------
__device__ __forceinline__ uint32_t smem_u32(const void* p) {
    uint32_t a;
    asm("{ .reg .u64 t; cvta.to.shared.u64 t, %1; cvt.u32.u64 %0, t; }" : "=r"(a) : "l"(p));
    return a;
}
__device__ __forceinline__ void cp16(uint32_t saddr, const void* g) {
    asm volatile("cp.async.cg.shared.global [%0], [%1], 16;" :: "r"(saddr), "l"(g));
}
__device__ __forceinline__ void ldsm4(uint32_t* r, uint32_t addr) {
    asm volatile("ldmatrix.sync.aligned.m8n8.x4.shared.b16 {%0,%1,%2,%3}, [%4];"
                 : "=r"(r[0]), "=r"(r[1]), "=r"(r[2]), "=r"(r[3]) : "r"(addr));
}
__device__ __forceinline__ void ldsm4t(uint32_t* r, uint32_t addr) {
    asm volatile("ldmatrix.sync.aligned.m8n8.x4.trans.shared.b16 {%0,%1,%2,%3}, [%4];"
                 : "=r"(r[0]), "=r"(r[1]), "=r"(r[2]), "=r"(r[3]) : "r"(addr));
}
__device__ __forceinline__ void mma16816h(float* c, const uint32_t* a, const uint32_t* b) {
    asm volatile(
        "mma.sync.aligned.m16n8k16.row.col.f32.f16.f16.f32 "
        "{%0,%1,%2,%3}, {%4,%5,%6,%7}, {%8,%9}, {%0,%1,%2,%3};"
        : "+f"(c[0]), "+f"(c[1]), "+f"(c[2]), "+f"(c[3])
        : "r"(a[0]), "r"(a[1]), "r"(a[2]), "r"(a[3]), "r"(b[0]), "r"(b[1]));
}
__device__ __forceinline__ uint32_t packh2(float a, float b) {
    __half2 h = __floats2half2_rn(a, b);
    return *(uint32_t*)&h;
}

// ---------------- conversions ----------------------------------------------
__global__ __launch_bounds__(256) void quant_half_kernel(
    const float* __restrict__ in, __half* __restrict__ out, int n)
{
    int i = blockIdx.x * 256 + threadIdx.x;
    if (i >= n) return;
    out[i] = __float2half(in[i]);
}

// W[K,N] f32 -> [N,K] fp16 (transpose + quantize once)
__global__ __launch_bounds__(256) void transpose_half_kernel(
    const float* __restrict__ W, __half* __restrict__ Wt, int K, int N)
{
    __shared__ float tile[32][33];
    int k0 = blockIdx.x * 32, n0 = blockIdx.y * 32;
    int tx = threadIdx.x & 31, ty = threadIdx.x >> 5;   // 32x8
    #pragma unroll
    for (int r = 0; r < 4; r++)
        tile[ty + 8 * r][tx] = W[(size_t)(k0 + ty + 8 * r) * N + n0 + tx];
    __syncthreads();
    #pragma unroll
    for (int r = 0; r < 4; r++)
        Wt[(size_t)(n0 + ty + 8 * r) * K + k0 + tx] = __float2half(tile[tx][ty + 8 * r]);
}

// ---------------- RoPE table (mimic jax f32 computation) -------------------
__global__ __launch_bounds__(256) void rope_table_kernel(float* ct, float* st) {
    int idx = blockIdx.x * 256 + threadIdx.x;   // TT*32
    int t = idx >> 5, i = idx & 31;
    float invf = (float)exp(-(double)i / 32.0 * 9.210340371976184);
    float fr = (float)t * invf;
    double a = (double)fr;
    ct[idx] = (float)cos(a);
    st[idx] = (float)sin(a);
}

// ---------------- HMMA GEMM (mma.sync, 1-pass fp16, 4-stage pipeline) ------
// C = A @ B^T ; A:[M,K] fp16, B:[N,K] fp16
// MODE 0: f32 out + bias.  MODE 1: fused QKV bias+RoPE -> fp16 Q,K,V.
#define TILE_B 16384
#define STB (2*TILE_B)          // A tile + B tile per stage (32 KB)
#define GS (4*STB)              // 4 stages = 128 KB

__device__ __forceinline__ void load_stage(
    uint32_t base, int kt, int tid, int row0, int col0, int K,
    const __half* __restrict__ Ah, const __half* __restrict__ Bq)
{
    int k0 = kt * 64;
    #pragma unroll
    for (int i = 0; i < 4; i++) {
        int lin = i * 256 + tid;
        int r = lin >> 3, c = lin & 7;
        uint32_t off = r * 128 + c * 16;
        uint32_t sw = off ^ ((off >> 3) & 0x70);
        cp16(base + sw, Ah + (size_t)(row0 + r) * K + k0 + c * 8);
        cp16(base + TILE_B + sw, Bq + (size_t)(col0 + r) * K + k0 + c * 8);
    }
    asm volatile("cp.async.commit_group;" ::: "memory");
}

template<int MODE>
__global__ __launch_bounds__(256, 1) void tc_gemm_kernel(
    const __half* __restrict__ Ah, const __half* __restrict__ Bq,
    const float* __restrict__ bias, float* __restrict__ C,
    __half* __restrict__ Qo, __half* __restrict__ Ko, __half* __restrict__ Vo,
    const float* __restrict__ ct, const float* __restrict__ st,
    int N, int K)
{
    extern __shared__ char smem[];
    uint32_t sb = smem_u32(smem);
    const int tid = threadIdx.x;
    const int wid = tid >> 5, lane = tid & 31;
    const int wr = (wid & 3) * 32;
    const int wc = (wid >> 2) * 64;
    const int col0 = blockIdx.x * 128;
    const int row0 = blockIdx.y * 128;
    const int NK = K >> 6;

    float acc[2][8][4];
    #pragma unroll
    for (int mi = 0; mi < 2; mi++)
        #pragma unroll
        for (int ni = 0; ni < 8; ni++)
            #pragma unroll
            for (int j = 0; j < 4; j++) acc[mi][ni][j] = 0.f;

    load_stage(sb, 0, tid, row0, col0, K, Ah, Bq);
    if (NK > 1) load_stage(sb + STB, 1, tid, row0, col0, K, Ah, Bq);
    if (NK > 2) load_stage(sb + 2 * STB, 2, tid, row0, col0, K, Ah, Bq);

    const int grp = lane >> 3, l8 = lane & 7;

    for (int kt = 0; kt < NK; kt++) {
        int rem = NK - 1 - kt;
        if (rem >= 2)      { asm volatile("cp.async.wait_group 2;" ::: "memory"); }
        else if (rem == 1) { asm volatile("cp.async.wait_group 1;" ::: "memory"); }
        else               { asm volatile("cp.async.wait_group 0;" ::: "memory"); }
        __syncthreads();

        // issue prefetch for kt+3 BEFORE compute (slot of kt-1, consumed)
        if (kt + 3 < NK)
            load_stage(sb + ((kt + 3) & 3) * STB, kt + 3, tid, row0, col0, K, Ah, Bq);

        uint32_t sbase = sb + (kt & 3) * STB;
        uint32_t ahb = sbase, bbase = sbase + TILE_B;
        #pragma unroll
        for (int ks = 0; ks < 4; ks++) {
            uint32_t b[8][2];
            #pragma unroll
            for (int nj = 0; nj < 4; nj++) {
                int row = wc + nj * 16 + (grp >> 1) * 8 + l8;
                int chunk = ks * 2 + (grp & 1);
                uint32_t rr[4];
                ldsm4(rr, bbase + row * 128 + ((chunk ^ (row & 7)) << 4));
                b[2 * nj][0] = rr[0]; b[2 * nj][1] = rr[1];
                b[2 * nj + 1][0] = rr[2]; b[2 * nj + 1][1] = rr[3];
            }
            uint32_t ah[2][4];
            #pragma unroll
            for (int mi = 0; mi < 2; mi++) {
                int row = wr + mi * 16 + (grp & 1) * 8 + l8;
                int chunk = ks * 2 + (grp >> 1);
                ldsm4(ah[mi], ahb + row * 128 + ((chunk ^ (row & 7)) << 4));
            }
            #pragma unroll
            for (int mi = 0; mi < 2; mi++)
                #pragma unroll
                for (int ni = 0; ni < 8; ni++)
                    mma16816h(acc[mi][ni], ah[mi], b[ni]);
        }
    }

    const int qr = lane >> 2, qc = (lane & 3) * 2;

    if (MODE == 0) {
        #pragma unroll
        for (int mi = 0; mi < 2; mi++) {
            #pragma unroll
            for (int ni = 0; ni < 8; ni++) {
                int r = row0 + wr + mi * 16 + qr;
                int c = col0 + wc + ni * 8 + qc;
                float b0 = bias[c], b1 = bias[c + 1];
                float2 o0 = make_float2(acc[mi][ni][0] + b0, acc[mi][ni][1] + b1);
                float2 o1 = make_float2(acc[mi][ni][2] + b0, acc[mi][ni][3] + b1);
                *(float2*)&C[(size_t)r * N + c] = o0;
                *(float2*)&C[(size_t)(r + 8) * N + c] = o1;
            }
        }
    } else {
        // fused QKV epilogue: bias + RoPE -> fp16
        int cb = col0 + wc;                 // 64-aligned head base
        int sec = cb >> 10;                 // 0=q, 1=k, 2=v
        int h = (cb & 1023) >> 6;
        #pragma unroll
        for (int mi = 0; mi < 2; mi++) {
            int r0 = row0 + wr + mi * 16 + qr;
            #pragma unroll
            for (int half = 0; half < 2; half++) {
                int r = r0 + half * 8;
                int e = half * 2;
                int t = r & (TT - 1);
                int b_ = r >> 11;
                size_t rowoff = ((size_t)((b_ * NHH + h) * TT + t)) * HDD;
                #pragma unroll
                for (int nj = 0; nj < 4; nj++) {
                    int d0 = nj * 8 + qc;            // even, < 32
                    int c0 = cb + d0;
                    float u00 = acc[mi][nj][e]     + bias[c0];
                    float u01 = acc[mi][nj][e + 1] + bias[c0 + 1];
                    float u10 = acc[mi][nj + 4][e]     + bias[c0 + 32];
                    float u11 = acc[mi][nj + 4][e + 1] + bias[c0 + 33];
                    if (sec < 2) {
                        float cA = ct[t * 32 + d0], cB = ct[t * 32 + d0 + 1];
                        float sA = st[t * 32 + d0], sB = st[t * 32 + d0 + 1];
                        float lo0 = u00 * cA - u10 * sA;
                        float lo1 = u01 * cB - u11 * sB;
                        float hi0 = u10 * cA + u00 * sA;
                        float hi1 = u11 * cB + u01 * sB;
                        __half* dst = (sec == 0) ? Qo : Ko;
                        *(__half2*)&dst[rowoff + d0]      = __floats2half2_rn(lo0, lo1);
                        *(__half2*)&dst[rowoff + d0 + 32] = __floats2half2_rn(hi0, hi1);
                    } else {
                        *(__half2*)&Vo[rowoff + d0]      = __floats2half2_rn(u00, u01);
                        *(__half2*)&Vo[rowoff + d0 + 32] = __floats2half2_rn(u10, u11);
                    }
                }
            }
        }
    }
}

// ---------------- Tensor-core flash attention (fp16, BM=128 BN=64) ---------
// 256 threads (8 warps x 16 q-rows), 2-stage KV pipeline, diag work skipping.
// V consumed straight from [t][d] layout via ldmatrix.trans.
#define AT_SMEM (16384 + 2*16384)   // Q + 2 stages of (K 8KB + V 8KB)

__device__ __forceinline__ void attn_load_kv(
    uint32_t dst, const __half* __restrict__ Kb, const __half* __restrict__ Vb,
    int ktbase, int tid)
{
    #pragma unroll
    for (int i = 0; i < 2; i++) {
        int lin = i * 256 + tid;
        int r = lin >> 3, c = lin & 7;
        uint32_t sw = r * 128 + ((c ^ (r & 7)) << 4);
        cp16(dst + sw, Kb + (size_t)(ktbase + r) * HDD + c * 8);
        cp16(dst + 8192 + sw, Vb + (size_t)(ktbase + r) * HDD + c * 8);
    }
    asm volatile("cp.async.commit_group;" ::: "memory");
}

__global__ __launch_bounds__(256, 2) void attn_kernel(
    const __half* __restrict__ Qg, const __half* __restrict__ Kg,
    const __half* __restrict__ Vg, __half* __restrict__ Yh)
{
    extern __shared__ char smem[];
    uint32_t sb = smem_u32(smem);
    uint32_t sQ = sb;
    uint32_t sKV = sb + 16384;

    const int tid = threadIdx.x;
    const int wid = tid >> 5, lane = tid & 31;
    const int grp = lane >> 3, l8 = lane & 7;
    const int qt = (int)gridDim.x - 1 - (int)blockIdx.x;   // longest first
    const int bh = blockIdx.y;
    const int q0 = qt * 128;
    const int nkt = 2 * qt + 2;

    const __half* Qb = Qg + ((size_t)bh * TT + q0) * HDD;
    const __half* Kb = Kg + (size_t)bh * TT * HDD;
    const __half* Vb = Vg + (size_t)bh * TT * HDD;

    // stage Q (group 0) then prefetch kv tile 0 (group 1)
    #pragma unroll
    for (int i = 0; i < 4; i++) {
        int lin = i * 256 + tid;
        int r = lin >> 3, c = lin & 7;
        cp16(sQ + r * 128 + ((c ^ (r & 7)) << 4), Qb + (size_t)r * HDD + c * 8);
    }
    asm volatile("cp.async.commit_group;" ::: "memory");
    attn_load_kv(sKV, Kb, Vb, 0, tid);

    asm volatile("cp.async.wait_group 1;" ::: "memory");   // Q ready
    __syncthreads();

    // preload Q fragments
    uint32_t qf[4][4];
    #pragma unroll
    for (int kc = 0; kc < 4; kc++) {
        int row = wid * 16 + (grp & 1) * 8 + l8;
        int ch = kc * 2 + (grp >> 1);
        ldsm4(qf[kc], sQ + row * 128 + ((ch ^ (row & 7)) << 4));
    }

    float m0 = -1e30f, m1 = -1e30f, l0 = 0.f, l1 = 0.f;
    float oacc[8][4];
    #pragma unroll
    for (int nj = 0; nj < 8; nj++)
        #pragma unroll
        for (int e = 0; e < 4; e++) oacc[nj][e] = 0.f;

    const int rquad = lane >> 2;       // 0..7
    const int cpair = (lane & 3) * 2;  // 0,2,4,6

    for (int kt = 0; kt < nkt; kt++) {
        int s = kt & 1;
        if (kt + 1 < nkt) {
            attn_load_kv(sKV + (s ^ 1) * 16384, Kb, Vb, (kt + 1) * 64, tid);
            asm volatile("cp.async.wait_group 1;" ::: "memory");
        } else {
            asm volatile("cp.async.wait_group 0;" ::: "memory");
        }
        __syncthreads();

        uint32_t sK = sKV + s * 16384;
        uint32_t sV = sK + 8192;

        // diagonal work skipping: nb = # of active 16-col blocks (of 4)
        int nb = 4;
        if (kt == nkt - 2)      nb = (wid + 1 < 4) ? wid + 1 : 4;
        else if (kt == nkt - 1) nb = (wid >= 4) ? ((wid - 3 < 4) ? wid - 3 : 4) : 0;

        // S = Q K^T
        float sacc[8][4];
        #pragma unroll
        for (int nj = 0; nj < 8; nj++)
            #pragma unroll
            for (int e = 0; e < 4; e++) sacc[nj][e] = 0.f;

        #pragma unroll
        for (int ks = 0; ks < 4; ks++) {
            #pragma unroll
            for (int nj = 0; nj < 4; nj++) {
                if (nj < nb) {
                    int row = nj * 16 + (grp >> 1) * 8 + l8;
                    int ch = ks * 2 + (grp & 1);
                    uint32_t rr[4];
                    ldsm4(rr, sK + row * 128 + ((ch ^ (row & 7)) << 4));
                    uint32_t b0[2] = {rr[0], rr[1]}, b1[2] = {rr[2], rr[3]};
                    mma16816h(sacc[2 * nj], qf[ks], b0);
                    mma16816h(sacc[2 * nj + 1], qf[ks], b1);
                }
            }
        }

        // scale + causal mask (only last two tiles touch the diagonal)
        const float sc = 0.125f;
        if (kt >= nkt - 2) {
            int row0g = q0 + wid * 16 + rquad;
            #pragma unroll
            for (int nj = 0; nj < 8; nj++) {
                int colg = kt * 64 + nj * 8 + cpair;
                #pragma unroll
                for (int e = 0; e < 4; e++) {
                    int cg = colg + (e & 1);
                    int rg = row0g + ((e >= 2) ? 8 : 0);
                    sacc[nj][e] = (cg <= rg) ? sacc[nj][e] * sc : -1e30f;
                }
            }
        } else {
            #pragma unroll
            for (int nj = 0; nj < 8; nj++)
                #pragma unroll
                for (int e = 0; e < 4; e++) sacc[nj][e] *= sc;
        }

        // online softmax (two rows per thread; 4-lane quad reductions)
        float rm0 = -1e30f, rm1 = -1e30f;
        #pragma unroll
        for (int nj = 0; nj < 8; nj++) {
            rm0 = fmaxf(rm0, fmaxf(sacc[nj][0], sacc[nj][1]));
            rm1 = fmaxf(rm1, fmaxf(sacc[nj][2], sacc[nj][3]));
        }
        rm0 = fmaxf(rm0, __shfl_xor_sync(0xffffffffu, rm0, 1));
        rm0 = fmaxf(rm0, __shfl_xor_sync(0xffffffffu, rm0, 2));
        rm1 = fmaxf(rm1, __shfl_xor_sync(0xffffffffu, rm1, 1));
        rm1 = fmaxf(rm1, __shfl_xor_sync(0xffffffffu, rm1, 2));

        float n0 = fmaxf(m0, rm0), n1 = fmaxf(m1, rm1);
        float a0 = __expf(m0 - n0), a1 = __expf(m1 - n1);
        float rs0 = 0.f, rs1 = 0.f;
        #pragma unroll
        for (int nj = 0; nj < 8; nj++) {
            sacc[nj][0] = __expf(sacc[nj][0] - n0);
            sacc[nj][1] = __expf(sacc[nj][1] - n0);
            sacc[nj][2] = __expf(sacc[nj][2] - n1);
            sacc[nj][3] = __expf(sacc[nj][3] - n1);
            rs0 += sacc[nj][0] + sacc[nj][1];
            rs1 += sacc[nj][2] + sacc[nj][3];
        }
        rs0 += __shfl_xor_sync(0xffffffffu, rs0, 1);
        rs0 += __shfl_xor_sync(0xffffffffu, rs0, 2);
        rs1 += __shfl_xor_sync(0xffffffffu, rs1, 1);
        rs1 += __shfl_xor_sync(0xffffffffu, rs1, 2);

        l0 = l0 * a0 + rs0;
        l1 = l1 * a1 + rs1;
        m0 = n0; m1 = n1;
        #pragma unroll
        for (int nj = 0; nj < 8; nj++) {
            oacc[nj][0] *= a0; oacc[nj][1] *= a0;
            oacc[nj][2] *= a1; oacc[nj][3] *= a1;
        }

        // pack P into A-operand fragments (registers only)
        uint32_t pf[4][4];
        #pragma unroll
        for (int kc = 0; kc < 4; kc++) {
            pf[kc][0] = packh2(sacc[2 * kc][0],     sacc[2 * kc][1]);
            pf[kc][1] = packh2(sacc[2 * kc][2],     sacc[2 * kc][3]);
            pf[kc][2] = packh2(sacc[2 * kc + 1][0], sacc[2 * kc + 1][1]);
            pf[kc][3] = packh2(sacc[2 * kc + 1][2], sacc[2 * kc + 1][3]);
        }

        // O += P @ V ; V is [t][d] in smem, B-fragments via ldmatrix.trans
        #pragma unroll
        for (int kc = 0; kc < 4; kc++) {
            if (kc < nb) {
                #pragma unroll
                for (int nj = 0; nj < 4; nj++) {
                    int trow = kc * 16 + (grp & 1) * 8 + l8;   // t rows
                    int ch = nj * 2 + (grp >> 1);              // d chunks
                    uint32_t rr[4];
                    ldsm4t(rr, sV + trow * 128 + ((ch ^ (trow & 7)) << 4));
                    uint32_t b0[2] = {rr[0], rr[1]}, b1[2] = {rr[2], rr[3]};
                    mma16816h(oacc[2 * nj], pf[kc], b0);
                    mma16816h(oacc[2 * nj + 1], pf[kc], b1);
                }
            }
        }
        __syncthreads();
    }

    // epilogue: normalize + fp16 store to [b,t,c]
    float i0 = 1.f / l0, i1 = 1.f / l1;
    int b_ = bh >> 4, h = bh & 15;
    int r0g = q0 + wid * 16 + rquad;
    #pragma unroll
    for (int nj = 0; nj < 8; nj++) {
        int c = h * 64 + nj * 8 + cpair;
        float v0 = oacc[nj][0] * i0, v1 = oacc[nj][1] * i0;
        float v2 = oacc[nj][2] * i1, v3 = oacc[nj][3] * i1;
        size_t o0 = (size_t)(b_ * TT + r0g) * CC + c;
        size_t o1 = (size_t)(b_ * TT + r0g + 8) * CC + c;
        *(__half2*)&Yh[o0] = __floats2half2_rn(v0, v1);
        *(__half2*)&Yh[o1] = __floats2half2_rn(v2, v3);
    }
}

// ---------------- launch ---------------------------------------------------
extern "C" void kernel_launch(void* const* d_in, const int* in_sizes, int n_in,
                              void* d_out, int out_size)
{
    const float* x     = (const float*)d_in[0];
    const float* Wqkv  = (const float*)d_in[1];
    const float* bqkv  = (const float*)d_in[2];
    const float* Wproj = (const float*)d_in[3];
    const float* bproj = (const float*)d_in[4];
    float* out = (float*)d_out;

    float *ct, *st;
    __half *xh, *wq, *wp, *yh, *qh, *kh, *vh;
    cudaGetSymbolAddress((void**)&ct, g_cost);
    cudaGetSymbolAddress((void**)&st, g_sint);
    cudaGetSymbolAddress((void**)&xh, g_xh);
    cudaGetSymbolAddress((void**)&wq, g_wq);
    cudaGetSymbolAddress((void**)&wp, g_wp);
    cudaGetSymbolAddress((void**)&yh, g_yh);
    cudaGetSymbolAddress((void**)&qh, g_qh);
    cudaGetSymbolAddress((void**)&kh, g_kh);
    cudaGetSymbolAddress((void**)&vh, g_vh);

    cudaFuncSetAttribute(tc_gemm_kernel<1>,
                         cudaFuncAttributeMaxDynamicSharedMemorySize, GS);
    cudaFuncSetAttribute(tc_gemm_kernel<0>,
                         cudaFuncAttributeMaxDynamicSharedMemorySize, GS);
    cudaFuncSetAttribute(attn_kernel,
                         cudaFuncAttributeMaxDynamicSharedMemorySize, AT_SMEM);

    quant_half_kernel<<<(ROWS * CC) / 256, 256>>>(x, xh, ROWS * CC);                   // 1
    transpose_half_kernel<<<dim3(CC / 32, N_QKV / 32), 256>>>(Wqkv, wq, CC, N_QKV);    // 2
    rope_table_kernel<<<(TT * 32) / 256, 256>>>(ct, st);                               // 3

    // 4) QKV GEMM (1-pass fp16) + bias + fused RoPE -> fp16 Q,K,V
    tc_gemm_kernel<1><<<dim3(N_QKV / 128, ROWS / 128), 256, GS>>>(
        xh, wq, bqkv, nullptr, qh, kh, vh, ct, st, N_QKV, CC);

    transpose_half_kernel<<<dim3(CC / 32, CC / 32), 256>>>(Wproj, wp, CC, CC);         // 5

    // 6) tensor-core causal flash attention -> fp16 Y
    attn_kernel<<<dim3(TT / 128, BB * NHH), 256, AT_SMEM>>>(qh, kh, vh, yh);

    // 7) output projection (1-pass fp16) + bias
    tc_gemm_kernel<0><<<dim3(CC / 128, ROWS / 128), 256, GS>>>(
        yh, wp, bproj, out, nullptr, nullptr, nullptr, ct, st, CC, CC);
}

// round 12
// speedup vs baseline: 2.1455x; 1.1478x over previous
#include <cuda_runtime.h>
#include <cuda_bf16.h>
#include <cuda_fp16.h>
#include <math.h>
#include <stdint.h>

// Problem constants
#define BB 4
#define TT 2048
#define CC 1024
#define NHH 16
#define HDD 64
#define ROWS (BB*TT)          // 8192
#define N_QKV (3*CC)          // 3072

// ---------------- scratch (device globals; no allocation) ----------------
__device__ __half g_xh[(size_t)ROWS * CC];            // x fp16
__device__ __half g_wq[(size_t)N_QKV * CC];           // Wqkv^T [N,K] fp16
__device__ __half g_wp[(size_t)CC * CC];              // Wproj^T [N,K] fp16
__device__ __half g_yh[(size_t)ROWS * CC];            // attn out (fp16)
__device__ float g_cost[(size_t)TT * 32];
__device__ float g_sint[(size_t)TT * 32];

__device__ __half g_qh[(size_t)BB * NHH * TT * HDD];  // [bh][t][d]
__device__ __half g_kh[(size_t)BB * NHH * TT * HDD];  // [bh][t][d]
__device__ __half g_vh[(size_t)BB * NHH * TT * HDD];  // [bh][t][d]

// ---------------- PTX helpers (arch-baseline only: no tcgen05) ------------
__device__ __forceinline__ uint32_t smem_u32(const void* p) {
    uint32_t a;
    asm("{ .reg .u64 t; cvta.to.shared.u64 t, %1; cvt.u32.u64 %0, t; }" : "=r"(a) : "l"(p));
    return a;
}
__device__ __forceinline__ void cp16(uint32_t saddr, const void* g) {
    asm volatile("cp.async.cg.shared.global [%0], [%1], 16;" :: "r"(saddr), "l"(g));
}
__device__ __forceinline__ void ldsm4(uint32_t* r, uint32_t addr) {
    asm volatile("ldmatrix.sync.aligned.m8n8.x4.shared.b16 {%0,%1,%2,%3}, [%4];"
                 : "=r"(r[0]), "=r"(r[1]), "=r"(r[2]), "=r"(r[3]) : "r"(addr));
}
__device__ __forceinline__ void ldsm4t(uint32_t* r, uint32_t addr) {
    asm volatile("ldmatrix.sync.aligned.m8n8.x4.trans.shared.b16 {%0,%1,%2,%3}, [%4];"
                 : "=r"(r[0]), "=r"(r[1]), "=r"(r[2]), "=r"(r[3]) : "r"(addr));
}
__device__ __forceinline__ void mma16816h(float* c, const uint32_t* a, const uint32_t* b) {
    asm volatile(
        "mma.sync.aligned.m16n8k16.row.col.f32.f16.f16.f32 "
        "{%0,%1,%2,%3}, {%4,%5,%6,%7}, {%8,%9}, {%0,%1,%2,%3};"
        : "+f"(c[0]), "+f"(c[1]), "+f"(c[2]), "+f"(c[3])
        : "r"(a[0]), "r"(a[1]), "r"(a[2]), "r"(a[3]), "r"(b[0]), "r"(b[1]));
}
__device__ __forceinline__ uint32_t packh2(float a, float b) {
    __half2 h = __floats2half2_rn(a, b);
    return *(uint32_t*)&h;
}

// ---------------- conversions ----------------------------------------------
__global__ __launch_bounds__(256) void quant_half_kernel(
    const float* __restrict__ in, __half* __restrict__ out, int n)
{
    int i = blockIdx.x * 256 + threadIdx.x;
    if (i >= n) return;
    out[i] = __float2half(in[i]);
}

// W[K,N] f32 -> [N,K] fp16 (transpose + quantize once)
__global__ __launch_bounds__(256) void transpose_half_kernel(
    const float* __restrict__ W, __half* __restrict__ Wt, int K, int N)
{
    __shared__ float tile[32][33];
    int k0 = blockIdx.x * 32, n0 = blockIdx.y * 32;
    int tx = threadIdx.x & 31, ty = threadIdx.x >> 5;   // 32x8
    #pragma unroll
    for (int r = 0; r < 4; r++)
        tile[ty + 8 * r][tx] = W[(size_t)(k0 + ty + 8 * r) * N + n0 + tx];
    __syncthreads();
    #pragma unroll
    for (int r = 0; r < 4; r++)
        Wt[(size_t)(n0 + ty + 8 * r) * K + k0 + tx] = __float2half(tile[tx][ty + 8 * r]);
}

// ---------------- RoPE table (mimic jax f32 computation) -------------------
__global__ __launch_bounds__(256) void rope_table_kernel(float* ct, float* st) {
    int idx = blockIdx.x * 256 + threadIdx.x;   // TT*32
    int t = idx >> 5, i = idx & 31;
    float invf = (float)exp(-(double)i / 32.0 * 9.210340371976184);
    float fr = (float)t * invf;
    double a = (double)fr;
    ct[idx] = (float)cos(a);
    st[idx] = (float)sin(a);
}

// ---------------- HMMA GEMM (mma.sync, 1-pass fp16, 2-stage, 2 CTAs/SM) ----
// C = A @ B^T ; A:[M,K] fp16, B:[N,K] fp16
// MODE 0: f32 out + bias.  MODE 1: fused QKV bias+RoPE -> fp16 Q,K,V.
#define TILE_B 16384
#define STB (2*TILE_B)          // A tile + B tile per stage (32 KB)
#define GS (2*STB)              // 2 stages = 64 KB -> 2 CTAs/SM

__device__ __forceinline__ void load_stage(
    uint32_t base, int kt, int tid, int row0, int col0, int K,
    const __half* __restrict__ Ah, const __half* __restrict__ Bq)
{
    int k0 = kt * 64;
    #pragma unroll
    for (int i = 0; i < 4; i++) {
        int lin = i * 256 + tid;
        int r = lin >> 3, c = lin & 7;
        uint32_t off = r * 128 + c * 16;
        uint32_t sw = off ^ ((off >> 3) & 0x70);
        cp16(base + sw, Ah + (size_t)(row0 + r) * K + k0 + c * 8);
        cp16(base + TILE_B + sw, Bq + (size_t)(col0 + r) * K + k0 + c * 8);
    }
    asm volatile("cp.async.commit_group;" ::: "memory");
}

template<int MODE>
__global__ __launch_bounds__(256, 2) void tc_gemm_kernel(
    const __half* __restrict__ Ah, const __half* __restrict__ Bq,
    const float* __restrict__ bias, float* __restrict__ C,
    __half* __restrict__ Qo, __half* __restrict__ Ko, __half* __restrict__ Vo,
    const float* __restrict__ ct, const float* __restrict__ st,
    int N, int K)
{
    extern __shared__ char smem[];
    uint32_t sb = smem_u32(smem);
    const int tid = threadIdx.x;
    const int wid = tid >> 5, lane = tid & 31;
    const int wr = (wid & 3) * 32;
    const int wc = (wid >> 2) * 64;
    const int col0 = blockIdx.x * 128;
    const int row0 = blockIdx.y * 128;
    const int NK = K >> 6;

    float acc[2][8][4];
    #pragma unroll
    for (int mi = 0; mi < 2; mi++)
        #pragma unroll
        for (int ni = 0; ni < 8; ni++)
            #pragma unroll
            for (int j = 0; j < 4; j++) acc[mi][ni][j] = 0.f;

    load_stage(sb, 0, tid, row0, col0, K, Ah, Bq);

    const int grp = lane >> 3, l8 = lane & 7;

    for (int kt = 0; kt < NK; kt++) {
        asm volatile("cp.async.wait_group 0;" ::: "memory");
        __syncthreads();
        // issue next load AFTER the sync (slot of kt-1: all warps finished it)
        if (kt + 1 < NK)
            load_stage(sb + ((kt + 1) & 1) * STB, kt + 1, tid, row0, col0, K, Ah, Bq);

        uint32_t sbase = sb + (kt & 1) * STB;
        uint32_t ahb = sbase, bbase = sbase + TILE_B;
        #pragma unroll
        for (int ks = 0; ks < 4; ks++) {
            // A fragments (2 ldsm4)
            uint32_t ah[2][4];
            #pragma unroll
            for (int mi = 0; mi < 2; mi++) {
                int row = wr + mi * 16 + (grp & 1) * 8 + l8;
                int chunk = ks * 2 + (grp >> 1);
                ldsm4(ah[mi], ahb + row * 128 + ((chunk ^ (row & 7)) << 4));
            }
            // N in two halves of 4 n8-tiles -> lower register liveness
            #pragma unroll
            for (int half = 0; half < 2; half++) {
                uint32_t b[4][2];
                #pragma unroll
                for (int nj = 0; nj < 2; nj++) {
                    int row = wc + (half * 2 + nj) * 16 + (grp >> 1) * 8 + l8;
                    int chunk = ks * 2 + (grp & 1);
                    uint32_t rr[4];
                    ldsm4(rr, bbase + row * 128 + ((chunk ^ (row & 7)) << 4));
                    b[2 * nj][0] = rr[0]; b[2 * nj][1] = rr[1];
                    b[2 * nj + 1][0] = rr[2]; b[2 * nj + 1][1] = rr[3];
                }
                #pragma unroll
                for (int mi = 0; mi < 2; mi++)
                    #pragma unroll
                    for (int ni = 0; ni < 4; ni++)
                        mma16816h(acc[mi][half * 4 + ni], ah[mi], b[ni]);
            }
        }
    }

    const int qr = lane >> 2, qc = (lane & 3) * 2;

    if (MODE == 0) {
        #pragma unroll
        for (int mi = 0; mi < 2; mi++) {
            #pragma unroll
            for (int ni = 0; ni < 8; ni++) {
                int r = row0 + wr + mi * 16 + qr;
                int c = col0 + wc + ni * 8 + qc;
                float b0 = bias[c], b1 = bias[c + 1];
                float2 o0 = make_float2(acc[mi][ni][0] + b0, acc[mi][ni][1] + b1);
                float2 o1 = make_float2(acc[mi][ni][2] + b0, acc[mi][ni][3] + b1);
                *(float2*)&C[(size_t)r * N + c] = o0;
                *(float2*)&C[(size_t)(r + 8) * N + c] = o1;
            }
        }
    } else {
        // fused QKV epilogue: bias + RoPE -> fp16
        int cb = col0 + wc;                 // 64-aligned head base
        int sec = cb >> 10;                 // 0=q, 1=k, 2=v
        int h = (cb & 1023) >> 6;
        #pragma unroll
        for (int mi = 0; mi < 2; mi++) {
            int r0 = row0 + wr + mi * 16 + qr;
            #pragma unroll
            for (int half = 0; half < 2; half++) {
                int r = r0 + half * 8;
                int e = half * 2;
                int t = r & (TT - 1);
                int b_ = r >> 11;
                size_t rowoff = ((size_t)((b_ * NHH + h) * TT + t)) * HDD;
                #pragma unroll
                for (int nj = 0; nj < 4; nj++) {
                    int d0 = nj * 8 + qc;            // even, < 32
                    int c0 = cb + d0;
                    float u00 = acc[mi][nj][e]     + bias[c0];
                    float u01 = acc[mi][nj][e + 1] + bias[c0 + 1];
                    float u10 = acc[mi][nj + 4][e]     + bias[c0 + 32];
                    float u11 = acc[mi][nj + 4][e + 1] + bias[c0 + 33];
                    if (sec < 2) {
                        float cA = ct[t * 32 + d0], cB = ct[t * 32 + d0 + 1];
                        float sA = st[t * 32 + d0], sB = st[t * 32 + d0 + 1];
                        float lo0 = u00 * cA - u10 * sA;
                        float lo1 = u01 * cB - u11 * sB;
                        float hi0 = u10 * cA + u00 * sA;
                        float hi1 = u11 * cB + u01 * sB;
                        __half* dst = (sec == 0) ? Qo : Ko;
                        *(__half2*)&dst[rowoff + d0]      = __floats2half2_rn(lo0, lo1);
                        *(__half2*)&dst[rowoff + d0 + 32] = __floats2half2_rn(hi0, hi1);
                    } else {
                        *(__half2*)&Vo[rowoff + d0]      = __floats2half2_rn(u00, u01);
                        *(__half2*)&Vo[rowoff + d0 + 32] = __floats2half2_rn(u10, u11);
                    }
                }
            }
        }
    }
}

// ---------------- Tensor-core flash attention (fp16, BM=128 BN=64) ---------
// 256 threads (8 warps x 16 q-rows), 2-stage KV pipeline, diag work skipping.
// V consumed straight from [t][d] layout via ldmatrix.trans.
#define AT_SMEM (16384 + 2*16384)   // Q + 2 stages of (K 8KB + V 8KB)

__device__ __forceinline__ void attn_load_kv(
    uint32_t dst, const __half* __restrict__ Kb, const __half* __restrict__ Vb,
    int ktbase, int tid)
{
    #pragma unroll
    for (int i = 0; i < 2; i++) {
        int lin = i * 256 + tid;
        int r = lin >> 3, c = lin & 7;
        uint32_t sw = r * 128 + ((c ^ (r & 7)) << 4);
        cp16(dst + sw, Kb + (size_t)(ktbase + r) * HDD + c * 8);
        cp16(dst + 8192 + sw, Vb + (size_t)(ktbase + r) * HDD + c * 8);
    }
    asm volatile("cp.async.commit_group;" ::: "memory");
}

__global__ __launch_bounds__(256, 2) void attn_kernel(
    const __half* __restrict__ Qg, const __half* __restrict__ Kg,
    const __half* __restrict__ Vg, __half* __restrict__ Yh)
{
    extern __shared__ char smem[];
    uint32_t sb = smem_u32(smem);
    uint32_t sQ = sb;
    uint32_t sKV = sb + 16384;

    const int tid = threadIdx.x;
    const int wid = tid >> 5, lane = tid & 31;
    const int grp = lane >> 3, l8 = lane & 7;
    const int qt = (int)gridDim.x - 1 - (int)blockIdx.x;   // longest first
    const int bh = blockIdx.y;
    const int q0 = qt * 128;
    const int nkt = 2 * qt + 2;

    const __half* Qb = Qg + ((size_t)bh * TT + q0) * HDD;
    const __half* Kb = Kg + (size_t)bh * TT * HDD;
    const __half* Vb = Vg + (size_t)bh * TT * HDD;

    // stage Q (group 0) then prefetch kv tile 0 (group 1)
    #pragma unroll
    for (int i = 0; i < 4; i++) {
        int lin = i * 256 + tid;
        int r = lin >> 3, c = lin & 7;
        cp16(sQ + r * 128 + ((c ^ (r & 7)) << 4), Qb + (size_t)r * HDD + c * 8);
    }
    asm volatile("cp.async.commit_group;" ::: "memory");
    attn_load_kv(sKV, Kb, Vb, 0, tid);

    asm volatile("cp.async.wait_group 1;" ::: "memory");   // Q ready
    __syncthreads();

    // preload Q fragments
    uint32_t qf[4][4];
    #pragma unroll
    for (int kc = 0; kc < 4; kc++) {
        int row = wid * 16 + (grp & 1) * 8 + l8;
        int ch = kc * 2 + (grp >> 1);
        ldsm4(qf[kc], sQ + row * 128 + ((ch ^ (row & 7)) << 4));
    }

    float m0 = -1e30f, m1 = -1e30f, l0 = 0.f, l1 = 0.f;
    float oacc[8][4];
    #pragma unroll
    for (int nj = 0; nj < 8; nj++)
        #pragma unroll
        for (int e = 0; e < 4; e++) oacc[nj][e] = 0.f;

    const int rquad = lane >> 2;       // 0..7
    const int cpair = (lane & 3) * 2;  // 0,2,4,6

    for (int kt = 0; kt < nkt; kt++) {
        int s = kt & 1;
        if (kt + 1 < nkt) {
            attn_load_kv(sKV + (s ^ 1) * 16384, Kb, Vb, (kt + 1) * 64, tid);
            asm volatile("cp.async.wait_group 1;" ::: "memory");
        } else {
            asm volatile("cp.async.wait_group 0;" ::: "memory");
        }
        __syncthreads();

        uint32_t sK = sKV + s * 16384;
        uint32_t sV = sK + 8192;

        // diagonal work skipping: nb = # of active 16-col blocks (of 4)
        int nb = 4;
        if (kt == nkt - 2)      nb = (wid + 1 < 4) ? wid + 1 : 4;
        else if (kt == nkt - 1) nb = (wid >= 4) ? ((wid - 3 < 4) ? wid - 3 : 4) : 0;

        // S = Q K^T
        float sacc[8][4];
        #pragma unroll
        for (int nj = 0; nj < 8; nj++)
            #pragma unroll
            for (int e = 0; e < 4; e++) sacc[nj][e] = 0.f;

        #pragma unroll
        for (int ks = 0; ks < 4; ks++) {
            #pragma unroll
            for (int nj = 0; nj < 4; nj++) {
                if (nj < nb) {
                    int row = nj * 16 + (grp >> 1) * 8 + l8;
                    int ch = ks * 2 + (grp & 1);
                    uint32_t rr[4];
                    ldsm4(rr, sK + row * 128 + ((ch ^ (row & 7)) << 4));
                    uint32_t b0[2] = {rr[0], rr[1]}, b1[2] = {rr[2], rr[3]};
                    mma16816h(sacc[2 * nj], qf[ks], b0);
                    mma16816h(sacc[2 * nj + 1], qf[ks], b1);
                }
            }
        }

        // scale + causal mask (only last two tiles touch the diagonal)
        const float sc = 0.125f;
        if (kt >= nkt - 2) {
            int row0g = q0 + wid * 16 + rquad;
            #pragma unroll
            for (int nj = 0; nj < 8; nj++) {
                int colg = kt * 64 + nj * 8 + cpair;
                #pragma unroll
                for (int e = 0; e < 4; e++) {
                    int cg = colg + (e & 1);
                    int rg = row0g + ((e >= 2) ? 8 : 0);
                    sacc[nj][e] = (cg <= rg) ? sacc[nj][e] * sc : -1e30f;
                }
            }
        } else {
            #pragma unroll
            for (int nj = 0; nj < 8; nj++)
                #pragma unroll
                for (int e = 0; e < 4; e++) sacc[nj][e] *= sc;
        }

        // online softmax (two rows per thread; 4-lane quad reductions)
        float rm0 = -1e30f, rm1 = -1e30f;
        #pragma unroll
        for (int nj = 0; nj < 8; nj++) {
            rm0 = fmaxf(rm0, fmaxf(sacc[nj][0], sacc[nj][1]));
            rm1 = fmaxf(rm1, fmaxf(sacc[nj][2], sacc[nj][3]));
        }
        rm0 = fmaxf(rm0, __shfl_xor_sync(0xffffffffu, rm0, 1));
        rm0 = fmaxf(rm0, __shfl_xor_sync(0xffffffffu, rm0, 2));
        rm1 = fmaxf(rm1, __shfl_xor_sync(0xffffffffu, rm1, 1));
        rm1 = fmaxf(rm1, __shfl_xor_sync(0xffffffffu, rm1, 2));

        float n0 = fmaxf(m0, rm0), n1 = fmaxf(m1, rm1);
        float a0 = __expf(m0 - n0), a1 = __expf(m1 - n1);
        float rs0 = 0.f, rs1 = 0.f;
        #pragma unroll
        for (int nj = 0; nj < 8; nj++) {
            sacc[nj][0] = __expf(sacc[nj][0] - n0);
            sacc[nj][1] = __expf(sacc[nj][1] - n0);
            sacc[nj][2] = __expf(sacc[nj][2] - n1);
            sacc[nj][3] = __expf(sacc[nj][3] - n1);
            rs0 += sacc[nj][0] + sacc[nj][1];
            rs1 += sacc[nj][2] + sacc[nj][3];
        }
        rs0 += __shfl_xor_sync(0xffffffffu, rs0, 1);
        rs0 += __shfl_xor_sync(0xffffffffu, rs0, 2);
        rs1 += __shfl_xor_sync(0xffffffffu, rs1, 1);
        rs1 += __shfl_xor_sync(0xffffffffu, rs1, 2);

        l0 = l0 * a0 + rs0;
        l1 = l1 * a1 + rs1;
        m0 = n0; m1 = n1;
        #pragma unroll
        for (int nj = 0; nj < 8; nj++) {
            oacc[nj][0] *= a0; oacc[nj][1] *= a0;
            oacc[nj][2] *= a1; oacc[nj][3] *= a1;
        }

        // pack P into A-operand fragments (registers only)
        uint32_t pf[4][4];
        #pragma unroll
        for (int kc = 0; kc < 4; kc++) {
            pf[kc][0] = packh2(sacc[2 * kc][0],     sacc[2 * kc][1]);
            pf[kc][1] = packh2(sacc[2 * kc][2],     sacc[2 * kc][3]);
            pf[kc][2] = packh2(sacc[2 * kc + 1][0], sacc[2 * kc + 1][1]);
            pf[kc][3] = packh2(sacc[2 * kc + 1][2], sacc[2 * kc + 1][3]);
        }

        // O += P @ V ; V is [t][d] in smem, B-fragments via ldmatrix.trans
        #pragma unroll
        for (int kc = 0; kc < 4; kc++) {
            if (kc < nb) {
                #pragma unroll
                for (int nj = 0; nj < 4; nj++) {
                    int trow = kc * 16 + (grp & 1) * 8 + l8;   // t rows
                    int ch = nj * 2 + (grp >> 1);              // d chunks
                    uint32_t rr[4];
                    ldsm4t(rr, sV + trow * 128 + ((ch ^ (trow & 7)) << 4));
                    uint32_t b0[2] = {rr[0], rr[1]}, b1[2] = {rr[2], rr[3]};
                    mma16816h(oacc[2 * nj], pf[kc], b0);
                    mma16816h(oacc[2 * nj + 1], pf[kc], b1);
                }
            }
        }
        __syncthreads();
    }

    // epilogue: normalize + fp16 store to [b,t,c]
    float i0 = 1.f / l0, i1 = 1.f / l1;
    int b_ = bh >> 4, h = bh & 15;
    int r0g = q0 + wid * 16 + rquad;
    #pragma unroll
    for (int nj = 0; nj < 8; nj++) {
        int c = h * 64 + nj * 8 + cpair;
        float v0 = oacc[nj][0] * i0, v1 = oacc[nj][1] * i0;
        float v2 = oacc[nj][2] * i1, v3 = oacc[nj][3] * i1;
        size_t o0 = (size_t)(b_ * TT + r0g) * CC + c;
        size_t o1 = (size_t)(b_ * TT + r0g + 8) * CC + c;
        *(__half2*)&Yh[o0] = __floats2half2_rn(v0, v1);
        *(__half2*)&Yh[o1] = __floats2half2_rn(v2, v3);
    }
}

// ---------------- launch ---------------------------------------------------
extern "C" void kernel_launch(void* const* d_in, const int* in_sizes, int n_in,
                              void* d_out, int out_size)
{
    const float* x     = (const float*)d_in[0];
    const float* Wqkv  = (const float*)d_in[1];
    const float* bqkv  = (const float*)d_in[2];
    const float* Wproj = (const float*)d_in[3];
    const float* bproj = (const float*)d_in[4];
    float* out = (float*)d_out;

    float *ct, *st;
    __half *xh, *wq, *wp, *yh, *qh, *kh, *vh;
    cudaGetSymbolAddress((void**)&ct, g_cost);
    cudaGetSymbolAddress((void**)&st, g_sint);
    cudaGetSymbolAddress((void**)&xh, g_xh);
    cudaGetSymbolAddress((void**)&wq, g_wq);
    cudaGetSymbolAddress((void**)&wp, g_wp);
    cudaGetSymbolAddress((void**)&yh, g_yh);
    cudaGetSymbolAddress((void**)&qh, g_qh);
    cudaGetSymbolAddress((void**)&kh, g_kh);
    cudaGetSymbolAddress((void**)&vh, g_vh);

    cudaFuncSetAttribute(tc_gemm_kernel<1>,
                         cudaFuncAttributeMaxDynamicSharedMemorySize, GS);
    cudaFuncSetAttribute(tc_gemm_kernel<0>,
                         cudaFuncAttributeMaxDynamicSharedMemorySize, GS);
    cudaFuncSetAttribute(attn_kernel,
                         cudaFuncAttributeMaxDynamicSharedMemorySize, AT_SMEM);

    quant_half_kernel<<<(ROWS * CC) / 256, 256>>>(x, xh, ROWS * CC);                   // 1
    transpose_half_kernel<<<dim3(CC / 32, N_QKV / 32), 256>>>(Wqkv, wq, CC, N_QKV);    // 2
    rope_table_kernel<<<(TT * 32) / 256, 256>>>(ct, st);                               // 3

    // 4) QKV GEMM (1-pass fp16, 2 CTAs/SM) + bias + fused RoPE -> fp16 Q,K,V
    tc_gemm_kernel<1><<<dim3(N_QKV / 128, ROWS / 128), 256, GS>>>(
        xh, wq, bqkv, nullptr, qh, kh, vh, ct, st, N_QKV, CC);

    transpose_half_kernel<<<dim3(CC / 32, CC / 32), 256>>>(Wproj, wp, CC, CC);         // 5

    // 6) tensor-core causal flash attention -> fp16 Y
    attn_kernel<<<dim3(TT / 128, BB * NHH), 256, AT_SMEM>>>(qh, kh, vh, yh);

    // 7) output projection (1-pass fp16) + bias
    tc_gemm_kernel<0><<<dim3(CC / 128, ROWS / 128), 256, GS>>>(
        yh, wp, bproj, out, nullptr, nullptr, nullptr, ct, st, CC, CC);
}

// round 13
// speedup vs baseline: 2.1809x; 1.0165x over previous
#include <cuda_runtime.h>
#include <cuda_bf16.h>
#include <cuda_fp16.h>
#include <math.h>
#include <stdint.h>

// Problem constants
#define BB 4
#define TT 2048
#define CC 1024
#define NHH 16
#define HDD 64
#define ROWS (BB*TT)          // 8192
#define N_QKV (3*CC)          // 3072

// ---------------- scratch (device globals; no allocation) ----------------
__device__ __half g_xh[(size_t)ROWS * CC];            // x fp16
__device__ __half g_wq[(size_t)N_QKV * CC];           // Wqkv^T [N,K] fp16
__device__ __half g_wp[(size_t)CC * CC];              // Wproj^T [N,K] fp16
__device__ __half g_yh[(size_t)ROWS * CC];            // attn out (fp16)
__device__ float g_cost[(size_t)TT * 32];
__device__ float g_sint[(size_t)TT * 32];

__device__ __half g_qh[(size_t)BB * NHH * TT * HDD];  // [bh][t][d] (pre-scaled)
__device__ __half g_kh[(size_t)BB * NHH * TT * HDD];  // [bh][t][d]
__device__ __half g_vh[(size_t)BB * NHH * TT * HDD];  // [bh][t][d]

// ---------------- PTX helpers (arch-baseline only: no tcgen05) ------------
__device__ __forceinline__ uint32_t smem_u32(const void* p) {
    uint32_t a;
    asm("{ .reg .u64 t; cvta.to.shared.u64 t, %1; cvt.u32.u64 %0, t; }" : "=r"(a) : "l"(p));
    return a;
}
__device__ __forceinline__ void cp16(uint32_t saddr, const void* g) {
    asm volatile("cp.async.cg.shared.global [%0], [%1], 16;" :: "r"(saddr), "l"(g));
}
__device__ __forceinline__ void ldsm4(uint32_t* r, uint32_t addr) {
    asm volatile("ldmatrix.sync.aligned.m8n8.x4.shared.b16 {%0,%1,%2,%3}, [%4];"
                 : "=r"(r[0]), "=r"(r[1]), "=r"(r[2]), "=r"(r[3]) : "r"(addr));
}
__device__ __forceinline__ void ldsm4t(uint32_t* r, uint32_t addr) {
    asm volatile("ldmatrix.sync.aligned.m8n8.x4.trans.shared.b16 {%0,%1,%2,%3}, [%4];"
                 : "=r"(r[0]), "=r"(r[1]), "=r"(r[2]), "=r"(r[3]) : "r"(addr));
}
__device__ __forceinline__ void mma16816h(float* c, const uint32_t* a, const uint32_t* b) {
    asm volatile(
        "mma.sync.aligned.m16n8k16.row.col.f32.f16.f16.f32 "
        "{%0,%1,%2,%3}, {%4,%5,%6,%7}, {%8,%9}, {%0,%1,%2,%3};"
        : "+f"(c[0]), "+f"(c[1]), "+f"(c[2]), "+f"(c[3])
        : "r"(a[0]), "r"(a[1]), "r"(a[2]), "r"(a[3]), "r"(b[0]), "r"(b[1]));
}
__device__ __forceinline__ uint32_t packh2(float a, float b) {
    __half2 h = __floats2half2_rn(a, b);
    return *(uint32_t*)&h;
}

// ---------------- conversions ----------------------------------------------
__global__ __launch_bounds__(256) void quant_half_kernel(
    const float* __restrict__ in, __half* __restrict__ out, int n)
{
    int i = blockIdx.x * 256 + threadIdx.x;
    if (i >= n) return;
    out[i] = __float2half(in[i]);
}

// W[K,N] f32 -> [N,K] fp16 (transpose + quantize once)
__global__ __launch_bounds__(256) void transpose_half_kernel(
    const float* __restrict__ W, __half* __restrict__ Wt, int K, int N)
{
    __shared__ float tile[32][33];
    int k0 = blockIdx.x * 32, n0 = blockIdx.y * 32;
    int tx = threadIdx.x & 31, ty = threadIdx.x >> 5;   // 32x8
    #pragma unroll
    for (int r = 0; r < 4; r++)
        tile[ty + 8 * r][tx] = W[(size_t)(k0 + ty + 8 * r) * N + n0 + tx];
    __syncthreads();
    #pragma unroll
    for (int r = 0; r < 4; r++)
        Wt[(size_t)(n0 + ty + 8 * r) * K + k0 + tx] = __float2half(tile[tx][ty + 8 * r]);
}

// ---------------- RoPE table (mimic jax f32 computation) -------------------
__global__ __launch_bounds__(256) void rope_table_kernel(float* ct, float* st) {
    int idx = blockIdx.x * 256 + threadIdx.x;   // TT*32
    int t = idx >> 5, i = idx & 31;
    float invf = (float)exp(-(double)i / 32.0 * 9.210340371976184);
    float fr = (float)t * invf;
    double a = (double)fr;
    ct[idx] = (float)cos(a);
    st[idx] = (float)sin(a);
}

// ---------------- HMMA GEMM (mma.sync, 1-pass fp16, 2-stage, 2 CTAs/SM) ----
// C = A @ B^T ; A:[M,K] fp16, B:[N,K] fp16
// MODE 0: f32 out + bias.  MODE 1: fused QKV bias+RoPE -> fp16 Q,K,V.
//         Q is pre-scaled by 1/sqrt(HD)*log2(e) for the base-2 softmax.
#define TILE_B 16384
#define STB (2*TILE_B)          // A tile + B tile per stage (32 KB)
#define GS (2*STB)              // 2 stages = 64 KB -> 2 CTAs/SM
#define SCQ 0.18033688f         // 0.125 * log2(e)

__device__ __forceinline__ void load_stage(
    uint32_t base, int kt, int tid, int row0, int col0, int K,
    const __half* __restrict__ Ah, const __half* __restrict__ Bq)
{
    int k0 = kt * 64;
    #pragma unroll
    for (int i = 0; i < 4; i++) {
        int lin = i * 256 + tid;
        int r = lin >> 3, c = lin & 7;
        uint32_t off = r * 128 + c * 16;
        uint32_t sw = off ^ ((off >> 3) & 0x70);
        cp16(base + sw, Ah + (size_t)(row0 + r) * K + k0 + c * 8);
        cp16(base + TILE_B + sw, Bq + (size_t)(col0 + r) * K + k0 + c * 8);
    }
    asm volatile("cp.async.commit_group;" ::: "memory");
}

template<int MODE>
__global__ __launch_bounds__(256, 2) void tc_gemm_kernel(
    const __half* __restrict__ Ah, const __half* __restrict__ Bq,
    const float* __restrict__ bias, float* __restrict__ C,
    __half* __restrict__ Qo, __half* __restrict__ Ko, __half* __restrict__ Vo,
    const float* __restrict__ ct, const float* __restrict__ st,
    int N, int K)
{
    extern __shared__ char smem[];
    uint32_t sb = smem_u32(smem);
    const int tid = threadIdx.x;
    const int wid = tid >> 5, lane = tid & 31;
    const int wr = (wid & 3) * 32;
    const int wc = (wid >> 2) * 64;
    const int col0 = blockIdx.x * 128;
    const int row0 = blockIdx.y * 128;
    const int NK = K >> 6;

    float acc[2][8][4];
    #pragma unroll
    for (int mi = 0; mi < 2; mi++)
        #pragma unroll
        for (int ni = 0; ni < 8; ni++)
            #pragma unroll
            for (int j = 0; j < 4; j++) acc[mi][ni][j] = 0.f;

    load_stage(sb, 0, tid, row0, col0, K, Ah, Bq);

    const int grp = lane >> 3, l8 = lane & 7;

    for (int kt = 0; kt < NK; kt++) {
        asm volatile("cp.async.wait_group 0;" ::: "memory");
        __syncthreads();
        if (kt + 1 < NK)
            load_stage(sb + ((kt + 1) & 1) * STB, kt + 1, tid, row0, col0, K, Ah, Bq);

        uint32_t sbase = sb + (kt & 1) * STB;
        uint32_t ahb = sbase, bbase = sbase + TILE_B;
        #pragma unroll
        for (int ks = 0; ks < 4; ks++) {
            uint32_t ah[2][4];
            #pragma unroll
            for (int mi = 0; mi < 2; mi++) {
                int row = wr + mi * 16 + (grp & 1) * 8 + l8;
                int chunk = ks * 2 + (grp >> 1);
                ldsm4(ah[mi], ahb + row * 128 + ((chunk ^ (row & 7)) << 4));
            }
            #pragma unroll
            for (int half = 0; half < 2; half++) {
                uint32_t b[4][2];
                #pragma unroll
                for (int nj = 0; nj < 2; nj++) {
                    int row = wc + (half * 2 + nj) * 16 + (grp >> 1) * 8 + l8;
                    int chunk = ks * 2 + (grp & 1);
                    uint32_t rr[4];
                    ldsm4(rr, bbase + row * 128 + ((chunk ^ (row & 7)) << 4));
                    b[2 * nj][0] = rr[0]; b[2 * nj][1] = rr[1];
                    b[2 * nj + 1][0] = rr[2]; b[2 * nj + 1][1] = rr[3];
                }
                #pragma unroll
                for (int mi = 0; mi < 2; mi++)
                    #pragma unroll
                    for (int ni = 0; ni < 4; ni++)
                        mma16816h(acc[mi][half * 4 + ni], ah[mi], b[ni]);
            }
        }
    }

    const int qr = lane >> 2, qc = (lane & 3) * 2;

    if (MODE == 0) {
        #pragma unroll
        for (int mi = 0; mi < 2; mi++) {
            #pragma unroll
            for (int ni = 0; ni < 8; ni++) {
                int r = row0 + wr + mi * 16 + qr;
                int c = col0 + wc + ni * 8 + qc;
                float b0 = bias[c], b1 = bias[c + 1];
                float2 o0 = make_float2(acc[mi][ni][0] + b0, acc[mi][ni][1] + b1);
                float2 o1 = make_float2(acc[mi][ni][2] + b0, acc[mi][ni][3] + b1);
                *(float2*)&C[(size_t)r * N + c] = o0;
                *(float2*)&C[(size_t)(r + 8) * N + c] = o1;
            }
        }
    } else {
        // fused QKV epilogue: bias + RoPE -> fp16 (Q pre-scaled by SCQ)
        int cb = col0 + wc;                 // 64-aligned head base
        int sec = cb >> 10;                 // 0=q, 1=k, 2=v
        int h = (cb & 1023) >> 6;
        #pragma unroll
        for (int mi = 0; mi < 2; mi++) {
            int r0 = row0 + wr + mi * 16 + qr;
            #pragma unroll
            for (int half = 0; half < 2; half++) {
                int r = r0 + half * 8;
                int e = half * 2;
                int t = r & (TT - 1);
                int b_ = r >> 11;
                size_t rowoff = ((size_t)((b_ * NHH + h) * TT + t)) * HDD;
                #pragma unroll
                for (int nj = 0; nj < 4; nj++) {
                    int d0 = nj * 8 + qc;            // even, < 32
                    int c0 = cb + d0;
                    float u00 = acc[mi][nj][e]     + bias[c0];
                    float u01 = acc[mi][nj][e + 1] + bias[c0 + 1];
                    float u10 = acc[mi][nj + 4][e]     + bias[c0 + 32];
                    float u11 = acc[mi][nj + 4][e + 1] + bias[c0 + 33];
                    if (sec < 2) {
                        float cA = ct[t * 32 + d0], cB = ct[t * 32 + d0 + 1];
                        float sA = st[t * 32 + d0], sB = st[t * 32 + d0 + 1];
                        float lo0 = u00 * cA - u10 * sA;
                        float lo1 = u01 * cB - u11 * sB;
                        float hi0 = u10 * cA + u00 * sA;
                        float hi1 = u11 * cB + u01 * sB;
                        if (sec == 0) {
                            lo0 *= SCQ; lo1 *= SCQ; hi0 *= SCQ; hi1 *= SCQ;
                        }
                        __half* dst = (sec == 0) ? Qo : Ko;
                        *(__half2*)&dst[rowoff + d0]      = __floats2half2_rn(lo0, lo1);
                        *(__half2*)&dst[rowoff + d0 + 32] = __floats2half2_rn(hi0, hi1);
                    } else {
                        *(__half2*)&Vo[rowoff + d0]      = __floats2half2_rn(u00, u01);
                        *(__half2*)&Vo[rowoff + d0 + 32] = __floats2half2_rn(u10, u11);
                    }
                }
            }
        }
    }
}

// ---------------- Tensor-core flash attention (fp16, BM=128 BN=64) ---------
// 256 threads (8 warps x 16 q-rows), 2-stage KV pipeline, 1 sync/iter,
// base-2 softmax (Q pre-scaled), diag work skipping, V via ldmatrix.trans.
#define AT_SMEM (16384 + 2*16384)   // Q + 2 stages of (K 8KB + V 8KB)

__device__ __forceinline__ void attn_load_kv(
    uint32_t dst, const __half* __restrict__ Kb, const __half* __restrict__ Vb,
    int ktbase, int tid)
{
    #pragma unroll
    for (int i = 0; i < 2; i++) {
        int lin = i * 256 + tid;
        int r = lin >> 3, c = lin & 7;
        uint32_t sw = r * 128 + ((c ^ (r & 7)) << 4);
        cp16(dst + sw, Kb + (size_t)(ktbase + r) * HDD + c * 8);
        cp16(dst + 8192 + sw, Vb + (size_t)(ktbase + r) * HDD + c * 8);
    }
    asm volatile("cp.async.commit_group;" ::: "memory");
}

__global__ __launch_bounds__(256, 2) void attn_kernel(
    const __half* __restrict__ Qg, const __half* __restrict__ Kg,
    const __half* __restrict__ Vg, __half* __restrict__ Yh)
{
    extern __shared__ char smem[];
    uint32_t sb = smem_u32(smem);
    uint32_t sQ = sb;
    uint32_t sKV = sb + 16384;

    const int tid = threadIdx.x;
    const int wid = tid >> 5, lane = tid & 31;
    const int grp = lane >> 3, l8 = lane & 7;
    const int qt = (int)gridDim.x - 1 - (int)blockIdx.x;   // longest first
    const int bh = blockIdx.y;
    const int q0 = qt * 128;
    const int nkt = 2 * qt + 2;

    const __half* Qb = Qg + ((size_t)bh * TT + q0) * HDD;
    const __half* Kb = Kg + (size_t)bh * TT * HDD;
    const __half* Vb = Vg + (size_t)bh * TT * HDD;

    // prologue: Q + kv tile 0 in ONE cp.async group
    #pragma unroll
    for (int i = 0; i < 4; i++) {
        int lin = i * 256 + tid;
        int r = lin >> 3, c = lin & 7;
        cp16(sQ + r * 128 + ((c ^ (r & 7)) << 4), Qb + (size_t)r * HDD + c * 8);
    }
    attn_load_kv(sKV, Kb, Vb, 0, tid);     // commits Q + KV0 together

    asm volatile("cp.async.wait_group 0;" ::: "memory");
    __syncthreads();

    // preload Q fragments
    uint32_t qf[4][4];
    #pragma unroll
    for (int kc = 0; kc < 4; kc++) {
        int row = wid * 16 + (grp & 1) * 8 + l8;
        int ch = kc * 2 + (grp >> 1);
        ldsm4(qf[kc], sQ + row * 128 + ((ch ^ (row & 7)) << 4));
    }

    float m0 = -1e30f, m1 = -1e30f, l0 = 0.f, l1 = 0.f;
    float oacc[8][4];
    #pragma unroll
    for (int nj = 0; nj < 8; nj++)
        #pragma unroll
        for (int e = 0; e < 4; e++) oacc[nj][e] = 0.f;

    const int rquad = lane >> 2;       // 0..7
    const int cpair = (lane & 3) * 2;  // 0,2,4,6

    for (int kt = 0; kt < nkt; kt++) {
        if (kt > 0) {
            asm volatile("cp.async.wait_group 0;" ::: "memory");
            __syncthreads();
        }
        // issue next load AFTER sync (targets slot last read in iter kt-1)
        if (kt + 1 < nkt)
            attn_load_kv(sKV + ((kt + 1) & 1) * 16384, Kb, Vb, (kt + 1) * 64, tid);

        uint32_t sK = sKV + (kt & 1) * 16384;
        uint32_t sV = sK + 8192;

        // diagonal work skipping: nb = # of active 16-col blocks (of 4)
        int nb = 4;
        if (kt == nkt - 2)      nb = (wid + 1 < 4) ? wid + 1 : 4;
        else if (kt == nkt - 1) nb = (wid >= 4) ? ((wid - 3 < 4) ? wid - 3 : 4) : 0;

        // S = Q K^T   (Q pre-scaled: S already in log2-softmax units)
        float sacc[8][4];
        #pragma unroll
        for (int nj = 0; nj < 8; nj++)
            #pragma unroll
            for (int e = 0; e < 4; e++) sacc[nj][e] = 0.f;

        #pragma unroll
        for (int ks = 0; ks < 4; ks++) {
            #pragma unroll
            for (int nj = 0; nj < 4; nj++) {
                if (nj < nb) {
                    int row = nj * 16 + (grp >> 1) * 8 + l8;
                    int ch = ks * 2 + (grp & 1);
                    uint32_t rr[4];
                    ldsm4(rr, sK + row * 128 + ((ch ^ (row & 7)) << 4));
                    uint32_t b0[2] = {rr[0], rr[1]}, b1[2] = {rr[2], rr[3]};
                    mma16816h(sacc[2 * nj], qf[ks], b0);
                    mma16816h(sacc[2 * nj + 1], qf[ks], b1);
                }
            }
        }

        // causal mask only (no scaling needed — folded into Q)
        if (kt >= nkt - 2) {
            int row0g = q0 + wid * 16 + rquad;
            #pragma unroll
            for (int nj = 0; nj < 8; nj++) {
                int colg = kt * 64 + nj * 8 + cpair;
                #pragma unroll
                for (int e = 0; e < 4; e++) {
                    int cg = colg + (e & 1);
                    int rg = row0g + ((e >= 2) ? 8 : 0);
                    if (cg > rg) sacc[nj][e] = -1e30f;
                }
            }
        }

        // online softmax in base-2 (two rows per thread; quad reductions)
        float rm0 = -1e30f, rm1 = -1e30f;
        #pragma unroll
        for (int nj = 0; nj < 8; nj++) {
            rm0 = fmaxf(rm0, fmaxf(sacc[nj][0], sacc[nj][1]));
            rm1 = fmaxf(rm1, fmaxf(sacc[nj][2], sacc[nj][3]));
        }
        rm0 = fmaxf(rm0, __shfl_xor_sync(0xffffffffu, rm0, 1));
        rm0 = fmaxf(rm0, __shfl_xor_sync(0xffffffffu, rm0, 2));
        rm1 = fmaxf(rm1, __shfl_xor_sync(0xffffffffu, rm1, 1));
        rm1 = fmaxf(rm1, __shfl_xor_sync(0xffffffffu, rm1, 2));

        float n0 = fmaxf(m0, rm0), n1 = fmaxf(m1, rm1);
        float a0 = exp2f(m0 - n0), a1 = exp2f(m1 - n1);
        float rs0 = 0.f, rs1 = 0.f;
        #pragma unroll
        for (int nj = 0; nj < 8; nj++) {
            sacc[nj][0] = exp2f(sacc[nj][0] - n0);
            sacc[nj][1] = exp2f(sacc[nj][1] - n0);
            sacc[nj][2] = exp2f(sacc[nj][2] - n1);
            sacc[nj][3] = exp2f(sacc[nj][3] - n1);
            rs0 += sacc[nj][0] + sacc[nj][1];
            rs1 += sacc[nj][2] + sacc[nj][3];
        }
        rs0 += __shfl_xor_sync(0xffffffffu, rs0, 1);
        rs0 += __shfl_xor_sync(0xffffffffu, rs0, 2);
        rs1 += __shfl_xor_sync(0xffffffffu, rs1, 1);
        rs1 += __shfl_xor_sync(0xffffffffu, rs1, 2);

        l0 = l0 * a0 + rs0;
        l1 = l1 * a1 + rs1;
        m0 = n0; m1 = n1;
        #pragma unroll
        for (int nj = 0; nj < 8; nj++) {
            oacc[nj][0] *= a0; oacc[nj][1] *= a0;
            oacc[nj][2] *= a1; oacc[nj][3] *= a1;
        }

        // pack P into A-operand fragments (registers only)
        uint32_t pf[4][4];
        #pragma unroll
        for (int kc = 0; kc < 4; kc++) {
            pf[kc][0] = packh2(sacc[2 * kc][0],     sacc[2 * kc][1]);
            pf[kc][1] = packh2(sacc[2 * kc][2],     sacc[2 * kc][3]);
            pf[kc][2] = packh2(sacc[2 * kc + 1][0], sacc[2 * kc + 1][1]);
            pf[kc][3] = packh2(sacc[2 * kc + 1][2], sacc[2 * kc + 1][3]);
        }

        // O += P @ V ; V is [t][d] in smem, B-fragments via ldmatrix.trans
        #pragma unroll
        for (int kc = 0; kc < 4; kc++) {
            if (kc < nb) {
                #pragma unroll
                for (int nj = 0; nj < 4; nj++) {
                    int trow = kc * 16 + (grp & 1) * 8 + l8;   // t rows
                    int ch = nj * 2 + (grp >> 1);              // d chunks
                    uint32_t rr[4];
                    ldsm4t(rr, sV + trow * 128 + ((ch ^ (trow & 7)) << 4));
                    uint32_t b0[2] = {rr[0], rr[1]}, b1[2] = {rr[2], rr[3]};
                    mma16816h(oacc[2 * nj], pf[kc], b0);
                    mma16816h(oacc[2 * nj + 1], pf[kc], b1);
                }
            }
        }
    }

    // epilogue: normalize + fp16 store to [b,t,c]
    float i0 = 1.f / l0, i1 = 1.f / l1;
    int b_ = bh >> 4, h = bh & 15;
    int r0g = q0 + wid * 16 + rquad;
    #pragma unroll
    for (int nj = 0; nj < 8; nj++) {
        int c = h * 64 + nj * 8 + cpair;
        float v0 = oacc[nj][0] * i0, v1 = oacc[nj][1] * i0;
        float v2 = oacc[nj][2] * i1, v3 = oacc[nj][3] * i1;
        size_t o0 = (size_t)(b_ * TT + r0g) * CC + c;
        size_t o1 = (size_t)(b_ * TT + r0g + 8) * CC + c;
        *(__half2*)&Yh[o0] = __floats2half2_rn(v0, v1);
        *(__half2*)&Yh[o1] = __floats2half2_rn(v2, v3);
    }
}

// ---------------- launch ---------------------------------------------------
extern "C" void kernel_launch(void* const* d_in, const int* in_sizes, int n_in,
                              void* d_out, int out_size)
{
    const float* x     = (const float*)d_in[0];
    const float* Wqkv  = (const float*)d_in[1];
    const float* bqkv  = (const float*)d_in[2];
    const float* Wproj = (const float*)d_in[3];
    const float* bproj = (const float*)d_in[4];
    float* out = (float*)d_out;

    float *ct, *st;
    __half *xh, *wq, *wp, *yh, *qh, *kh, *vh;
    cudaGetSymbolAddress((void**)&ct, g_cost);
    cudaGetSymbolAddress((void**)&st, g_sint);
    cudaGetSymbolAddress((void**)&xh, g_xh);
    cudaGetSymbolAddress((void**)&wq, g_wq);
    cudaGetSymbolAddress((void**)&wp, g_wp);
    cudaGetSymbolAddress((void**)&yh, g_yh);
    cudaGetSymbolAddress((void**)&qh, g_qh);
    cudaGetSymbolAddress((void**)&kh, g_kh);
    cudaGetSymbolAddress((void**)&vh, g_vh);

    cudaFuncSetAttribute(tc_gemm_kernel<1>,
                         cudaFuncAttributeMaxDynamicSharedMemorySize, GS);
    cudaFuncSetAttribute(tc_gemm_kernel<0>,
                         cudaFuncAttributeMaxDynamicSharedMemorySize, GS);
    cudaFuncSetAttribute(attn_kernel,
                         cudaFuncAttributeMaxDynamicSharedMemorySize, AT_SMEM);

    quant_half_kernel<<<(ROWS * CC) / 256, 256>>>(x, xh, ROWS * CC);                   // 1
    transpose_half_kernel<<<dim3(CC / 32, N_QKV / 32), 256>>>(Wqkv, wq, CC, N_QKV);    // 2
    rope_table_kernel<<<(TT * 32) / 256, 256>>>(ct, st);                               // 3

    // 4) QKV GEMM (1-pass fp16, 2 CTAs/SM) + bias + fused RoPE -> fp16 Q,K,V
    tc_gemm_kernel<1><<<dim3(N_QKV / 128, ROWS / 128), 256, GS>>>(
        xh, wq, bqkv, nullptr, qh, kh, vh, ct, st, N_QKV, CC);

    transpose_half_kernel<<<dim3(CC / 32, CC / 32), 256>>>(Wproj, wp, CC, CC);         // 5

    // 6) tensor-core causal flash attention (base-2 softmax) -> fp16 Y
    attn_kernel<<<dim3(TT / 128, BB * NHH), 256, AT_SMEM>>>(qh, kh, vh, yh);

    // 7) output projection (1-pass fp16) + bias
    tc_gemm_kernel<0><<<dim3(CC / 128, ROWS / 128), 256, GS>>>(
        yh, wp, bproj, out, nullptr, nullptr, nullptr, ct, st, CC, CC);
}

// round 14
// speedup vs baseline: 2.2061x; 1.0115x over previous
#include <cuda_runtime.h>
#include <cuda_bf16.h>
#include <cuda_fp16.h>
#include <math.h>
#include <stdint.h>

// Problem constants
#define BB 4
#define TT 2048
#define CC 1024
#define NHH 16
#define HDD 64
#define ROWS (BB*TT)          // 8192
#define N_QKV (3*CC)          // 3072

// ---------------- scratch (device globals; no allocation) ----------------
__device__ __half g_xh[(size_t)ROWS * CC];            // x fp16
__device__ __half g_wq[(size_t)N_QKV * CC];           // Wqkv^T [N,K] fp16
__device__ __half g_wp[(size_t)CC * CC];              // Wproj^T [N,K] fp16
__device__ __half g_yh[(size_t)ROWS * CC];            // attn out (fp16)
__device__ float g_cost[(size_t)TT * 32];
__device__ float g_sint[(size_t)TT * 32];

__device__ __half g_qh[(size_t)BB * NHH * TT * HDD];  // [bh][t][d] (pre-scaled)
__device__ __half g_kh[(size_t)BB * NHH * TT * HDD];  // [bh][t][d]
__device__ __half g_vh[(size_t)BB * NHH * TT * HDD];  // [bh][t][d]

// ---------------- PTX helpers (arch-baseline only: no tcgen05) ------------
__device__ __forceinline__ uint32_t smem_u32(const void* p) {
    uint32_t a;
    asm("{ .reg .u64 t; cvta.to.shared.u64 t, %1; cvt.u32.u64 %0, t; }" : "=r"(a) : "l"(p));
    return a;
}
__device__ __forceinline__ void cp16(uint32_t saddr, const void* g) {
    asm volatile("cp.async.cg.shared.global [%0], [%1], 16;" :: "r"(saddr), "l"(g));
}
__device__ __forceinline__ void ldsm4(uint32_t* r, uint32_t addr) {
    asm volatile("ldmatrix.sync.aligned.m8n8.x4.shared.b16 {%0,%1,%2,%3}, [%4];"
                 : "=r"(r[0]), "=r"(r[1]), "=r"(r[2]), "=r"(r[3]) : "r"(addr));
}
__device__ __forceinline__ void ldsm4t(uint32_t* r, uint32_t addr) {
    asm volatile("ldmatrix.sync.aligned.m8n8.x4.trans.shared.b16 {%0,%1,%2,%3}, [%4];"
                 : "=r"(r[0]), "=r"(r[1]), "=r"(r[2]), "=r"(r[3]) : "r"(addr));
}
__device__ __forceinline__ void mma16816h(float* c, const uint32_t* a, const uint32_t* b) {
    asm volatile(
        "mma.sync.aligned.m16n8k16.row.col.f32.f16.f16.f32 "
        "{%0,%1,%2,%3}, {%4,%5,%6,%7}, {%8,%9}, {%0,%1,%2,%3};"
        : "+f"(c[0]), "+f"(c[1]), "+f"(c[2]), "+f"(c[3])
        : "r"(a[0]), "r"(a[1]), "r"(a[2]), "r"(a[3]), "r"(b[0]), "r"(b[1]));
}
__device__ __forceinline__ uint32_t packh2(float a, float b) {
    __half2 h = __floats2half2_rn(a, b);
    return *(uint32_t*)&h;
}
__device__ __forceinline__ uint32_t ex2h2(uint32_t p) {
    asm("ex2.approx.f16x2 %0, %0;" : "+r"(p));
    return p;
}

// ---------------- conversions ----------------------------------------------
__global__ __launch_bounds__(256) void quant_half_kernel(
    const float* __restrict__ in, __half* __restrict__ out, int n)
{
    int i = blockIdx.x * 256 + threadIdx.x;
    if (i >= n) return;
    out[i] = __float2half(in[i]);
}

// W[K,N] f32 -> [N,K] fp16 (transpose + quantize once)
__global__ __launch_bounds__(256) void transpose_half_kernel(
    const float* __restrict__ W, __half* __restrict__ Wt, int K, int N)
{
    __shared__ float tile[32][33];
    int k0 = blockIdx.x * 32, n0 = blockIdx.y * 32;
    int tx = threadIdx.x & 31, ty = threadIdx.x >> 5;   // 32x8
    #pragma unroll
    for (int r = 0; r < 4; r++)
        tile[ty + 8 * r][tx] = W[(size_t)(k0 + ty + 8 * r) * N + n0 + tx];
    __syncthreads();
    #pragma unroll
    for (int r = 0; r < 4; r++)
        Wt[(size_t)(n0 + ty + 8 * r) * K + k0 + tx] = __float2half(tile[tx][ty + 8 * r]);
}

// ---------------- RoPE table (mimic jax f32 computation) -------------------
__global__ __launch_bounds__(256) void rope_table_kernel(float* ct, float* st) {
    int idx = blockIdx.x * 256 + threadIdx.x;   // TT*32
    int t = idx >> 5, i = idx & 31;
    float invf = (float)exp(-(double)i / 32.0 * 9.210340371976184);
    float fr = (float)t * invf;
    double a = (double)fr;
    ct[idx] = (float)cos(a);
    st[idx] = (float)sin(a);
}

// ---------------- HMMA GEMM (1-pass fp16, 3-stage, 2 CTAs/SM) --------------
// C = A @ B^T ; A:[M,K] fp16, B:[N,K] fp16
// MODE 0: f32 out + bias.  MODE 1: fused QKV bias+RoPE -> fp16 Q,K,V.
//         Q is pre-scaled by 1/sqrt(HD)*log2(e) for the base-2 softmax.
#define TILE_B 16384
#define STB (2*TILE_B)          // A tile + B tile per stage (32 KB)
#define GS (3*STB)              // 3 stages = 96 KB -> still 2 CTAs/SM
#define SCQ 0.18033688f         // 0.125 * log2(e)

__device__ __forceinline__ void load_stage(
    uint32_t base, int kt, int tid, int row0, int col0, int K,
    const __half* __restrict__ Ah, const __half* __restrict__ Bq)
{
    int k0 = kt * 64;
    #pragma unroll
    for (int i = 0; i < 4; i++) {
        int lin = i * 256 + tid;
        int r = lin >> 3, c = lin & 7;
        uint32_t off = r * 128 + c * 16;
        uint32_t sw = off ^ ((off >> 3) & 0x70);
        cp16(base + sw, Ah + (size_t)(row0 + r) * K + k0 + c * 8);
        cp16(base + TILE_B + sw, Bq + (size_t)(col0 + r) * K + k0 + c * 8);
    }
    asm volatile("cp.async.commit_group;" ::: "memory");
}

template<int MODE>
__global__ __launch_bounds__(256, 2) void tc_gemm_kernel(
    const __half* __restrict__ Ah, const __half* __restrict__ Bq,
    const float* __restrict__ bias, float* __restrict__ C,
    __half* __restrict__ Qo, __half* __restrict__ Ko, __half* __restrict__ Vo,
    const float* __restrict__ ct, const float* __restrict__ st,
    int N, int K)
{
    extern __shared__ char smem[];
    uint32_t sb = smem_u32(smem);
    const int tid = threadIdx.x;
    const int wid = tid >> 5, lane = tid & 31;
    const int wr = (wid & 3) * 32;
    const int wc = (wid >> 2) * 64;
    const int col0 = blockIdx.x * 128;
    const int row0 = blockIdx.y * 128;
    const int NK = K >> 6;

    float acc[2][8][4];
    #pragma unroll
    for (int mi = 0; mi < 2; mi++)
        #pragma unroll
        for (int ni = 0; ni < 8; ni++)
            #pragma unroll
            for (int j = 0; j < 4; j++) acc[mi][ni][j] = 0.f;

    load_stage(sb, 0, tid, row0, col0, K, Ah, Bq);
    if (NK > 1) load_stage(sb + STB, 1, tid, row0, col0, K, Ah, Bq);

    const int grp = lane >> 3, l8 = lane & 7;

    for (int kt = 0; kt < NK; kt++) {
        if (kt + 1 < NK) { asm volatile("cp.async.wait_group 1;" ::: "memory"); }
        else             { asm volatile("cp.async.wait_group 0;" ::: "memory"); }
        __syncthreads();
        // issue load for kt+2 (slot of kt-1; all warps finished it before sync)
        if (kt + 2 < NK)
            load_stage(sb + ((kt + 2) % 3) * STB, kt + 2, tid, row0, col0, K, Ah, Bq);

        uint32_t sbase = sb + (kt % 3) * STB;
        uint32_t ahb = sbase, bbase = sbase + TILE_B;
        #pragma unroll
        for (int ks = 0; ks < 4; ks++) {
            uint32_t ah[2][4];
            #pragma unroll
            for (int mi = 0; mi < 2; mi++) {
                int row = wr + mi * 16 + (grp & 1) * 8 + l8;
                int chunk = ks * 2 + (grp >> 1);
                ldsm4(ah[mi], ahb + row * 128 + ((chunk ^ (row & 7)) << 4));
            }
            #pragma unroll
            for (int half = 0; half < 2; half++) {
                uint32_t b[4][2];
                #pragma unroll
                for (int nj = 0; nj < 2; nj++) {
                    int row = wc + (half * 2 + nj) * 16 + (grp >> 1) * 8 + l8;
                    int chunk = ks * 2 + (grp & 1);
                    uint32_t rr[4];
                    ldsm4(rr, bbase + row * 128 + ((chunk ^ (row & 7)) << 4));
                    b[2 * nj][0] = rr[0]; b[2 * nj][1] = rr[1];
                    b[2 * nj + 1][0] = rr[2]; b[2 * nj + 1][1] = rr[3];
                }
                #pragma unroll
                for (int mi = 0; mi < 2; mi++)
                    #pragma unroll
                    for (int ni = 0; ni < 4; ni++)
                        mma16816h(acc[mi][half * 4 + ni], ah[mi], b[ni]);
            }
        }
    }

    const int qr = lane >> 2, qc = (lane & 3) * 2;

    if (MODE == 0) {
        #pragma unroll
        for (int mi = 0; mi < 2; mi++) {
            #pragma unroll
            for (int ni = 0; ni < 8; ni++) {
                int r = row0 + wr + mi * 16 + qr;
                int c = col0 + wc + ni * 8 + qc;
                float b0 = bias[c], b1 = bias[c + 1];
                float2 o0 = make_float2(acc[mi][ni][0] + b0, acc[mi][ni][1] + b1);
                float2 o1 = make_float2(acc[mi][ni][2] + b0, acc[mi][ni][3] + b1);
                *(float2*)&C[(size_t)r * N + c] = o0;
                *(float2*)&C[(size_t)(r + 8) * N + c] = o1;
            }
        }
    } else {
        // fused QKV epilogue: bias + RoPE -> fp16 (Q pre-scaled by SCQ)
        int cb = col0 + wc;                 // 64-aligned head base
        int sec = cb >> 10;                 // 0=q, 1=k, 2=v
        int h = (cb & 1023) >> 6;
        #pragma unroll
        for (int mi = 0; mi < 2; mi++) {
            int r0 = row0 + wr + mi * 16 + qr;
            #pragma unroll
            for (int half = 0; half < 2; half++) {
                int r = r0 + half * 8;
                int e = half * 2;
                int t = r & (TT - 1);
                int b_ = r >> 11;
                size_t rowoff = ((size_t)((b_ * NHH + h) * TT + t)) * HDD;
                #pragma unroll
                for (int nj = 0; nj < 4; nj++) {
                    int d0 = nj * 8 + qc;            // even, < 32
                    int c0 = cb + d0;
                    float u00 = acc[mi][nj][e]     + bias[c0];
                    float u01 = acc[mi][nj][e + 1] + bias[c0 + 1];
                    float u10 = acc[mi][nj + 4][e]     + bias[c0 + 32];
                    float u11 = acc[mi][nj + 4][e + 1] + bias[c0 + 33];
                    if (sec < 2) {
                        float cA = ct[t * 32 + d0], cB = ct[t * 32 + d0 + 1];
                        float sA = st[t * 32 + d0], sB = st[t * 32 + d0 + 1];
                        float lo0 = u00 * cA - u10 * sA;
                        float lo1 = u01 * cB - u11 * sB;
                        float hi0 = u10 * cA + u00 * sA;
                        float hi1 = u11 * cB + u01 * sB;
                        if (sec == 0) {
                            lo0 *= SCQ; lo1 *= SCQ; hi0 *= SCQ; hi1 *= SCQ;
                        }
                        __half* dst = (sec == 0) ? Qo : Ko;
                        *(__half2*)&dst[rowoff + d0]      = __floats2half2_rn(lo0, lo1);
                        *(__half2*)&dst[rowoff + d0 + 32] = __floats2half2_rn(hi0, hi1);
                    } else {
                        *(__half2*)&Vo[rowoff + d0]      = __floats2half2_rn(u00, u01);
                        *(__half2*)&Vo[rowoff + d0 + 32] = __floats2half2_rn(u10, u11);
                    }
                }
            }
        }
    }
}

// ---------------- Tensor-core flash attention (fp16, BM=128 BN=64) ---------
// 256 threads (8 warps x 16 q-rows), 2-stage KV pipeline, 1 sync/iter,
// base-2 softmax via ex2.approx.f16x2 (P lands pre-packed as A-fragments),
// diag work skipping, V via ldmatrix.trans.
#define AT_SMEM (16384 + 2*16384)   // Q + 2 stages of (K 8KB + V 8KB)

__device__ __forceinline__ void attn_load_kv(
    uint32_t dst, const __half* __restrict__ Kb, const __half* __restrict__ Vb,
    int ktbase, int tid)
{
    #pragma unroll
    for (int i = 0; i < 2; i++) {
        int lin = i * 256 + tid;
        int r = lin >> 3, c = lin & 7;
        uint32_t sw = r * 128 + ((c ^ (r & 7)) << 4);
        cp16(dst + sw, Kb + (size_t)(ktbase + r) * HDD + c * 8);
        cp16(dst + 8192 + sw, Vb + (size_t)(ktbase + r) * HDD + c * 8);
    }
    asm volatile("cp.async.commit_group;" ::: "memory");
}

__global__ __launch_bounds__(256, 2) void attn_kernel(
    const __half* __restrict__ Qg, const __half* __restrict__ Kg,
    const __half* __restrict__ Vg, __half* __restrict__ Yh)
{
    extern __shared__ char smem[];
    uint32_t sb = smem_u32(smem);
    uint32_t sQ = sb;
    uint32_t sKV = sb + 16384;

    const int tid = threadIdx.x;
    const int wid = tid >> 5, lane = tid & 31;
    const int grp = lane >> 3, l8 = lane & 7;
    const int qt = (int)gridDim.x - 1 - (int)blockIdx.x;   // longest first
    const int bh = blockIdx.y;
    const int q0 = qt * 128;
    const int nkt = 2 * qt + 2;

    const __half* Qb = Qg + ((size_t)bh * TT + q0) * HDD;
    const __half* Kb = Kg + (size_t)bh * TT * HDD;
    const __half* Vb = Vg + (size_t)bh * TT * HDD;

    // prologue: Q + kv tile 0 in ONE cp.async group
    #pragma unroll
    for (int i = 0; i < 4; i++) {
        int lin = i * 256 + tid;
        int r = lin >> 3, c = lin & 7;
        cp16(sQ + r * 128 + ((c ^ (r & 7)) << 4), Qb + (size_t)r * HDD + c * 8);
    }
    attn_load_kv(sKV, Kb, Vb, 0, tid);     // commits Q + KV0 together

    asm volatile("cp.async.wait_group 0;" ::: "memory");
    __syncthreads();

    // preload Q fragments
    uint32_t qf[4][4];
    #pragma unroll
    for (int kc = 0; kc < 4; kc++) {
        int row = wid * 16 + (grp & 1) * 8 + l8;
        int ch = kc * 2 + (grp >> 1);
        ldsm4(qf[kc], sQ + row * 128 + ((ch ^ (row & 7)) << 4));
    }

    float m0 = -1e30f, m1 = -1e30f, l0 = 0.f, l1 = 0.f;
    float oacc[8][4];
    #pragma unroll
    for (int nj = 0; nj < 8; nj++)
        #pragma unroll
        for (int e = 0; e < 4; e++) oacc[nj][e] = 0.f;

    const int rquad = lane >> 2;       // 0..7
    const int cpair = (lane & 3) * 2;  // 0,2,4,6

    for (int kt = 0; kt < nkt; kt++) {
        if (kt > 0) {
            asm volatile("cp.async.wait_group 0;" ::: "memory");
            __syncthreads();
        }
        if (kt + 1 < nkt)
            attn_load_kv(sKV + ((kt + 1) & 1) * 16384, Kb, Vb, (kt + 1) * 64, tid);

        uint32_t sK = sKV + (kt & 1) * 16384;
        uint32_t sV = sK + 8192;

        // diagonal work skipping: nb = # of active 16-col blocks (of 4)
        int nb = 4;
        if (kt == nkt - 2)      nb = (wid + 1 < 4) ? wid + 1 : 4;
        else if (kt == nkt - 1) nb = (wid >= 4) ? ((wid - 3 < 4) ? wid - 3 : 4) : 0;

        // S = Q K^T   (Q pre-scaled: S already in log2-softmax units)
        float sacc[8][4];
        #pragma unroll
        for (int nj = 0; nj < 8; nj++)
            #pragma unroll
            for (int e = 0; e < 4; e++) sacc[nj][e] = 0.f;

        #pragma unroll
        for (int ks = 0; ks < 4; ks++) {
            #pragma unroll
            for (int nj = 0; nj < 4; nj++) {
                if (nj < nb) {
                    int row = nj * 16 + (grp >> 1) * 8 + l8;
                    int ch = ks * 2 + (grp & 1);
                    uint32_t rr[4];
                    ldsm4(rr, sK + row * 128 + ((ch ^ (row & 7)) << 4));
                    uint32_t b0[2] = {rr[0], rr[1]}, b1[2] = {rr[2], rr[3]};
                    mma16816h(sacc[2 * nj], qf[ks], b0);
                    mma16816h(sacc[2 * nj + 1], qf[ks], b1);
                }
            }
        }

        // causal mask only (scaling folded into Q)
        if (kt >= nkt - 2) {
            int row0g = q0 + wid * 16 + rquad;
            #pragma unroll
            for (int nj = 0; nj < 8; nj++) {
                int colg = kt * 64 + nj * 8 + cpair;
                #pragma unroll
                for (int e = 0; e < 4; e++) {
                    int cg = colg + (e & 1);
                    int rg = row0g + ((e >= 2) ? 8 : 0);
                    if (cg > rg) sacc[nj][e] = -1e30f;
                }
            }
        }

        // online softmax in base-2 (two rows per thread; quad reductions)
        float rm0 = -1e30f, rm1 = -1e30f;
        #pragma unroll
        for (int nj = 0; nj < 8; nj++) {
            rm0 = fmaxf(rm0, fmaxf(sacc[nj][0], sacc[nj][1]));
            rm1 = fmaxf(rm1, fmaxf(sacc[nj][2], sacc[nj][3]));
        }
        rm0 = fmaxf(rm0, __shfl_xor_sync(0xffffffffu, rm0, 1));
        rm0 = fmaxf(rm0, __shfl_xor_sync(0xffffffffu, rm0, 2));
        rm1 = fmaxf(rm1, __shfl_xor_sync(0xffffffffu, rm1, 1));
        rm1 = fmaxf(rm1, __shfl_xor_sync(0xffffffffu, rm1, 2));

        float n0 = fmaxf(m0, rm0), n1 = fmaxf(m1, rm1);
        float a0 = exp2f(m0 - n0), a1 = exp2f(m1 - n1);

        // P = 2^(S-max) computed in fp16x2, landing pre-packed as A-fragments
        uint32_t pf[4][4];
        float rs0 = 0.f, rs1 = 0.f;
        #pragma unroll
        for (int nj = 0; nj < 8; nj++) {
            uint32_t p01 = ex2h2(packh2(sacc[nj][0] - n0, sacc[nj][1] - n0));
            uint32_t p23 = ex2h2(packh2(sacc[nj][2] - n1, sacc[nj][3] - n1));
            float2 f01 = __half22float2(*(__half2*)&p01);
            float2 f23 = __half22float2(*(__half2*)&p23);
            rs0 += f01.x + f01.y;
            rs1 += f23.x + f23.y;
            pf[nj >> 1][(nj & 1) * 2 + 0] = p01;
            pf[nj >> 1][(nj & 1) * 2 + 1] = p23;
        }
        rs0 += __shfl_xor_sync(0xffffffffu, rs0, 1);
        rs0 += __shfl_xor_sync(0xffffffffu, rs0, 2);
        rs1 += __shfl_xor_sync(0xffffffffu, rs1, 1);
        rs1 += __shfl_xor_sync(0xffffffffu, rs1, 2);

        l0 = l0 * a0 + rs0;
        l1 = l1 * a1 + rs1;
        m0 = n0; m1 = n1;
        #pragma unroll
        for (int nj = 0; nj < 8; nj++) {
            oacc[nj][0] *= a0; oacc[nj][1] *= a0;
            oacc[nj][2] *= a1; oacc[nj][3] *= a1;
        }

        // O += P @ V ; V is [t][d] in smem, B-fragments via ldmatrix.trans
        #pragma unroll
        for (int kc = 0; kc < 4; kc++) {
            if (kc < nb) {
                #pragma unroll
                for (int nj = 0; nj < 4; nj++) {
                    int trow = kc * 16 + (grp & 1) * 8 + l8;   // t rows
                    int ch = nj * 2 + (grp >> 1);              // d chunks
                    uint32_t rr[4];
                    ldsm4t(rr, sV + trow * 128 + ((ch ^ (trow & 7)) << 4));
                    uint32_t b0[2] = {rr[0], rr[1]}, b1[2] = {rr[2], rr[3]};
                    mma16816h(oacc[2 * nj], pf[kc], b0);
                    mma16816h(oacc[2 * nj + 1], pf[kc], b1);
                }
            }
        }
    }

    // epilogue: normalize + fp16 store to [b,t,c]
    float i0 = 1.f / l0, i1 = 1.f / l1;
    int b_ = bh >> 4, h = bh & 15;
    int r0g = q0 + wid * 16 + rquad;
    #pragma unroll
    for (int nj = 0; nj < 8; nj++) {
        int c = h * 64 + nj * 8 + cpair;
        float v0 = oacc[nj][0] * i0, v1 = oacc[nj][1] * i0;
        float v2 = oacc[nj][2] * i1, v3 = oacc[nj][3] * i1;
        size_t o0 = (size_t)(b_ * TT + r0g) * CC + c;
        size_t o1 = (size_t)(b_ * TT + r0g + 8) * CC + c;
        *(__half2*)&Yh[o0] = __floats2half2_rn(v0, v1);
        *(__half2*)&Yh[o1] = __floats2half2_rn(v2, v3);
    }
}

// ---------------- launch ---------------------------------------------------
extern "C" void kernel_launch(void* const* d_in, const int* in_sizes, int n_in,
                              void* d_out, int out_size)
{
    const float* x     = (const float*)d_in[0];
    const float* Wqkv  = (const float*)d_in[1];
    const float* bqkv  = (const float*)d_in[2];
    const float* Wproj = (const float*)d_in[3];
    const float* bproj = (const float*)d_in[4];
    float* out = (float*)d_out;

    float *ct, *st;
    __half *xh, *wq, *wp, *yh, *qh, *kh, *vh;
    cudaGetSymbolAddress((void**)&ct, g_cost);
    cudaGetSymbolAddress((void**)&st, g_sint);
    cudaGetSymbolAddress((void**)&xh, g_xh);
    cudaGetSymbolAddress((void**)&wq, g_wq);
    cudaGetSymbolAddress((void**)&wp, g_wp);
    cudaGetSymbolAddress((void**)&yh, g_yh);
    cudaGetSymbolAddress((void**)&qh, g_qh);
    cudaGetSymbolAddress((void**)&kh, g_kh);
    cudaGetSymbolAddress((void**)&vh, g_vh);

    cudaFuncSetAttribute(tc_gemm_kernel<1>,
                         cudaFuncAttributeMaxDynamicSharedMemorySize, GS);
    cudaFuncSetAttribute(tc_gemm_kernel<0>,
                         cudaFuncAttributeMaxDynamicSharedMemorySize, GS);
    cudaFuncSetAttribute(attn_kernel,
                         cudaFuncAttributeMaxDynamicSharedMemorySize, AT_SMEM);

    quant_half_kernel<<<(ROWS * CC) / 256, 256>>>(x, xh, ROWS * CC);                   // 1
    transpose_half_kernel<<<dim3(CC / 32, N_QKV / 32), 256>>>(Wqkv, wq, CC, N_QKV);    // 2
    rope_table_kernel<<<(TT * 32) / 256, 256>>>(ct, st);                               // 3

    // 4) QKV GEMM (1-pass fp16, 3-stage, 2 CTAs/SM) + bias + RoPE -> Q,K,V
    tc_gemm_kernel<1><<<dim3(N_QKV / 128, ROWS / 128), 256, GS>>>(
        xh, wq, bqkv, nullptr, qh, kh, vh, ct, st, N_QKV, CC);

    transpose_half_kernel<<<dim3(CC / 32, CC / 32), 256>>>(Wproj, wp, CC, CC);         // 5

    // 6) tensor-core causal flash attention (f16x2 base-2 softmax) -> fp16 Y
    attn_kernel<<<dim3(TT / 128, BB * NHH), 256, AT_SMEM>>>(qh, kh, vh, yh);

    // 7) output projection (1-pass fp16) + bias
    tc_gemm_kernel<0><<<dim3(CC / 128, ROWS / 128), 256, GS>>>(
        yh, wp, bproj, out, nullptr, nullptr, nullptr, ct, st, CC, CC);
}

// round 15
// speedup vs baseline: 2.2516x; 1.0206x over previous
#include <cuda_runtime.h>
#include <cuda_bf16.h>
#include <cuda_fp16.h>
#include <math.h>
#include <stdint.h>

// Problem constants
#define BB 4
#define TT 2048
#define CC 1024
#define NHH 16
#define HDD 64
#define ROWS (BB*TT)          // 8192
#define N_QKV (3*CC)          // 3072

// ---------------- scratch (device globals; no allocation) ----------------
__device__ __half g_xh[(size_t)ROWS * CC];            // x fp16
__device__ __half g_wq[(size_t)N_QKV * CC];           // Wqkv^T [N,K] fp16
__device__ __half g_wp[(size_t)CC * CC];              // Wproj^T [N,K] fp16
__device__ __half g_yh[(size_t)ROWS * CC];            // attn out (fp16)
__device__ float g_cost[(size_t)TT * 32];
__device__ float g_sint[(size_t)TT * 32];

__device__ __half g_qh[(size_t)BB * NHH * TT * HDD];  // [bh][t][d] (pre-scaled)
__device__ __half g_kh[(size_t)BB * NHH * TT * HDD];  // [bh][t][d]
__device__ __half g_vh[(size_t)BB * NHH * TT * HDD];  // [bh][t][d]

// ---------------- PTX helpers (arch-baseline only: no tcgen05) ------------
__device__ __forceinline__ uint32_t smem_u32(const void* p) {
    uint32_t a;
    asm("{ .reg .u64 t; cvta.to.shared.u64 t, %1; cvt.u32.u64 %0, t; }" : "=r"(a) : "l"(p));
    return a;
}
__device__ __forceinline__ void cp16(uint32_t saddr, const void* g) {
    asm volatile("cp.async.cg.shared.global [%0], [%1], 16;" :: "r"(saddr), "l"(g));
}
__device__ __forceinline__ void ldsm4(uint32_t* r, uint32_t addr) {
    asm volatile("ldmatrix.sync.aligned.m8n8.x4.shared.b16 {%0,%1,%2,%3}, [%4];"
                 : "=r"(r[0]), "=r"(r[1]), "=r"(r[2]), "=r"(r[3]) : "r"(addr));
}
__device__ __forceinline__ void ldsm4t(uint32_t* r, uint32_t addr) {
    asm volatile("ldmatrix.sync.aligned.m8n8.x4.trans.shared.b16 {%0,%1,%2,%3}, [%4];"
                 : "=r"(r[0]), "=r"(r[1]), "=r"(r[2]), "=r"(r[3]) : "r"(addr));
}
__device__ __forceinline__ void mma16816h(float* c, const uint32_t* a, const uint32_t* b) {
    asm volatile(
        "mma.sync.aligned.m16n8k16.row.col.f32.f16.f16.f32 "
        "{%0,%1,%2,%3}, {%4,%5,%6,%7}, {%8,%9}, {%0,%1,%2,%3};"
        : "+f"(c[0]), "+f"(c[1]), "+f"(c[2]), "+f"(c[3])
        : "r"(a[0]), "r"(a[1]), "r"(a[2]), "r"(a[3]), "r"(b[0]), "r"(b[1]));
}
__device__ __forceinline__ uint32_t packh2(float a, float b) {
    __half2 h = __floats2half2_rn(a, b);
    return *(uint32_t*)&h;
}
__device__ __forceinline__ uint32_t ex2h2(uint32_t p) {
    asm("ex2.approx.f16x2 %0, %0;" : "+r"(p));
    return p;
}

// ---------------- fused prep: x quant (x8 vectorized) + RoPE table ---------
__global__ __launch_bounds__(256) void prep_kernel(
    const float* __restrict__ x, __half* __restrict__ xh,
    float* __restrict__ ct, float* __restrict__ st)
{
    if (blockIdx.x < 4096) {
        // quant: 4096 blocks * 256 threads * 8 elems = 8388608 = ROWS*CC
        int i = (blockIdx.x * 256 + threadIdx.x) * 8;
        float4 a = *(const float4*)&x[i];
        float4 b = *(const float4*)&x[i + 4];
        __half2 h[4];
        h[0] = __floats2half2_rn(a.x, a.y);
        h[1] = __floats2half2_rn(a.z, a.w);
        h[2] = __floats2half2_rn(b.x, b.y);
        h[3] = __floats2half2_rn(b.z, b.w);
        *(uint4*)&xh[i] = *(uint4*)h;
    } else {
        // RoPE table: 256 blocks * 256 threads = TT*32
        int idx = (blockIdx.x - 4096) * 256 + threadIdx.x;
        int t = idx >> 5, i = idx & 31;
        float invf = (float)exp(-(double)i / 32.0 * 9.210340371976184);
        float fr = (float)t * invf;
        double a = (double)fr;
        ct[idx] = (float)cos(a);
        st[idx] = (float)sin(a);
    }
}

// ---- merged W transpose: z=0 -> Wqkv (N=3072), z=1 -> Wproj (N=1024) ------
__global__ __launch_bounds__(256) void transpose_both_kernel(
    const float* __restrict__ Wq, __half* __restrict__ WqT,
    const float* __restrict__ Wp, __half* __restrict__ WpT)
{
    const int K = CC;
    int z = blockIdx.z;
    const float* W = z ? Wp : Wq;
    __half* Wt = z ? WpT : WqT;
    int N = z ? CC : N_QKV;
    int n0 = blockIdx.y * 32;
    if (n0 >= N) return;
    int k0 = blockIdx.x * 32;

    __shared__ float tile[32][33];
    int tx = threadIdx.x & 31, ty = threadIdx.x >> 5;   // 32x8
    #pragma unroll
    for (int r = 0; r < 4; r++)
        tile[ty + 8 * r][tx] = W[(size_t)(k0 + ty + 8 * r) * N + n0 + tx];
    __syncthreads();
    #pragma unroll
    for (int r = 0; r < 4; r++)
        Wt[(size_t)(n0 + ty + 8 * r) * K + k0 + tx] = __float2half(tile[tx][ty + 8 * r]);
}

// ---------------- HMMA GEMM (1-pass fp16, 2-stage, 2 CTAs/SM) --------------
// C = A @ B^T ; A:[M,K] fp16, B:[N,K] fp16
// MODE 0: f32 out + bias.  MODE 1: fused QKV bias+RoPE -> fp16 Q,K,V.
//         Q is pre-scaled by 1/sqrt(HD)*log2(e) for the base-2 softmax.
#define TILE_B 16384
#define STB (2*TILE_B)          // A tile + B tile per stage (32 KB)
#define GS (2*STB)              // 2 stages = 64 KB -> 2 CTAs/SM
#define SCQ 0.18033688f         // 0.125 * log2(e)

__device__ __forceinline__ void load_stage(
    uint32_t base, int kt, int tid, int row0, int col0, int K,
    const __half* __restrict__ Ah, const __half* __restrict__ Bq)
{
    int k0 = kt * 64;
    #pragma unroll
    for (int i = 0; i < 4; i++) {
        int lin = i * 256 + tid;
        int r = lin >> 3, c = lin & 7;
        uint32_t off = r * 128 + c * 16;
        uint32_t sw = off ^ ((off >> 3) & 0x70);
        cp16(base + sw, Ah + (size_t)(row0 + r) * K + k0 + c * 8);
        cp16(base + TILE_B + sw, Bq + (size_t)(col0 + r) * K + k0 + c * 8);
    }
    asm volatile("cp.async.commit_group;" ::: "memory");
}

template<int MODE>
__global__ __launch_bounds__(256, 2) void tc_gemm_kernel(
    const __half* __restrict__ Ah, const __half* __restrict__ Bq,
    const float* __restrict__ bias, float* __restrict__ C,
    __half* __restrict__ Qo, __half* __restrict__ Ko, __half* __restrict__ Vo,
    const float* __restrict__ ct, const float* __restrict__ st,
    int N, int K)
{
    extern __shared__ char smem[];
    uint32_t sb = smem_u32(smem);
    const int tid = threadIdx.x;
    const int wid = tid >> 5, lane = tid & 31;
    const int wr = (wid & 3) * 32;
    const int wc = (wid >> 2) * 64;
    const int col0 = blockIdx.x * 128;
    const int row0 = blockIdx.y * 128;
    const int NK = K >> 6;

    float acc[2][8][4];
    #pragma unroll
    for (int mi = 0; mi < 2; mi++)
        #pragma unroll
        for (int ni = 0; ni < 8; ni++)
            #pragma unroll
            for (int j = 0; j < 4; j++) acc[mi][ni][j] = 0.f;

    load_stage(sb, 0, tid, row0, col0, K, Ah, Bq);

    const int grp = lane >> 3, l8 = lane & 7;

    for (int kt = 0; kt < NK; kt++) {
        asm volatile("cp.async.wait_group 0;" ::: "memory");
        __syncthreads();
        if (kt + 1 < NK)
            load_stage(sb + ((kt + 1) & 1) * STB, kt + 1, tid, row0, col0, K, Ah, Bq);

        uint32_t sbase = sb + (kt & 1) * STB;
        uint32_t ahb = sbase, bbase = sbase + TILE_B;
        #pragma unroll
        for (int ks = 0; ks < 4; ks++) {
            uint32_t ah[2][4];
            #pragma unroll
            for (int mi = 0; mi < 2; mi++) {
                int row = wr + mi * 16 + (grp & 1) * 8 + l8;
                int chunk = ks * 2 + (grp >> 1);
                ldsm4(ah[mi], ahb + row * 128 + ((chunk ^ (row & 7)) << 4));
            }
            #pragma unroll
            for (int half = 0; half < 2; half++) {
                uint32_t b[4][2];
                #pragma unroll
                for (int nj = 0; nj < 2; nj++) {
                    int row = wc + (half * 2 + nj) * 16 + (grp >> 1) * 8 + l8;
                    int chunk = ks * 2 + (grp & 1);
                    uint32_t rr[4];
                    ldsm4(rr, bbase + row * 128 + ((chunk ^ (row & 7)) << 4));
                    b[2 * nj][0] = rr[0]; b[2 * nj][1] = rr[1];
                    b[2 * nj + 1][0] = rr[2]; b[2 * nj + 1][1] = rr[3];
                }
                #pragma unroll
                for (int mi = 0; mi < 2; mi++)
                    #pragma unroll
                    for (int ni = 0; ni < 4; ni++)
                        mma16816h(acc[mi][half * 4 + ni], ah[mi], b[ni]);
            }
        }
    }

    const int qr = lane >> 2, qc = (lane & 3) * 2;

    if (MODE == 0) {
        #pragma unroll
        for (int mi = 0; mi < 2; mi++) {
            #pragma unroll
            for (int ni = 0; ni < 8; ni++) {
                int r = row0 + wr + mi * 16 + qr;
                int c = col0 + wc + ni * 8 + qc;
                float b0 = bias[c], b1 = bias[c + 1];
                float2 o0 = make_float2(acc[mi][ni][0] + b0, acc[mi][ni][1] + b1);
                float2 o1 = make_float2(acc[mi][ni][2] + b0, acc[mi][ni][3] + b1);
                *(float2*)&C[(size_t)r * N + c] = o0;
                *(float2*)&C[(size_t)(r + 8) * N + c] = o1;
            }
        }
    } else {
        // fused QKV epilogue: bias + RoPE -> fp16 (Q pre-scaled by SCQ)
        int cb = col0 + wc;                 // 64-aligned head base
        int sec = cb >> 10;                 // 0=q, 1=k, 2=v
        int h = (cb & 1023) >> 6;
        #pragma unroll
        for (int mi = 0; mi < 2; mi++) {
            int r0 = row0 + wr + mi * 16 + qr;
            #pragma unroll
            for (int half = 0; half < 2; half++) {
                int r = r0 + half * 8;
                int e = half * 2;
                int t = r & (TT - 1);
                int b_ = r >> 11;
                size_t rowoff = ((size_t)((b_ * NHH + h) * TT + t)) * HDD;
                #pragma unroll
                for (int nj = 0; nj < 4; nj++) {
                    int d0 = nj * 8 + qc;            // even, < 32
                    int c0 = cb + d0;
                    float u00 = acc[mi][nj][e]     + bias[c0];
                    float u01 = acc[mi][nj][e + 1] + bias[c0 + 1];
                    float u10 = acc[mi][nj + 4][e]     + bias[c0 + 32];
                    float u11 = acc[mi][nj + 4][e + 1] + bias[c0 + 33];
                    if (sec < 2) {
                        float cA = ct[t * 32 + d0], cB = ct[t * 32 + d0 + 1];
                        float sA = st[t * 32 + d0], sB = st[t * 32 + d0 + 1];
                        float lo0 = u00 * cA - u10 * sA;
                        float lo1 = u01 * cB - u11 * sB;
                        float hi0 = u10 * cA + u00 * sA;
                        float hi1 = u11 * cB + u01 * sB;
                        if (sec == 0) {
                            lo0 *= SCQ; lo1 *= SCQ; hi0 *= SCQ; hi1 *= SCQ;
                        }
                        __half* dst = (sec == 0) ? Qo : Ko;
                        *(__half2*)&dst[rowoff + d0]      = __floats2half2_rn(lo0, lo1);
                        *(__half2*)&dst[rowoff + d0 + 32] = __floats2half2_rn(hi0, hi1);
                    } else {
                        *(__half2*)&Vo[rowoff + d0]      = __floats2half2_rn(u00, u01);
                        *(__half2*)&Vo[rowoff + d0 + 32] = __floats2half2_rn(u10, u11);
                    }
                }
            }
        }
    }
}

// ---------------- Tensor-core flash attention (fp16, BM=128 BN=64) ---------
// 256 threads (8 warps x 16 q-rows), 3-stage KV pipeline, 1 sync/iter,
// base-2 softmax via ex2.approx.f16x2, diag skipping, V via ldmatrix.trans.
#define KVSTG 16384
#define AT_SMEM (16384 + 3*KVSTG)   // Q + 3 stages of (K 8KB + V 8KB) = 64 KB

__device__ __forceinline__ void attn_load_kv(
    uint32_t dst, const __half* __restrict__ Kb, const __half* __restrict__ Vb,
    int ktbase, int tid)
{
    #pragma unroll
    for (int i = 0; i < 2; i++) {
        int lin = i * 256 + tid;
        int r = lin >> 3, c = lin & 7;
        uint32_t sw = r * 128 + ((c ^ (r & 7)) << 4);
        cp16(dst + sw, Kb + (size_t)(ktbase + r) * HDD + c * 8);
        cp16(dst + 8192 + sw, Vb + (size_t)(ktbase + r) * HDD + c * 8);
    }
    asm volatile("cp.async.commit_group;" ::: "memory");
}

__global__ __launch_bounds__(256, 2) void attn_kernel(
    const __half* __restrict__ Qg, const __half* __restrict__ Kg,
    const __half* __restrict__ Vg, __half* __restrict__ Yh)
{
    extern __shared__ char smem[];
    uint32_t sb = smem_u32(smem);
    uint32_t sQ = sb;
    uint32_t sKV = sb + 16384;

    const int tid = threadIdx.x;
    const int wid = tid >> 5, lane = tid & 31;
    const int grp = lane >> 3, l8 = lane & 7;
    const int qt = (int)gridDim.x - 1 - (int)blockIdx.x;   // longest first
    const int bh = blockIdx.y;
    const int q0 = qt * 128;
    const int nkt = 2 * qt + 2;

    const __half* Qb = Qg + ((size_t)bh * TT + q0) * HDD;
    const __half* Kb = Kg + (size_t)bh * TT * HDD;
    const __half* Vb = Vg + (size_t)bh * TT * HDD;

    // prologue: group0 = Q + KV0 ; group1 = KV1
    #pragma unroll
    for (int i = 0; i < 4; i++) {
        int lin = i * 256 + tid;
        int r = lin >> 3, c = lin & 7;
        cp16(sQ + r * 128 + ((c ^ (r & 7)) << 4), Qb + (size_t)r * HDD + c * 8);
    }
    attn_load_kv(sKV, Kb, Vb, 0, tid);                   // commits Q + KV0
    if (nkt > 1) attn_load_kv(sKV + KVSTG, Kb, Vb, 64, tid);

    uint32_t qf[4][4];
    float m0 = -1e30f, m1 = -1e30f, l0 = 0.f, l1 = 0.f;
    float oacc[8][4];
    #pragma unroll
    for (int nj = 0; nj < 8; nj++)
        #pragma unroll
        for (int e = 0; e < 4; e++) oacc[nj][e] = 0.f;

    const int rquad = lane >> 2;       // 0..7
    const int cpair = (lane & 3) * 2;  // 0,2,4,6

    for (int kt = 0; kt < nkt; kt++) {
        if (kt + 1 < nkt) { asm volatile("cp.async.wait_group 1;" ::: "memory"); }
        else              { asm volatile("cp.async.wait_group 0;" ::: "memory"); }
        __syncthreads();
        // issue KV(kt+2): overwrites slot (kt-1)%3, consumed before this sync
        if (kt + 2 < nkt)
            attn_load_kv(sKV + ((kt + 2) % 3) * KVSTG, Kb, Vb, (kt + 2) * 64, tid);

        if (kt == 0) {
            #pragma unroll
            for (int kc = 0; kc < 4; kc++) {
                int row = wid * 16 + (grp & 1) * 8 + l8;
                int ch = kc * 2 + (grp >> 1);
                ldsm4(qf[kc], sQ + row * 128 + ((ch ^ (row & 7)) << 4));
            }
        }

        uint32_t sK = sKV + (kt % 3) * KVSTG;
        uint32_t sV = sK + 8192;

        // diagonal work skipping: nb = # of active 16-col blocks (of 4)
        int nb = 4;
        if (kt == nkt - 2)      nb = (wid + 1 < 4) ? wid + 1 : 4;
        else if (kt == nkt - 1) nb = (wid >= 4) ? ((wid - 3 < 4) ? wid - 3 : 4) : 0;

        // S = Q K^T   (Q pre-scaled: S already in log2-softmax units)
        float sacc[8][4];
        #pragma unroll
        for (int nj = 0; nj < 8; nj++)
            #pragma unroll
            for (int e = 0; e < 4; e++) sacc[nj][e] = 0.f;

        #pragma unroll
        for (int ks = 0; ks < 4; ks++) {
            #pragma unroll
            for (int nj = 0; nj < 4; nj++) {
                if (nj < nb) {
                    int row = nj * 16 + (grp >> 1) * 8 + l8;
                    int ch = ks * 2 + (grp & 1);
                    uint32_t rr[4];
                    ldsm4(rr, sK + row * 128 + ((ch ^ (row & 7)) << 4));
                    uint32_t b0[2] = {rr[0], rr[1]}, b1[2] = {rr[2], rr[3]};
                    mma16816h(sacc[2 * nj], qf[ks], b0);
                    mma16816h(sacc[2 * nj + 1], qf[ks], b1);
                }
            }
        }

        // causal mask only (scaling folded into Q)
        if (kt >= nkt - 2) {
            int row0g = q0 + wid * 16 + rquad;
            #pragma unroll
            for (int nj = 0; nj < 8; nj++) {
                int colg = kt * 64 + nj * 8 + cpair;
                #pragma unroll
                for (int e = 0; e < 4; e++) {
                    int cg = colg + (e & 1);
                    int rg = row0g + ((e >= 2) ? 8 : 0);
                    if (cg > rg) sacc[nj][e] = -1e30f;
                }
            }
        }

        // online softmax in base-2 (two rows per thread; quad reductions)
        float rm0 = -1e30f, rm1 = -1e30f;
        #pragma unroll
        for (int nj = 0; nj < 8; nj++) {
            rm0 = fmaxf(rm0, fmaxf(sacc[nj][0], sacc[nj][1]));
            rm1 = fmaxf(rm1, fmaxf(sacc[nj][2], sacc[nj][3]));
        }
        rm0 = fmaxf(rm0, __shfl_xor_sync(0xffffffffu, rm0, 1));
        rm0 = fmaxf(rm0, __shfl_xor_sync(0xffffffffu, rm0, 2));
        rm1 = fmaxf(rm1, __shfl_xor_sync(0xffffffffu, rm1, 1));
        rm1 = fmaxf(rm1, __shfl_xor_sync(0xffffffffu, rm1, 2));

        float n0 = fmaxf(m0, rm0), n1 = fmaxf(m1, rm1);
        float a0 = exp2f(m0 - n0), a1 = exp2f(m1 - n1);

        // P = 2^(S-max) in fp16x2, landing pre-packed as A-fragments
        uint32_t pf[4][4];
        float rs0 = 0.f, rs1 = 0.f;
        #pragma unroll
        for (int nj = 0; nj < 8; nj++) {
            uint32_t p01 = ex2h2(packh2(sacc[nj][0] - n0, sacc[nj][1] - n0));
            uint32_t p23 = ex2h2(packh2(sacc[nj][2] - n1, sacc[nj][3] - n1));
            float2 f01 = __half22float2(*(__half2*)&p01);
            float2 f23 = __half22float2(*(__half2*)&p23);
            rs0 += f01.x + f01.y;
            rs1 += f23.x + f23.y;
            pf[nj >> 1][(nj & 1) * 2 + 0] = p01;
            pf[nj >> 1][(nj & 1) * 2 + 1] = p23;
        }
        rs0 += __shfl_xor_sync(0xffffffffu, rs0, 1);
        rs0 += __shfl_xor_sync(0xffffffffu, rs0, 2);
        rs1 += __shfl_xor_sync(0xffffffffu, rs1, 1);
        rs1 += __shfl_xor_sync(0xffffffffu, rs1, 2);

        l0 = l0 * a0 + rs0;
        l1 = l1 * a1 + rs1;
        m0 = n0; m1 = n1;
        #pragma unroll
        for (int nj = 0; nj < 8; nj++) {
            oacc[nj][0] *= a0; oacc[nj][1] *= a0;
            oacc[nj][2] *= a1; oacc[nj][3] *= a1;
        }

        // O += P @ V ; V is [t][d] in smem, B-fragments via ldmatrix.trans
        #pragma unroll
        for (int kc = 0; kc < 4; kc++) {
            if (kc < nb) {
                #pragma unroll
                for (int nj = 0; nj < 4; nj++) {
                    int trow = kc * 16 + (grp & 1) * 8 + l8;   // t rows
                    int ch = nj * 2 + (grp >> 1);              // d chunks
                    uint32_t rr[4];
                    ldsm4t(rr, sV + trow * 128 + ((ch ^ (trow & 7)) << 4));
                    uint32_t b0[2] = {rr[0], rr[1]}, b1[2] = {rr[2], rr[3]};
                    mma16816h(oacc[2 * nj], pf[kc], b0);
                    mma16816h(oacc[2 * nj + 1], pf[kc], b1);
                }
            }
        }
    }

    // epilogue: normalize + fp16 store to [b,t,c]
    float i0 = 1.f / l0, i1 = 1.f / l1;
    int b_ = bh >> 4, h = bh & 15;
    int r0g = q0 + wid * 16 + rquad;
    #pragma unroll
    for (int nj = 0; nj < 8; nj++) {
        int c = h * 64 + nj * 8 + cpair;
        float v0 = oacc[nj][0] * i0, v1 = oacc[nj][1] * i0;
        float v2 = oacc[nj][2] * i1, v3 = oacc[nj][3] * i1;
        size_t o0 = (size_t)(b_ * TT + r0g) * CC + c;
        size_t o1 = (size_t)(b_ * TT + r0g + 8) * CC + c;
        *(__half2*)&Yh[o0] = __floats2half2_rn(v0, v1);
        *(__half2*)&Yh[o1] = __floats2half2_rn(v2, v3);
    }
}

// ---------------- launch ---------------------------------------------------
extern "C" void kernel_launch(void* const* d_in, const int* in_sizes, int n_in,
                              void* d_out, int out_size)
{
    const float* x     = (const float*)d_in[0];
    const float* Wqkv  = (const float*)d_in[1];
    const float* bqkv  = (const float*)d_in[2];
    const float* Wproj = (const float*)d_in[3];
    const float* bproj = (const float*)d_in[4];
    float* out = (float*)d_out;

    float *ct, *st;
    __half *xh, *wq, *wp, *yh, *qh, *kh, *vh;
    cudaGetSymbolAddress((void**)&ct, g_cost);
    cudaGetSymbolAddress((void**)&st, g_sint);
    cudaGetSymbolAddress((void**)&xh, g_xh);
    cudaGetSymbolAddress((void**)&wq, g_wq);
    cudaGetSymbolAddress((void**)&wp, g_wp);
    cudaGetSymbolAddress((void**)&yh, g_yh);
    cudaGetSymbolAddress((void**)&qh, g_qh);
    cudaGetSymbolAddress((void**)&kh, g_kh);
    cudaGetSymbolAddress((void**)&vh, g_vh);

    cudaFuncSetAttribute(tc_gemm_kernel<1>,
                         cudaFuncAttributeMaxDynamicSharedMemorySize, GS);
    cudaFuncSetAttribute(tc_gemm_kernel<0>,
                         cudaFuncAttributeMaxDynamicSharedMemorySize, GS);
    cudaFuncSetAttribute(attn_kernel,
                         cudaFuncAttributeMaxDynamicSharedMemorySize, AT_SMEM);

    // 1) fused prep: x -> fp16 (vectorized) + RoPE cos/sin table
    prep_kernel<<<4096 + 256, 256>>>(x, xh, ct, st);

    // 2) both weight transposes in one launch
    transpose_both_kernel<<<dim3(CC / 32, N_QKV / 32, 2), 256>>>(Wqkv, wq, Wproj, wp);

    // 3) QKV GEMM (1-pass fp16, 2-stage, 2 CTAs/SM) + bias + RoPE -> Q,K,V
    tc_gemm_kernel<1><<<dim3(N_QKV / 128, ROWS / 128), 256, GS>>>(
        xh, wq, bqkv, nullptr, qh, kh, vh, ct, st, N_QKV, CC);

    // 4) tensor-core causal flash attention (f16x2 base-2 softmax) -> fp16 Y
    attn_kernel<<<dim3(TT / 128, BB * NHH), 256, AT_SMEM>>>(qh, kh, vh, yh);

    // 5) output projection (1-pass fp16) + bias
    tc_gemm_kernel<0><<<dim3(CC / 128, ROWS / 128), 256, GS>>>(
        yh, wp, bproj, out, nullptr, nullptr, nullptr, ct, st, CC, CC);
}

// round 16
// speedup vs baseline: 2.2642x; 1.0056x over previous
#include <cuda_runtime.h>
#include <cuda_bf16.h>
#include <cuda_fp16.h>
#include <math.h>
#include <stdint.h>

// Problem constants
#define BB 4
#define TT 2048
#define CC 1024
#define NHH 16
#define HDD 64
#define ROWS (BB*TT)          // 8192
#define N_QKV (3*CC)          // 3072

// ---------------- scratch (device globals; no allocation) ----------------
__device__ __half g_xh[(size_t)ROWS * CC];            // x fp16
__device__ __half g_wq[(size_t)N_QKV * CC];           // Wqkv^T [N,K] fp16
__device__ __half g_wp[(size_t)CC * CC];              // Wproj^T [N,K] fp16
__device__ __half g_yh[(size_t)ROWS * CC];            // attn out (fp16)
__device__ float g_cost[(size_t)TT * 32];
__device__ float g_sint[(size_t)TT * 32];

__device__ __half g_qh[(size_t)BB * NHH * TT * HDD];  // [bh][t][d] (pre-scaled)
__device__ __half g_kh[(size_t)BB * NHH * TT * HDD];  // [bh][t][d]
__device__ __half g_vh[(size_t)BB * NHH * TT * HDD];  // [bh][t][d]

// ---------------- PTX helpers (arch-baseline only: no tcgen05) ------------
__device__ __forceinline__ uint32_t smem_u32(const void* p) {
    uint32_t a;
    asm("{ .reg .u64 t; cvta.to.shared.u64 t, %1; cvt.u32.u64 %0, t; }" : "=r"(a) : "l"(p));
    return a;
}
__device__ __forceinline__ void cp16(uint32_t saddr, const void* g) {
    asm volatile("cp.async.cg.shared.global [%0], [%1], 16;" :: "r"(saddr), "l"(g));
}
__device__ __forceinline__ void ldsm4(uint32_t* r, uint32_t addr) {
    asm volatile("ldmatrix.sync.aligned.m8n8.x4.shared.b16 {%0,%1,%2,%3}, [%4];"
                 : "=r"(r[0]), "=r"(r[1]), "=r"(r[2]), "=r"(r[3]) : "r"(addr));
}
__device__ __forceinline__ void ldsm4t(uint32_t* r, uint32_t addr) {
    asm volatile("ldmatrix.sync.aligned.m8n8.x4.trans.shared.b16 {%0,%1,%2,%3}, [%4];"
                 : "=r"(r[0]), "=r"(r[1]), "=r"(r[2]), "=r"(r[3]) : "r"(addr));
}
__device__ __forceinline__ void mma16816h(float* c, const uint32_t* a, const uint32_t* b) {
    asm volatile(
        "mma.sync.aligned.m16n8k16.row.col.f32.f16.f16.f32 "
        "{%0,%1,%2,%3}, {%4,%5,%6,%7}, {%8,%9}, {%0,%1,%2,%3};"
        : "+f"(c[0]), "+f"(c[1]), "+f"(c[2]), "+f"(c[3])
        : "r"(a[0]), "r"(a[1]), "r"(a[2]), "r"(a[3]), "r"(b[0]), "r"(b[1]));
}
__device__ __forceinline__ uint32_t packh2(float a, float b) {
    __half2 h = __floats2half2_rn(a, b);
    return *(uint32_t*)&h;
}
__device__ __forceinline__ uint32_t ex2h2(uint32_t p) {
    asm("ex2.approx.f16x2 %0, %0;" : "+r"(p));
    return p;
}

// ---------------- fused prep: x quant (x8 vectorized) + RoPE table ---------
__global__ __launch_bounds__(256) void prep_kernel(
    const float* __restrict__ x, __half* __restrict__ xh,
    float* __restrict__ ct, float* __restrict__ st)
{
    if (blockIdx.x < 4096) {
        int i = (blockIdx.x * 256 + threadIdx.x) * 8;
        float4 a = *(const float4*)&x[i];
        float4 b = *(const float4*)&x[i + 4];
        __half2 h[4];
        h[0] = __floats2half2_rn(a.x, a.y);
        h[1] = __floats2half2_rn(a.z, a.w);
        h[2] = __floats2half2_rn(b.x, b.y);
        h[3] = __floats2half2_rn(b.z, b.w);
        *(uint4*)&xh[i] = *(uint4*)h;
    } else {
        int idx = (blockIdx.x - 4096) * 256 + threadIdx.x;
        int t = idx >> 5, i = idx & 31;
        float invf = (float)exp(-(double)i / 32.0 * 9.210340371976184);
        float fr = (float)t * invf;
        double a = (double)fr;
        ct[idx] = (float)cos(a);
        st[idx] = (float)sin(a);
    }
}

// ---- merged W transpose: z=0 -> Wqkv (N=3072), z=1 -> Wproj (N=1024) ------
__global__ __launch_bounds__(256) void transpose_both_kernel(
    const float* __restrict__ Wq, __half* __restrict__ WqT,
    const float* __restrict__ Wp, __half* __restrict__ WpT)
{
    const int K = CC;
    int z = blockIdx.z;
    const float* W = z ? Wp : Wq;
    __half* Wt = z ? WpT : WqT;
    int N = z ? CC : N_QKV;
    int n0 = blockIdx.y * 32;
    if (n0 >= N) return;
    int k0 = blockIdx.x * 32;

    __shared__ float tile[32][33];
    int tx = threadIdx.x & 31, ty = threadIdx.x >> 5;   // 32x8
    #pragma unroll
    for (int r = 0; r < 4; r++)
        tile[ty + 8 * r][tx] = W[(size_t)(k0 + ty + 8 * r) * N + n0 + tx];
    __syncthreads();
    #pragma unroll
    for (int r = 0; r < 4; r++)
        Wt[(size_t)(n0 + ty + 8 * r) * K + k0 + tx] = __float2half(tile[tx][ty + 8 * r]);
}

// ---------------- HMMA GEMM (1-pass fp16, 2-stage, 2 CTAs/SM) --------------
// C = A @ B^T ; A:[M,K] fp16, B:[N,K] fp16
// MODE 0: f32 out + bias.  MODE 1: fused QKV bias+RoPE -> fp16 Q,K,V.
//         Q is pre-scaled by 1/sqrt(HD)*log2(e) for the base-2 softmax.
#define TILE_B 16384
#define STB (2*TILE_B)          // A tile + B tile per stage (32 KB)
#define GS (2*STB)              // 2 stages = 64 KB -> 2 CTAs/SM
#define SCQ 0.18033688f         // 0.125 * log2(e)

__device__ __forceinline__ void load_stage(
    uint32_t base, int kt, int tid, int row0, int col0, int K,
    const __half* __restrict__ Ah, const __half* __restrict__ Bq)
{
    int k0 = kt * 64;
    #pragma unroll
    for (int i = 0; i < 4; i++) {
        int lin = i * 256 + tid;
        int r = lin >> 3, c = lin & 7;
        uint32_t off = r * 128 + c * 16;
        uint32_t sw = off ^ ((off >> 3) & 0x70);
        cp16(base + sw, Ah + (size_t)(row0 + r) * K + k0 + c * 8);
        cp16(base + TILE_B + sw, Bq + (size_t)(col0 + r) * K + k0 + c * 8);
    }
    asm volatile("cp.async.commit_group;" ::: "memory");
}

template<int MODE>
__global__ __launch_bounds__(256, 2) void tc_gemm_kernel(
    const __half* __restrict__ Ah, const __half* __restrict__ Bq,
    const float* __restrict__ bias, float* __restrict__ C,
    __half* __restrict__ Qo, __half* __restrict__ Ko, __half* __restrict__ Vo,
    const float* __restrict__ ct, const float* __restrict__ st,
    int N, int K)
{
    extern __shared__ char smem[];
    uint32_t sb = smem_u32(smem);
    const int tid = threadIdx.x;
    const int wid = tid >> 5, lane = tid & 31;
    const int wr = (wid & 3) * 32;
    const int wc = (wid >> 2) * 64;
    const int col0 = blockIdx.x * 128;
    const int row0 = blockIdx.y * 128;
    const int NK = K >> 6;

    float acc[2][8][4];
    #pragma unroll
    for (int mi = 0; mi < 2; mi++)
        #pragma unroll
        for (int ni = 0; ni < 8; ni++)
            #pragma unroll
            for (int j = 0; j < 4; j++) acc[mi][ni][j] = 0.f;

    load_stage(sb, 0, tid, row0, col0, K, Ah, Bq);

    const int grp = lane >> 3, l8 = lane & 7;

    for (int kt = 0; kt < NK; kt++) {
        asm volatile("cp.async.wait_group 0;" ::: "memory");
        __syncthreads();
        if (kt + 1 < NK)
            load_stage(sb + ((kt + 1) & 1) * STB, kt + 1, tid, row0, col0, K, Ah, Bq);

        uint32_t sbase = sb + (kt & 1) * STB;
        uint32_t ahb = sbase, bbase = sbase + TILE_B;
        #pragma unroll
        for (int ks = 0; ks < 4; ks++) {
            uint32_t ah[2][4];
            #pragma unroll
            for (int mi = 0; mi < 2; mi++) {
                int row = wr + mi * 16 + (grp & 1) * 8 + l8;
                int chunk = ks * 2 + (grp >> 1);
                ldsm4(ah[mi], ahb + row * 128 + ((chunk ^ (row & 7)) << 4));
            }
            #pragma unroll
            for (int half = 0; half < 2; half++) {
                uint32_t b[4][2];
                #pragma unroll
                for (int nj = 0; nj < 2; nj++) {
                    int row = wc + (half * 2 + nj) * 16 + (grp >> 1) * 8 + l8;
                    int chunk = ks * 2 + (grp & 1);
                    uint32_t rr[4];
                    ldsm4(rr, bbase + row * 128 + ((chunk ^ (row & 7)) << 4));
                    b[2 * nj][0] = rr[0]; b[2 * nj][1] = rr[1];
                    b[2 * nj + 1][0] = rr[2]; b[2 * nj + 1][1] = rr[3];
                }
                #pragma unroll
                for (int mi = 0; mi < 2; mi++)
                    #pragma unroll
                    for (int ni = 0; ni < 4; ni++)
                        mma16816h(acc[mi][half * 4 + ni], ah[mi], b[ni]);
            }
        }
    }

    const int qr = lane >> 2, qc = (lane & 3) * 2;

    if (MODE == 0) {
        #pragma unroll
        for (int mi = 0; mi < 2; mi++) {
            #pragma unroll
            for (int ni = 0; ni < 8; ni++) {
                int r = row0 + wr + mi * 16 + qr;
                int c = col0 + wc + ni * 8 + qc;
                float b0 = bias[c], b1 = bias[c + 1];
                float2 o0 = make_float2(acc[mi][ni][0] + b0, acc[mi][ni][1] + b1);
                float2 o1 = make_float2(acc[mi][ni][2] + b0, acc[mi][ni][3] + b1);
                *(float2*)&C[(size_t)r * N + c] = o0;
                *(float2*)&C[(size_t)(r + 8) * N + c] = o1;
            }
        }
    } else {
        // fused QKV epilogue: bias + RoPE -> fp16 (Q pre-scaled by SCQ)
        int cb = col0 + wc;                 // 64-aligned head base
        int sec = cb >> 10;                 // 0=q, 1=k, 2=v
        int h = (cb & 1023) >> 6;
        #pragma unroll
        for (int mi = 0; mi < 2; mi++) {
            int r0 = row0 + wr + mi * 16 + qr;
            #pragma unroll
            for (int half = 0; half < 2; half++) {
                int r = r0 + half * 8;
                int e = half * 2;
                int t = r & (TT - 1);
                int b_ = r >> 11;
                size_t rowoff = ((size_t)((b_ * NHH + h) * TT + t)) * HDD;
                #pragma unroll
                for (int nj = 0; nj < 4; nj++) {
                    int d0 = nj * 8 + qc;            // even, < 32
                    int c0 = cb + d0;
                    float u00 = acc[mi][nj][e]     + bias[c0];
                    float u01 = acc[mi][nj][e + 1] + bias[c0 + 1];
                    float u10 = acc[mi][nj + 4][e]     + bias[c0 + 32];
                    float u11 = acc[mi][nj + 4][e + 1] + bias[c0 + 33];
                    if (sec < 2) {
                        float cA = ct[t * 32 + d0], cB = ct[t * 32 + d0 + 1];
                        float sA = st[t * 32 + d0], sB = st[t * 32 + d0 + 1];
                        float lo0 = u00 * cA - u10 * sA;
                        float lo1 = u01 * cB - u11 * sB;
                        float hi0 = u10 * cA + u00 * sA;
                        float hi1 = u11 * cB + u01 * sB;
                        if (sec == 0) {
                            lo0 *= SCQ; lo1 *= SCQ; hi0 *= SCQ; hi1 *= SCQ;
                        }
                        __half* dst = (sec == 0) ? Qo : Ko;
                        *(__half2*)&dst[rowoff + d0]      = __floats2half2_rn(lo0, lo1);
                        *(__half2*)&dst[rowoff + d0 + 32] = __floats2half2_rn(hi0, hi1);
                    } else {
                        *(__half2*)&Vo[rowoff + d0]      = __floats2half2_rn(u00, u01);
                        *(__half2*)&Vo[rowoff + d0 + 32] = __floats2half2_rn(u10, u11);
                    }
                }
            }
        }
    }
}

// ---------------- Tensor-core flash attention (fp16, BM=128 BN=64) ---------
// 256 threads (8 warps x 16 q-rows), 3-stage KV pipeline, 1 sync/iter,
// base-2 softmax via ex2.approx.f16x2; row-sums computed ON the tensor pipe
// via P @ ones-fragment (no shuffles); diag skipping; V via ldmatrix.trans.
#define KVSTG 16384
#define AT_SMEM (16384 + 3*KVSTG)   // Q + 3 stages of (K 8KB + V 8KB) = 64 KB
#define ONE_H2 0x3C003C00u           // {1.0h, 1.0h}

__device__ __forceinline__ void attn_load_kv(
    uint32_t dst, const __half* __restrict__ Kb, const __half* __restrict__ Vb,
    int ktbase, int tid)
{
    #pragma unroll
    for (int i = 0; i < 2; i++) {
        int lin = i * 256 + tid;
        int r = lin >> 3, c = lin & 7;
        uint32_t sw = r * 128 + ((c ^ (r & 7)) << 4);
        cp16(dst + sw, Kb + (size_t)(ktbase + r) * HDD + c * 8);
        cp16(dst + 8192 + sw, Vb + (size_t)(ktbase + r) * HDD + c * 8);
    }
    asm volatile("cp.async.commit_group;" ::: "memory");
}

__global__ __launch_bounds__(256, 2) void attn_kernel(
    const __half* __restrict__ Qg, const __half* __restrict__ Kg,
    const __half* __restrict__ Vg, __half* __restrict__ Yh)
{
    extern __shared__ char smem[];
    uint32_t sb = smem_u32(smem);
    uint32_t sQ = sb;
    uint32_t sKV = sb + 16384;

    const int tid = threadIdx.x;
    const int wid = tid >> 5, lane = tid & 31;
    const int grp = lane >> 3, l8 = lane & 7;
    const int qt = (int)gridDim.x - 1 - (int)blockIdx.x;   // longest first
    const int bh = blockIdx.y;
    const int q0 = qt * 128;
    const int nkt = 2 * qt + 2;

    const __half* Qb = Qg + ((size_t)bh * TT + q0) * HDD;
    const __half* Kb = Kg + (size_t)bh * TT * HDD;
    const __half* Vb = Vg + (size_t)bh * TT * HDD;

    // prologue: group0 = Q + KV0 ; group1 = KV1
    #pragma unroll
    for (int i = 0; i < 4; i++) {
        int lin = i * 256 + tid;
        int r = lin >> 3, c = lin & 7;
        cp16(sQ + r * 128 + ((c ^ (r & 7)) << 4), Qb + (size_t)r * HDD + c * 8);
    }
    attn_load_kv(sKV, Kb, Vb, 0, tid);                   // commits Q + KV0
    if (nkt > 1) attn_load_kv(sKV + KVSTG, Kb, Vb, 64, tid);

    uint32_t qf[4][4];
    float m0 = -1e30f, m1 = -1e30f;
    float oacc[8][4], lacc[4];
    #pragma unroll
    for (int nj = 0; nj < 8; nj++)
        #pragma unroll
        for (int e = 0; e < 4; e++) oacc[nj][e] = 0.f;
    #pragma unroll
    for (int e = 0; e < 4; e++) lacc[e] = 0.f;

    const int rquad = lane >> 2;       // 0..7
    const int cpair = (lane & 3) * 2;  // 0,2,4,6
    const uint32_t onesb[2] = {ONE_H2, ONE_H2};

    for (int kt = 0; kt < nkt; kt++) {
        if (kt + 1 < nkt) { asm volatile("cp.async.wait_group 1;" ::: "memory"); }
        else              { asm volatile("cp.async.wait_group 0;" ::: "memory"); }
        __syncthreads();
        if (kt + 2 < nkt)
            attn_load_kv(sKV + ((kt + 2) % 3) * KVSTG, Kb, Vb, (kt + 2) * 64, tid);

        if (kt == 0) {
            #pragma unroll
            for (int kc = 0; kc < 4; kc++) {
                int row = wid * 16 + (grp & 1) * 8 + l8;
                int ch = kc * 2 + (grp >> 1);
                ldsm4(qf[kc], sQ + row * 128 + ((ch ^ (row & 7)) << 4));
            }
        }

        uint32_t sK = sKV + (kt % 3) * KVSTG;
        uint32_t sV = sK + 8192;

        // diagonal work skipping: nb = # of active 16-col blocks (of 4)
        int nb = 4;
        if (kt == nkt - 2)      nb = (wid + 1 < 4) ? wid + 1 : 4;
        else if (kt == nkt - 1) nb = (wid >= 4) ? ((wid - 3 < 4) ? wid - 3 : 4) : 0;

        // S = Q K^T   (Q pre-scaled: S already in log2-softmax units)
        float sacc[8][4];
        #pragma unroll
        for (int nj = 0; nj < 8; nj++)
            #pragma unroll
            for (int e = 0; e < 4; e++) sacc[nj][e] = 0.f;

        #pragma unroll
        for (int ks = 0; ks < 4; ks++) {
            #pragma unroll
            for (int nj = 0; nj < 4; nj++) {
                if (nj < nb) {
                    int row = nj * 16 + (grp >> 1) * 8 + l8;
                    int ch = ks * 2 + (grp & 1);
                    uint32_t rr[4];
                    ldsm4(rr, sK + row * 128 + ((ch ^ (row & 7)) << 4));
                    uint32_t b0[2] = {rr[0], rr[1]}, b1[2] = {rr[2], rr[3]};
                    mma16816h(sacc[2 * nj], qf[ks], b0);
                    mma16816h(sacc[2 * nj + 1], qf[ks], b1);
                }
            }
        }

        // causal mask only (scaling folded into Q)
        if (kt >= nkt - 2) {
            int row0g = q0 + wid * 16 + rquad;
            #pragma unroll
            for (int nj = 0; nj < 8; nj++) {
                int colg = kt * 64 + nj * 8 + cpair;
                #pragma unroll
                for (int e = 0; e < 4; e++) {
                    int cg = colg + (e & 1);
                    int rg = row0g + ((e >= 2) ? 8 : 0);
                    if (cg > rg) sacc[nj][e] = -1e30f;
                }
            }
        }

        // online max in base-2 (two rows per thread; quad reductions)
        float rm0 = -1e30f, rm1 = -1e30f;
        #pragma unroll
        for (int nj = 0; nj < 8; nj++) {
            rm0 = fmaxf(rm0, fmaxf(sacc[nj][0], sacc[nj][1]));
            rm1 = fmaxf(rm1, fmaxf(sacc[nj][2], sacc[nj][3]));
        }
        rm0 = fmaxf(rm0, __shfl_xor_sync(0xffffffffu, rm0, 1));
        rm0 = fmaxf(rm0, __shfl_xor_sync(0xffffffffu, rm0, 2));
        rm1 = fmaxf(rm1, __shfl_xor_sync(0xffffffffu, rm1, 1));
        rm1 = fmaxf(rm1, __shfl_xor_sync(0xffffffffu, rm1, 2));

        float n0 = fmaxf(m0, rm0), n1 = fmaxf(m1, rm1);
        float a0 = exp2f(m0 - n0), a1 = exp2f(m1 - n1);
        m0 = n0; m1 = n1;

        // P = 2^(S-max) in fp16x2, landing pre-packed as A-fragments
        uint32_t pf[4][4];
        #pragma unroll
        for (int nj = 0; nj < 8; nj++) {
            pf[nj >> 1][(nj & 1) * 2 + 0] = ex2h2(packh2(sacc[nj][0] - n0, sacc[nj][1] - n0));
            pf[nj >> 1][(nj & 1) * 2 + 1] = ex2h2(packh2(sacc[nj][2] - n1, sacc[nj][3] - n1));
        }

        // rescale accumulators (l rides along as a 4-reg accumulator)
        #pragma unroll
        for (int nj = 0; nj < 8; nj++) {
            oacc[nj][0] *= a0; oacc[nj][1] *= a0;
            oacc[nj][2] *= a1; oacc[nj][3] *= a1;
        }
        lacc[0] *= a0; lacc[1] *= a0; lacc[2] *= a1; lacc[3] *= a1;

        // O += P @ V  and  l += P @ 1  (row-sum on the tensor pipe, no shfls)
        #pragma unroll
        for (int kc = 0; kc < 4; kc++) {
            if (kc < nb) {
                mma16816h(lacc, pf[kc], onesb);
                #pragma unroll
                for (int nj = 0; nj < 4; nj++) {
                    int trow = kc * 16 + (grp & 1) * 8 + l8;   // t rows
                    int ch = nj * 2 + (grp >> 1);              // d chunks
                    uint32_t rr[4];
                    ldsm4t(rr, sV + trow * 128 + ((ch ^ (trow & 7)) << 4));
                    uint32_t b0[2] = {rr[0], rr[1]}, b1[2] = {rr[2], rr[3]};
                    mma16816h(oacc[2 * nj], pf[kc], b0);
                    mma16816h(oacc[2 * nj + 1], pf[kc], b1);
                }
            }
        }
    }

    // epilogue: normalize + fp16 store to [b,t,c]
    float i0 = 1.f / lacc[0], i1 = 1.f / lacc[2];
    int b_ = bh >> 4, h = bh & 15;
    int r0g = q0 + wid * 16 + rquad;
    #pragma unroll
    for (int nj = 0; nj < 8; nj++) {
        int c = h * 64 + nj * 8 + cpair;
        float v0 = oacc[nj][0] * i0, v1 = oacc[nj][1] * i0;
        float v2 = oacc[nj][2] * i1, v3 = oacc[nj][3] * i1;
        size_t o0 = (size_t)(b_ * TT + r0g) * CC + c;
        size_t o1 = (size_t)(b_ * TT + r0g + 8) * CC + c;
        *(__half2*)&Yh[o0] = __floats2half2_rn(v0, v1);
        *(__half2*)&Yh[o1] = __floats2half2_rn(v2, v3);
    }
}

// ---------------- launch ---------------------------------------------------
extern "C" void kernel_launch(void* const* d_in, const int* in_sizes, int n_in,
                              void* d_out, int out_size)
{
    const float* x     = (const float*)d_in[0];
    const float* Wqkv  = (const float*)d_in[1];
    const float* bqkv  = (const float*)d_in[2];
    const float* Wproj = (const float*)d_in[3];
    const float* bproj = (const float*)d_in[4];
    float* out = (float*)d_out;

    float *ct, *st;
    __half *xh, *wq, *wp, *yh, *qh, *kh, *vh;
    cudaGetSymbolAddress((void**)&ct, g_cost);
    cudaGetSymbolAddress((void**)&st, g_sint);
    cudaGetSymbolAddress((void**)&xh, g_xh);
    cudaGetSymbolAddress((void**)&wq, g_wq);
    cudaGetSymbolAddress((void**)&wp, g_wp);
    cudaGetSymbolAddress((void**)&yh, g_yh);
    cudaGetSymbolAddress((void**)&qh, g_qh);
    cudaGetSymbolAddress((void**)&kh, g_kh);
    cudaGetSymbolAddress((void**)&vh, g_vh);

    cudaFuncSetAttribute(tc_gemm_kernel<1>,
                         cudaFuncAttributeMaxDynamicSharedMemorySize, GS);
    cudaFuncSetAttribute(tc_gemm_kernel<0>,
                         cudaFuncAttributeMaxDynamicSharedMemorySize, GS);
    cudaFuncSetAttribute(attn_kernel,
                         cudaFuncAttributeMaxDynamicSharedMemorySize, AT_SMEM);

    // 1) fused prep: x -> fp16 (vectorized) + RoPE cos/sin table
    prep_kernel<<<4096 + 256, 256>>>(x, xh, ct, st);

    // 2) both weight transposes in one launch
    transpose_both_kernel<<<dim3(CC / 32, N_QKV / 32, 2), 256>>>(Wqkv, wq, Wproj, wp);

    // 3) QKV GEMM (1-pass fp16, 2-stage, 2 CTAs/SM) + bias + RoPE -> Q,K,V
    tc_gemm_kernel<1><<<dim3(N_QKV / 128, ROWS / 128), 256, GS>>>(
        xh, wq, bqkv, nullptr, qh, kh, vh, ct, st, N_QKV, CC);

    // 4) tensor-core causal flash attention (tensor-pipe row sums) -> fp16 Y
    attn_kernel<<<dim3(TT / 128, BB * NHH), 256, AT_SMEM>>>(qh, kh, vh, yh);

    // 5) output projection (1-pass fp16) + bias
    tc_gemm_kernel<0><<<dim3(CC / 128, ROWS / 128), 256, GS>>>(
        yh, wp, bproj, out, nullptr, nullptr, nullptr, ct, st, CC, CC);
}